// round 4
// baseline (speedup 1.0000x reference)
#include <cuda_runtime.h>
#include <cstdint>

#define TT 1024
#define DM 512
#define NB 4
#define NH 8
#define DK 64
#define LL 2047   // 2*T - 1
typedef long long ll;
typedef unsigned long long u64;

// ---------------- scratch ----------------
__device__ float g_Q[NB * TT * DM];
__device__ float g_K[NB * TT * DM];
__device__ float g_V[NB * TT * DM];
__device__ float g_P[2048 * DM];
__device__ float g_R[32LL * 512 * LL];   // [b*8+h][m][l]
__device__ float g_O[NB * TT * DM];
__device__ unsigned int g_Mb[NB * TT * 32];   // bit-packed mask

// ---------------- helpers ----------------
__device__ __forceinline__ float tf32_hi(float x) {
    uint32_t uh;
    asm("cvt.rna.tf32.f32 %0, %1;" : "=r"(uh) : "f"(x));
    return __uint_as_float(uh);
}

__device__ __forceinline__ void mma_tf32(float* d, const float* a, float b0, float b1) {
    asm volatile(
        "mma.sync.aligned.m16n8k8.row.col.f32.tf32.tf32.f32 "
        "{%0,%1,%2,%3}, {%4,%5,%6,%7}, {%8,%9}, {%0,%1,%2,%3};\n"
        : "+f"(d[0]), "+f"(d[1]), "+f"(d[2]), "+f"(d[3])
        : "r"(__float_as_uint(a[0])), "r"(__float_as_uint(a[1])),
          "r"(__float_as_uint(a[2])), "r"(__float_as_uint(a[3])),
          "r"(__float_as_uint(b0)), "r"(__float_as_uint(b1)));
}

__device__ __forceinline__ void cp_async16(uint32_t dst, const void* src, bool p) {
    asm volatile("cp.async.cg.shared.global [%0], [%1], 16, %2;\n"
                 :: "r"(dst), "l"(src), "r"(p ? 16 : 0));
}
__device__ __forceinline__ void cp_commit() { asm volatile("cp.async.commit_group;\n"); }
template <int N>
__device__ __forceinline__ void cp_wait() { asm volatile("cp.async.wait_group %0;\n" :: "n"(N)); }

// ---------------- mask bit-pack: 32 bytes -> 1 u32 ----------------
__global__ void __launch_bounds__(256) mask_pack(const unsigned char* __restrict__ m,
                                                 unsigned int* __restrict__ out)
{
    int i = blockIdx.x * 256 + threadIdx.x;   // [0, 131072)
    const uchar4* p = (const uchar4*)(m + (ll)i * 32);
    unsigned int bits = 0;
#pragma unroll
    for (int j = 0; j < 8; j++) {
        uchar4 v = p[j];
        unsigned int q = (v.x ? 1u : 0u) | (v.y ? 2u : 0u) | (v.z ? 4u : 0u) | (v.w ? 8u : 0u);
        bits |= q << (4 * j);
    }
    out[i] = bits;
}

// ---------------- pipelined tf32x3 GEMM (R + out-proj) ----------------
#define ASTR 36
#define BSTR 72
#define TSTR 36
#define GEMM_SMEM ((2 * 128 * ASTR + 2 * 2304 + 64) * 4)

template <int TRANSB, int HASAB>
__global__ void __launch_bounds__(256) mma_gemm(
    const float* __restrict__ A, int lda, ll sAb, ll sAh,
    const float* __restrict__ B, int ldb, ll sBb, ll sBh,
    float* __restrict__ C, int ldc, ll sCb, ll sCh,
    int M, int N, int K,
    const float* __restrict__ bias, const float* __restrict__ aBias)
{
    extern __shared__ float sm[];
    float* As = sm;                       // [2][128][36]
    float* Bs = sm + 2 * 128 * ASTR;      // [2][2304]
    float* ab_s = Bs + 2 * 2304;          // [64]

    const int z = blockIdx.z, b = z >> 3, h = z & 7;
    A += (ll)b * sAb + (ll)h * sAh;
    B += (ll)b * sBb + (ll)h * sBh;

    const int tid = threadIdx.x;
    const int lane = tid & 31, wid = tid >> 5;
    const int g = lane >> 2, t = lane & 3;
    const int wm = wid & 3, wn = wid >> 2;
    const int m0 = blockIdx.y * 128, n0 = blockIdx.x * 64;

    if (HASAB && tid < 64) ab_s[tid] = aBias[h * DK + tid];

    uint32_t sA = (uint32_t)__cvta_generic_to_shared(As);
    uint32_t sB = (uint32_t)__cvta_generic_to_shared(Bs);

    const int a_row = tid >> 3, a_c4 = (tid & 7) << 2;
    const int bn_k = tid >> 4, bn_c4 = (tid & 15) << 2;
    const int bt_n = tid >> 3, bt_c4 = (tid & 7) << 2;

    auto stage = [&](int k0, int stg) {
        uint32_t aBase = sA + (uint32_t)(stg * 128 * ASTR) * 4;
        uint32_t bBase = sB + (uint32_t)(stg * 2304) * 4;
#pragma unroll
        for (int i = 0; i < 4; i++) {
            int row = a_row + 32 * i;
            cp_async16(aBase + (uint32_t)(row * ASTR + a_c4) * 4,
                       A + (ll)(m0 + row) * lda + k0 + a_c4, m0 + row < M);
        }
        if (!TRANSB) {
#pragma unroll
            for (int i = 0; i < 2; i++) {
                int k = bn_k + 16 * i;
                cp_async16(bBase + (uint32_t)(k * BSTR + bn_c4) * 4,
                           B + (ll)(k0 + k) * ldb + n0 + bn_c4, true);
            }
        } else {
#pragma unroll
            for (int i = 0; i < 2; i++) {
                int n = bt_n + 32 * i;
                cp_async16(bBase + (uint32_t)(n * TSTR + bt_c4) * 4,
                           B + (ll)(n0 + n) * ldb + k0 + bt_c4, n0 + n < N);
            }
        }
    };

    float d[2][4][4];
#pragma unroll
    for (int i = 0; i < 2; i++)
#pragma unroll
        for (int j = 0; j < 4; j++)
#pragma unroll
            for (int c = 0; c < 4; c++) d[i][j][c] = 0.f;

    const int nIter = K >> 5;
    stage(0, 0);
    cp_commit();

    for (int it = 0; it < nIter; it++) {
        __syncthreads();
        if (it + 1 < nIter) { stage((it + 1) << 5, (it + 1) & 1); cp_commit(); cp_wait<1>(); }
        else cp_wait<0>();
        __syncthreads();

        const float* pA = As + (it & 1) * 128 * ASTR;
        const float* pB = Bs + (it & 1) * 2304;
        const int k0 = it << 5;

#pragma unroll
        for (int ks = 0; ks < 4; ks++) {
            const int kb = ks * 8;
            float aH[2][4], aL[2][4];
            float ab0 = 0.f, ab1 = 0.f;
            if (HASAB) { ab0 = ab_s[k0 + kb + t]; ab1 = ab_s[k0 + kb + t + 4]; }
#pragma unroll
            for (int mt = 0; mt < 2; mt++) {
                int r0 = (wm * 32 + mt * 16 + g) * ASTR + kb;
                int r1 = r0 + 8 * ASTR;
                float v0 = pA[r0 + t] + ab0;
                float v1 = pA[r1 + t] + ab0;
                float v2 = pA[r0 + t + 4] + ab1;
                float v3 = pA[r1 + t + 4] + ab1;
                aH[mt][0] = tf32_hi(v0); aL[mt][0] = v0 - aH[mt][0];
                aH[mt][1] = tf32_hi(v1); aL[mt][1] = v1 - aH[mt][1];
                aH[mt][2] = tf32_hi(v2); aL[mt][2] = v2 - aH[mt][2];
                aH[mt][3] = tf32_hi(v3); aL[mt][3] = v3 - aH[mt][3];
            }
#pragma unroll
            for (int nt = 0; nt < 4; nt++) {
                int col = wn * 32 + nt * 8 + g;
                float r0, r1;
                if (!TRANSB) {
                    r0 = pB[(kb + t) * BSTR + col];
                    r1 = pB[(kb + t + 4) * BSTR + col];
                } else {
                    r0 = pB[col * TSTR + kb + t];
                    r1 = pB[col * TSTR + kb + t + 4];
                }
                float bh0 = tf32_hi(r0), bl0 = r0 - bh0;
                float bh1 = tf32_hi(r1), bl1 = r1 - bh1;
#pragma unroll
                for (int mt = 0; mt < 2; mt++) {
                    mma_tf32(d[mt][nt], aH[mt], bh0, bh1);
                    mma_tf32(d[mt][nt], aH[mt], bl0, bl1);
                    mma_tf32(d[mt][nt], aL[mt], bh0, bh1);
                }
            }
        }
    }

    float* Cz = C + (ll)b * sCb + (ll)h * sCh;
#pragma unroll
    for (int mt = 0; mt < 2; mt++) {
        int row = m0 + wm * 32 + mt * 16 + g;
#pragma unroll
        for (int nt = 0; nt < 4; nt++) {
            int col = n0 + wn * 32 + nt * 8 + 2 * t;
            float b0 = (bias && col < N) ? bias[col] : 0.f;
            float b1 = (bias && col + 1 < N) ? bias[col + 1] : 0.f;
            if (row < M) {
                if (col < N)     Cz[(ll)row * ldc + col]     = d[mt][nt][0] + b0;
                if (col + 1 < N) Cz[(ll)row * ldc + col + 1] = d[mt][nt][1] + b1;
            }
            if (row + 8 < M) {
                if (col < N)     Cz[(ll)(row + 8) * ldc + col]     = d[mt][nt][2] + b0;
                if (col + 1 < N) Cz[(ll)(row + 8) * ldc + col + 1] = d[mt][nt][3] + b1;
            }
        }
    }
}

// ---------------- fused Q/K/V/P projections: one launch, grid.z selects ----------------
__global__ void __launch_bounds__(256) proj_fused(
    const float* __restrict__ x, const float* __restrict__ pos,
    const float* __restrict__ Wq, const float* __restrict__ Wk,
    const float* __restrict__ Wv, const float* __restrict__ Wp,
    const float* __restrict__ bq, const float* __restrict__ bk,
    const float* __restrict__ bv, const float* __restrict__ bp,
    float* __restrict__ Q, float* __restrict__ K,
    float* __restrict__ V, float* __restrict__ P)
{
    const int sel = blockIdx.z;
    if (sel == 3 && blockIdx.y >= 16) return;
    const float* A    = (sel == 3) ? pos : x;
    const float* B    = sel == 0 ? Wq : sel == 1 ? Wk : sel == 2 ? Wv : Wp;
    const float* bias = sel == 0 ? bq : sel == 1 ? bk : sel == 2 ? bv : bp;
    float* C          = sel == 0 ? Q  : sel == 1 ? K  : sel == 2 ? V  : P;
    const int M = (sel == 3) ? LL : NB * TT;

    extern __shared__ float sm[];
    float* As = sm;
    float* Bs = sm + 2 * 128 * ASTR;

    const int tid = threadIdx.x;
    const int lane = tid & 31, wid = tid >> 5;
    const int g = lane >> 2, t = lane & 3;
    const int wm = wid & 3, wn = wid >> 2;
    const int m0 = blockIdx.y * 128, n0 = blockIdx.x * 64;

    uint32_t sA = (uint32_t)__cvta_generic_to_shared(As);
    uint32_t sB = (uint32_t)__cvta_generic_to_shared(Bs);

    const int a_row = tid >> 3, a_c4 = (tid & 7) << 2;
    const int bn_k = tid >> 4, bn_c4 = (tid & 15) << 2;

    auto stage = [&](int k0, int stg) {
        uint32_t aBase = sA + (uint32_t)(stg * 128 * ASTR) * 4;
        uint32_t bBase = sB + (uint32_t)(stg * 2304) * 4;
#pragma unroll
        for (int i = 0; i < 4; i++) {
            int row = a_row + 32 * i;
            cp_async16(aBase + (uint32_t)(row * ASTR + a_c4) * 4,
                       A + (ll)(m0 + row) * DM + k0 + a_c4, m0 + row < M);
        }
#pragma unroll
        for (int i = 0; i < 2; i++) {
            int k = bn_k + 16 * i;
            cp_async16(bBase + (uint32_t)(k * BSTR + bn_c4) * 4,
                       B + (ll)(k0 + k) * DM + n0 + bn_c4, true);
        }
    };

    float d[2][4][4];
#pragma unroll
    for (int i = 0; i < 2; i++)
#pragma unroll
        for (int j = 0; j < 4; j++)
#pragma unroll
            for (int c = 0; c < 4; c++) d[i][j][c] = 0.f;

    stage(0, 0);
    cp_commit();

    for (int it = 0; it < 16; it++) {
        __syncthreads();
        if (it + 1 < 16) { stage((it + 1) << 5, (it + 1) & 1); cp_commit(); cp_wait<1>(); }
        else cp_wait<0>();
        __syncthreads();

        const float* pA = As + (it & 1) * 128 * ASTR;
        const float* pB = Bs + (it & 1) * 2304;

#pragma unroll
        for (int ks = 0; ks < 4; ks++) {
            const int kb = ks * 8;
            float aH[2][4], aL[2][4];
#pragma unroll
            for (int mt = 0; mt < 2; mt++) {
                int r0 = (wm * 32 + mt * 16 + g) * ASTR + kb;
                int r1 = r0 + 8 * ASTR;
                float v0 = pA[r0 + t], v1 = pA[r1 + t];
                float v2 = pA[r0 + t + 4], v3 = pA[r1 + t + 4];
                aH[mt][0] = tf32_hi(v0); aL[mt][0] = v0 - aH[mt][0];
                aH[mt][1] = tf32_hi(v1); aL[mt][1] = v1 - aH[mt][1];
                aH[mt][2] = tf32_hi(v2); aL[mt][2] = v2 - aH[mt][2];
                aH[mt][3] = tf32_hi(v3); aL[mt][3] = v3 - aH[mt][3];
            }
#pragma unroll
            for (int nt = 0; nt < 4; nt++) {
                int col = wn * 32 + nt * 8 + g;
                float r0 = pB[(kb + t) * BSTR + col];
                float r1 = pB[(kb + t + 4) * BSTR + col];
                float bh0 = tf32_hi(r0), bl0 = r0 - bh0;
                float bh1 = tf32_hi(r1), bl1 = r1 - bh1;
#pragma unroll
                for (int mt = 0; mt < 2; mt++) {
                    mma_tf32(d[mt][nt], aH[mt], bh0, bh1);
                    mma_tf32(d[mt][nt], aH[mt], bl0, bl1);
                    mma_tf32(d[mt][nt], aL[mt], bh0, bh1);
                }
            }
        }
    }

#pragma unroll
    for (int mt = 0; mt < 2; mt++) {
        int row = m0 + wm * 32 + mt * 16 + g;
#pragma unroll
        for (int nt = 0; nt < 4; nt++) {
            int col = n0 + wn * 32 + nt * 8 + 2 * t;
            float b0 = bias[col], b1 = bias[col + 1];
            if (row < M) {
                C[(ll)row * DM + col]     = d[mt][nt][0] + b0;
                C[(ll)row * DM + col + 1] = d[mt][nt][1] + b1;
            }
            if (row + 8 < M) {
                C[(ll)(row + 8) * DM + col]     = d[mt][nt][2] + b0;
                C[(ll)(row + 8) * DM + col + 1] = d[mt][nt][3] + b1;
            }
        }
    }
}

// ---------------- fused flash attention (pre-split K/V in smem) ----------------
#define KSTR 68
#define VSTR 76
// KH[2][64][KSTR], KL[64][KSTR], VH[2][64][VSTR], VL[64][VSTR]
#define FL_SMEM ((3 * 64 * KSTR + 3 * 64 * VSTR) * 4)

__global__ void __launch_bounds__(128, 2) flash_attn(
    const float* __restrict__ Q, const float* __restrict__ Kg,
    const float* __restrict__ Vg, const float* __restrict__ pbu,
    const float* __restrict__ Rr, const unsigned int* __restrict__ mbits,
    float* __restrict__ Og)
{
    extern __shared__ float sm[];
    float* KH = sm;                        // [2][64][KSTR]  (raw lands here, hi in-place)
    float* KL = KH + 2 * 64 * KSTR;        // [64][KSTR]
    float* VH = KL + 64 * KSTR;            // [2][64][VSTR]
    float* VL = VH + 2 * 64 * VSTR;        // [64][VSTR]

    const int z = blockIdx.y, b = z >> 3, h = z & 7;
    const int t0 = blockIdx.x * 64;
    const int tid = threadIdx.x, lane = tid & 31, w = tid >> 5;
    const int g = lane >> 2, t = lane & 3;

    const float* Qb = Q + ((ll)(b * TT + t0)) * DM + h * DK;
    const float* Kb = Kg + ((ll)(b * TT)) * DM + h * DK;
    const float* Vb = Vg + ((ll)(b * TT)) * DM + h * DK;
    const ll rb = (ll)z * 512 * LL;

    // Q fragments in registers (+pbu), split once
    float qh[8][4], ql[8][4];
    {
        int r0 = w * 16 + g, r1 = r0 + 8;
#pragma unroll
        for (int ks = 0; ks < 8; ks++) {
            int c0 = ks * 8 + t, c1 = c0 + 4;
            float u0 = pbu[h * DK + c0], u1 = pbu[h * DK + c1];
            float v0 = Qb[(ll)r0 * DM + c0] + u0;
            float v1 = Qb[(ll)r1 * DM + c0] + u0;
            float v2 = Qb[(ll)r0 * DM + c1] + u1;
            float v3 = Qb[(ll)r1 * DM + c1] + u1;
            qh[ks][0] = tf32_hi(v0); ql[ks][0] = v0 - qh[ks][0];
            qh[ks][1] = tf32_hi(v1); ql[ks][1] = v1 - qh[ks][1];
            qh[ks][2] = tf32_hi(v2); ql[ks][2] = v2 - qh[ks][2];
            qh[ks][3] = tf32_hi(v3); ql[ks][3] = v3 - qh[ks][3];
        }
    }

    float o[8][4];
#pragma unroll
    for (int i = 0; i < 8; i++)
#pragma unroll
        for (int j = 0; j < 4; j++) o[i][j] = 0.f;
    float mx0 = -1e30f, mx1 = -1e30f, l0 = 0.f, l1 = 0.f;

    uint32_t sK = (uint32_t)__cvta_generic_to_shared(KH);
    uint32_t sV = (uint32_t)__cvta_generic_to_shared(VH);

    auto loadKV = [&](int st, int buf) {
        const float* kp = Kb + (ll)(st * 64) * DM;
        const float* vp = Vb + (ll)(st * 64) * DM;
        uint32_t kBase = sK + (uint32_t)(buf * 64 * KSTR) * 4;
        uint32_t vBase = sV + (uint32_t)(buf * 64 * VSTR) * 4;
#pragma unroll
        for (int i = 0; i < 8; i++) {
            int idx = tid + 128 * i;
            int row = idx >> 4, c4 = (idx & 15) << 2;
            cp_async16(kBase + (uint32_t)(row * KSTR + c4) * 4, kp + (ll)row * DM + c4, true);
            cp_async16(vBase + (uint32_t)(row * VSTR + c4) * 4, vp + (ll)row * DM + c4, true);
        }
    };

    loadKV(0, 0);
    cp_commit();

    const int tg0 = t0 + w * 16 + g, tg1 = tg0 + 8;
    const float* R0 = Rr + rb + (ll)(tg0 >> 1) * LL;
    const float* R1 = Rr + rb + (ll)(tg1 >> 1) * LL;
    const int p0 = (tg0 & 1) << 10, p1 = (tg1 & 1) << 10;
    const uint2* mrow0 = (const uint2*)(mbits + ((ll)b * TT + tg0) * 32);
    const uint2* mrow1 = (const uint2*)(mbits + ((ll)b * TT + tg1) * 32);

    for (int st = 0; st < 16; st++) {
        const int buf = st & 1;
        cp_wait<0>();
        __syncthreads();
        // prefetch next stage raw tiles into the other buffer
        if (st + 1 < 16) { loadKV(st + 1, 1 - buf); cp_commit(); }

        // ---- split pass: hi in place, lo to KL/VL ----
        {
            float4* kh4 = (float4*)(KH + buf * 64 * KSTR);
            float4* kl4 = (float4*)KL;
            float4* vh4 = (float4*)(VH + buf * 64 * VSTR);
            float4* vl4 = (float4*)VL;
#pragma unroll
            for (int i = 0; i < 8; i++) {
                int idx = tid + 128 * i;
                int row = idx >> 4, q4 = idx & 15;
                int kidx = row * 17 + q4;         // KSTR/4 = 17
                float4 v = kh4[kidx];
                float4 hv, lv;
                hv.x = tf32_hi(v.x); lv.x = v.x - hv.x;
                hv.y = tf32_hi(v.y); lv.y = v.y - hv.y;
                hv.z = tf32_hi(v.z); lv.z = v.z - hv.z;
                hv.w = tf32_hi(v.w); lv.w = v.w - hv.w;
                kh4[kidx] = hv; kl4[kidx] = lv;

                int vidx = row * 19 + q4;         // VSTR/4 = 19
                float4 u = vh4[vidx];
                float4 hu, lu;
                hu.x = tf32_hi(u.x); lu.x = u.x - hu.x;
                hu.y = tf32_hi(u.y); lu.y = u.y - hu.y;
                hu.z = tf32_hi(u.z); lu.z = u.z - hu.z;
                hu.w = tf32_hi(u.w); lu.w = u.w - hu.w;
                vh4[vidx] = hu; vl4[vidx] = lu;
            }
        }
        __syncthreads();

        const float* pKH = KH + buf * 64 * KSTR;
        const float* pVH = VH + buf * 64 * VSTR;

        // ---- scores = Q @ K^T (tf32x3, pre-split B) ----
        float sc[8][4];
#pragma unroll
        for (int i = 0; i < 8; i++)
#pragma unroll
            for (int j = 0; j < 4; j++) sc[i][j] = 0.f;
#pragma unroll
        for (int nt = 0; nt < 8; nt++) {
            int srow = (nt * 8 + g) * KSTR;
#pragma unroll
            for (int ks = 0; ks < 8; ks++) {
                float bh0 = pKH[srow + ks * 8 + t];
                float bh1 = pKH[srow + ks * 8 + t + 4];
                float bl0 = KL[srow + ks * 8 + t];
                float bl1 = KL[srow + ks * 8 + t + 4];
                mma_tf32(sc[nt], qh[ks], bh0, bh1);
                mma_tf32(sc[nt], qh[ks], bl0, bl1);
                mma_tf32(sc[nt], ql[ks], bh0, bh1);
            }
        }

        // ---- epilogue: pos + scale + mask, online softmax ----
        const int s0 = st * 64;
#pragma unroll
        for (int nt = 0; nt < 8; nt++) {
            int s_ = s0 + nt * 8 + 2 * t;
            int la = s_ + p0, lb = s_ + p1;
            float pa0 = (la == LL) ? 0.f : R0[la];
            float pa1 = (la + 1 == LL) ? 0.f : R0[la + 1];
            float pb0 = (lb == LL) ? 0.f : R1[lb];
            float pb1 = (lb + 1 == LL) ? 0.f : R1[lb + 1];
            sc[nt][0] = (sc[nt][0] + pa0) * 0.125f;
            sc[nt][1] = (sc[nt][1] + pa1) * 0.125f;
            sc[nt][2] = (sc[nt][2] + pb0) * 0.125f;
            sc[nt][3] = (sc[nt][3] + pb1) * 0.125f;
        }
        {
            uint2 w0 = mrow0[st], w1 = mrow1[st];
            u64 m0 = (u64)w0.x | ((u64)w0.y << 32);
            u64 m1 = (u64)w1.x | ((u64)w1.y << 32);
            if (m0 | m1) {
#pragma unroll
                for (int nt = 0; nt < 8; nt++) {
                    int p = nt * 8 + 2 * t;
                    if ((m0 >> p) & 1)       sc[nt][0] = -1e9f;
                    if ((m0 >> (p + 1)) & 1) sc[nt][1] = -1e9f;
                    if ((m1 >> p) & 1)       sc[nt][2] = -1e9f;
                    if ((m1 >> (p + 1)) & 1) sc[nt][3] = -1e9f;
                }
            }
        }

        float rmx0 = -1e30f, rmx1 = -1e30f;
#pragma unroll
        for (int nt = 0; nt < 8; nt++) {
            rmx0 = fmaxf(rmx0, fmaxf(sc[nt][0], sc[nt][1]));
            rmx1 = fmaxf(rmx1, fmaxf(sc[nt][2], sc[nt][3]));
        }
        rmx0 = fmaxf(rmx0, __shfl_xor_sync(0xffffffffu, rmx0, 1));
        rmx0 = fmaxf(rmx0, __shfl_xor_sync(0xffffffffu, rmx0, 2));
        rmx1 = fmaxf(rmx1, __shfl_xor_sync(0xffffffffu, rmx1, 1));
        rmx1 = fmaxf(rmx1, __shfl_xor_sync(0xffffffffu, rmx1, 2));

        float mn0 = fmaxf(mx0, rmx0), mn1 = fmaxf(mx1, rmx1);
        float al0 = __expf(mx0 - mn0), al1 = __expf(mx1 - mn1);
        float rs0 = 0.f, rs1 = 0.f;
#pragma unroll
        for (int nt = 0; nt < 8; nt++) {
            sc[nt][0] = __expf(sc[nt][0] - mn0);
            sc[nt][1] = __expf(sc[nt][1] - mn0);
            sc[nt][2] = __expf(sc[nt][2] - mn1);
            sc[nt][3] = __expf(sc[nt][3] - mn1);
            rs0 += sc[nt][0] + sc[nt][1];
            rs1 += sc[nt][2] + sc[nt][3];
        }
        rs0 += __shfl_xor_sync(0xffffffffu, rs0, 1);
        rs0 += __shfl_xor_sync(0xffffffffu, rs0, 2);
        rs1 += __shfl_xor_sync(0xffffffffu, rs1, 1);
        rs1 += __shfl_xor_sync(0xffffffffu, rs1, 2);
        l0 = l0 * al0 + rs0;
        l1 = l1 * al1 + rs1;
        mx0 = mn0; mx1 = mn1;
#pragma unroll
        for (int dt = 0; dt < 8; dt++) {
            o[dt][0] *= al0; o[dt][1] *= al0;
            o[dt][2] *= al1; o[dt][3] *= al1;
        }

        // ---- O += P @ V (accumulator reused as A, positional-k perm) ----
#pragma unroll
        for (int s8 = 0; s8 < 8; s8++) {
            float a0 = sc[s8][0], a1 = sc[s8][2], a2 = sc[s8][1], a3 = sc[s8][3];
            float ah[4], al_[4];
            ah[0] = tf32_hi(a0); al_[0] = a0 - ah[0];
            ah[1] = tf32_hi(a1); al_[1] = a1 - ah[1];
            ah[2] = tf32_hi(a2); al_[2] = a2 - ah[2];
            ah[3] = tf32_hi(a3); al_[3] = a3 - ah[3];
            int vr0 = (s8 * 8 + 2 * t) * VSTR, vr1 = vr0 + VSTR;
#pragma unroll
            for (int dt = 0; dt < 8; dt++) {
                int col = dt * 8 + g;
                float bh0 = pVH[vr0 + col], bh1 = pVH[vr1 + col];
                float bl0 = VL[vr0 + col],  bl1 = VL[vr1 + col];
                mma_tf32(o[dt], ah, bh0, bh1);
                mma_tf32(o[dt], ah, bl0, bl1);
                mma_tf32(o[dt], al_, bh0, bh1);
            }
        }
    }

    float inv0 = 1.f / l0, inv1 = 1.f / l1;
    float* o0 = Og + ((ll)(b * TT + tg0)) * DM + h * DK;
    float* o1 = Og + ((ll)(b * TT + tg1)) * DM + h * DK;
#pragma unroll
    for (int dt = 0; dt < 8; dt++) {
        int d0 = dt * 8 + 2 * t;
        o0[d0] = o[dt][0] * inv0; o0[d0 + 1] = o[dt][1] * inv0;
        o1[d0] = o[dt][2] * inv1; o1[d0 + 1] = o[dt][3] * inv1;
    }
}

// ---------------- launch ----------------
extern "C" void kernel_launch(void* const* d_in, const int* in_sizes, int n_in,
                              void* d_out, int out_size)
{
    const float* x   = (const float*)d_in[0];
    const float* pos = (const float*)d_in[1];
    const unsigned char* mask = (const unsigned char*)d_in[2];
    const float* Wq = (const float*)d_in[3];  const float* bq = (const float*)d_in[4];
    const float* Wk = (const float*)d_in[5];  const float* bk = (const float*)d_in[6];
    const float* Wv = (const float*)d_in[7];  const float* bv = (const float*)d_in[8];
    const float* Wp = (const float*)d_in[9];  const float* bp = (const float*)d_in[10];
    const float* Wo = (const float*)d_in[11]; const float* bo = (const float*)d_in[12];
    const float* pbu = (const float*)d_in[13];
    const float* pbv = (const float*)d_in[14];
    float* out = (float*)d_out;

    float *Q, *K, *V, *P, *R, *O;
    unsigned int* Mb;
    cudaGetSymbolAddress((void**)&Q, g_Q);
    cudaGetSymbolAddress((void**)&K, g_K);
    cudaGetSymbolAddress((void**)&V, g_V);
    cudaGetSymbolAddress((void**)&P, g_P);
    cudaGetSymbolAddress((void**)&R, g_R);
    cudaGetSymbolAddress((void**)&O, g_O);
    cudaGetSymbolAddress((void**)&Mb, g_Mb);

    cudaFuncSetAttribute(proj_fused, cudaFuncAttributeMaxDynamicSharedMemorySize, GEMM_SMEM);
    cudaFuncSetAttribute(mma_gemm<0, 0>, cudaFuncAttributeMaxDynamicSharedMemorySize, GEMM_SMEM);
    cudaFuncSetAttribute(mma_gemm<1, 1>, cudaFuncAttributeMaxDynamicSharedMemorySize, GEMM_SMEM);
    cudaFuncSetAttribute(flash_attn, cudaFuncAttributeMaxDynamicSharedMemorySize, FL_SMEM);

    dim3 blk(256);

    // pack mask bits (512 blocks x 256 threads over 4MB)
    mask_pack<<<512, 256>>>(mask, Mb);

    // fused Q/K/V/P projections
    proj_fused<<<dim3(8, 32, 4), blk, GEMM_SMEM>>>(
        x, pos, Wq, Wk, Wv, Wp, bq, bk, bv, bp, Q, K, V, P);

    // R = (Q[512:] + pos_bias_v) @ P^T per (b,h): M=512, N=2047, K=64
    mma_gemm<1, 1><<<dim3(32, 4, 32), blk, GEMM_SMEM>>>(
        Q + 512 * DM, DM, (ll)TT * DM, DK,
        P, DM, 0, DK,
        R, LL, 8LL * 512 * LL, (ll)512 * LL,
        512, LL, DK, nullptr, pbv);

    // fused scores + softmax + AV
    flash_attn<<<dim3(16, 32), dim3(128), FL_SMEM>>>(Q, K, V, pbu, R, Mb, O);

    // out = O @ Wo + bo
    mma_gemm<0, 0><<<dim3(8, 32, 1), blk, GEMM_SMEM>>>(
        O, DM, 0, 0, Wo, DM, 0, 0, out, DM, 0, 0,
        NB * TT, DM, DM, bo, nullptr);
}

// round 6
// speedup vs baseline: 1.5533x; 1.5533x over previous
#include <cuda_runtime.h>
#include <cuda_bf16.h>
#include <cstdint>

#define TT 1024
#define DM 512
#define NB 4
#define NH 8
#define DK 64
#define LL 2047   // 2*T - 1
#define RSTR 2048 // padded R row stride (even => aligned float2 gathers)
typedef long long ll;
typedef unsigned long long u64;

// ---------------- scratch ----------------
__device__ float g_Q[NB * TT * DM];
__device__ float g_K[NB * TT * DM];
__device__ float g_V[NB * TT * DM];
__device__ float g_P[2048 * DM];
__device__ float g_R[32LL * 512 * RSTR];     // [z][m][l], stride 2048
__device__ float g_O[NB * TT * DM];
__device__ unsigned int g_Mb[NB * TT * 32];        // bit-packed mask
__device__ unsigned int g_Kph[32LL * 1024 * 32];   // K bf16-hi pairs along d
__device__ unsigned int g_Kpl[32LL * 1024 * 32];   // K bf16-lo
__device__ unsigned int g_VTh[32LL * 64 * 512];    // V^T bf16-hi pairs along s
__device__ unsigned int g_VTl[32LL * 64 * 512];    // V^T bf16-lo

// ---------------- helpers ----------------
__device__ __forceinline__ float tf32_hi(float x) {
    uint32_t uh;
    asm("cvt.rna.tf32.f32 %0, %1;" : "=r"(uh) : "f"(x));
    return __uint_as_float(uh);
}
__device__ __forceinline__ float bf16_hi(float x) {
    return __bfloat162float(__float2bfloat16(x));
}
// pack two floats to bf16x2: lower half = lo_elem (smaller k), upper = hi_elem
__device__ __forceinline__ uint32_t pack_bf16(float lo_elem, float hi_elem) {
    uint32_t r;
    asm("cvt.rn.bf16x2.f32 %0, %1, %2;" : "=r"(r) : "f"(hi_elem), "f"(lo_elem));
    return r;
}

__device__ __forceinline__ void mma_tf32(float* d, const float* a, float b0, float b1) {
    asm volatile(
        "mma.sync.aligned.m16n8k8.row.col.f32.tf32.tf32.f32 "
        "{%0,%1,%2,%3}, {%4,%5,%6,%7}, {%8,%9}, {%0,%1,%2,%3};\n"
        : "+f"(d[0]), "+f"(d[1]), "+f"(d[2]), "+f"(d[3])
        : "r"(__float_as_uint(a[0])), "r"(__float_as_uint(a[1])),
          "r"(__float_as_uint(a[2])), "r"(__float_as_uint(a[3])),
          "r"(__float_as_uint(b0)), "r"(__float_as_uint(b1)));
}

__device__ __forceinline__ void mma_bf16(float* d, const uint32_t* a, uint32_t b0, uint32_t b1) {
    asm volatile(
        "mma.sync.aligned.m16n8k16.row.col.f32.bf16.bf16.f32 "
        "{%0,%1,%2,%3}, {%4,%5,%6,%7}, {%8,%9}, {%0,%1,%2,%3};\n"
        : "+f"(d[0]), "+f"(d[1]), "+f"(d[2]), "+f"(d[3])
        : "r"(a[0]), "r"(a[1]), "r"(a[2]), "r"(a[3]), "r"(b0), "r"(b1));
}

__device__ __forceinline__ void cp_async16(uint32_t dst, const void* src, bool p) {
    asm volatile("cp.async.cg.shared.global [%0], [%1], 16, %2;\n"
                 :: "r"(dst), "l"(src), "r"(p ? 16 : 0));
}
__device__ __forceinline__ void cp_commit() { asm volatile("cp.async.commit_group;\n"); }
template <int N>
__device__ __forceinline__ void cp_wait() { asm volatile("cp.async.wait_group %0;\n" :: "n"(N)); }

// ---------------- mask bit-pack ----------------
__global__ void __launch_bounds__(256) mask_pack(const unsigned char* __restrict__ m,
                                                 unsigned int* __restrict__ out)
{
    int i = blockIdx.x * 256 + threadIdx.x;
    const uchar4* p = (const uchar4*)(m + (ll)i * 32);
    unsigned int bits = 0;
#pragma unroll
    for (int j = 0; j < 8; j++) {
        uchar4 v = p[j];
        unsigned int q = (v.x ? 1u : 0u) | (v.y ? 2u : 0u) | (v.z ? 4u : 0u) | (v.w ? 8u : 0u);
        bits |= q << (4 * j);
    }
    out[i] = bits;
}

// ---------------- K/V bf16 split-pack (+ V transpose) ----------------
// grid(16, 32): x = s-tile(64), y = z=(b,h). 256 threads.
__global__ void __launch_bounds__(256) kv_pack(
    const float* __restrict__ Kf, const float* __restrict__ Vf,
    unsigned int* __restrict__ Kph, unsigned int* __restrict__ Kpl,
    unsigned int* __restrict__ VTh, unsigned int* __restrict__ VTl)
{
    __shared__ float sv[64][65];
    const int z = blockIdx.y, b = z >> 3, h = z & 7;
    const int s0 = blockIdx.x * 64;
    const int tid = threadIdx.x;
    const int row = tid >> 2, cq = (tid & 3) << 4;

    // ---- K: direct pack, pairs along d ----
    {
        const float* kr = Kf + ((ll)(b * TT + s0 + row)) * DM + h * DK + cq;
        float v[16];
#pragma unroll
        for (int i = 0; i < 4; i++) {
            float4 f = *(const float4*)(kr + 4 * i);
            v[4 * i] = f.x; v[4 * i + 1] = f.y; v[4 * i + 2] = f.z; v[4 * i + 3] = f.w;
        }
        ll base = ((ll)z * 1024 + s0 + row) * 32 + (cq >> 1);
#pragma unroll
        for (int j = 0; j < 8; j++) {
            float x0 = v[2 * j], x1 = v[2 * j + 1];
            float h0 = bf16_hi(x0), h1 = bf16_hi(x1);
            Kph[base + j] = pack_bf16(x0, x1);
            Kpl[base + j] = pack_bf16(x0 - h0, x1 - h1);
        }
    }

    // ---- V: load tile to smem, transpose, pack pairs along s ----
    {
        const float* vr = Vf + ((ll)(b * TT + s0 + row)) * DM + h * DK + cq;
#pragma unroll
        for (int i = 0; i < 4; i++) {
            float4 f = *(const float4*)(vr + 4 * i);
            sv[row][cq + 4 * i] = f.x; sv[row][cq + 4 * i + 1] = f.y;
            sv[row][cq + 4 * i + 2] = f.z; sv[row][cq + 4 * i + 3] = f.w;
        }
    }
    __syncthreads();
    {
        const int d = tid >> 2, sq = (tid & 3) << 4;
        ll base = ((ll)z * 64 + d) * 512 + ((s0 + sq) >> 1);
#pragma unroll
        for (int j = 0; j < 8; j++) {
            float x0 = sv[sq + 2 * j][d], x1 = sv[sq + 2 * j + 1][d];
            float h0 = bf16_hi(x0), h1 = bf16_hi(x1);
            VTh[base + j] = pack_bf16(x0, x1);
            VTl[base + j] = pack_bf16(x0 - h0, x1 - h1);
        }
    }
}

// ---------------- pipelined tf32x3 GEMM (projections, R, out-proj) ----------------
#define ASTR 36
#define BSTR 72
#define TSTR 36
#define GEMM_SMEM ((2 * 128 * ASTR + 2 * 2304 + 64) * 4)

template <int TRANSB, int HASAB>
__global__ void __launch_bounds__(256) mma_gemm(
    const float* __restrict__ A, int lda, ll sAb, ll sAh,
    const float* __restrict__ B, int ldb, ll sBb, ll sBh,
    float* __restrict__ C, int ldc, ll sCb, ll sCh,
    int M, int N, int K,
    const float* __restrict__ bias, const float* __restrict__ aBias)
{
    extern __shared__ float sm[];
    float* As = sm;
    float* Bs = sm + 2 * 128 * ASTR;
    float* ab_s = Bs + 2 * 2304;

    const int z = blockIdx.z, b = z >> 3, h = z & 7;
    A += (ll)b * sAb + (ll)h * sAh;
    B += (ll)b * sBb + (ll)h * sBh;

    const int tid = threadIdx.x;
    const int lane = tid & 31, wid = tid >> 5;
    const int g = lane >> 2, t = lane & 3;
    const int wm = wid & 3, wn = wid >> 2;
    const int m0 = blockIdx.y * 128, n0 = blockIdx.x * 64;

    if (HASAB && tid < 64) ab_s[tid] = aBias[h * DK + tid];

    uint32_t sA = (uint32_t)__cvta_generic_to_shared(As);
    uint32_t sB = (uint32_t)__cvta_generic_to_shared(Bs);

    const int a_row = tid >> 3, a_c4 = (tid & 7) << 2;
    const int bn_k = tid >> 4, bn_c4 = (tid & 15) << 2;
    const int bt_n = tid >> 3, bt_c4 = (tid & 7) << 2;

    auto stage = [&](int k0, int stg) {
        uint32_t aBase = sA + (uint32_t)(stg * 128 * ASTR) * 4;
        uint32_t bBase = sB + (uint32_t)(stg * 2304) * 4;
#pragma unroll
        for (int i = 0; i < 4; i++) {
            int row = a_row + 32 * i;
            cp_async16(aBase + (uint32_t)(row * ASTR + a_c4) * 4,
                       A + (ll)(m0 + row) * lda + k0 + a_c4, m0 + row < M);
        }
        if (!TRANSB) {
#pragma unroll
            for (int i = 0; i < 2; i++) {
                int k = bn_k + 16 * i;
                cp_async16(bBase + (uint32_t)(k * BSTR + bn_c4) * 4,
                           B + (ll)(k0 + k) * ldb + n0 + bn_c4, true);
            }
        } else {
#pragma unroll
            for (int i = 0; i < 2; i++) {
                int n = bt_n + 32 * i;
                cp_async16(bBase + (uint32_t)(n * TSTR + bt_c4) * 4,
                           B + (ll)(n0 + n) * ldb + k0 + bt_c4, n0 + n < N);
            }
        }
    };

    float d[2][4][4];
#pragma unroll
    for (int i = 0; i < 2; i++)
#pragma unroll
        for (int j = 0; j < 4; j++)
#pragma unroll
            for (int c = 0; c < 4; c++) d[i][j][c] = 0.f;

    const int nIter = K >> 5;
    stage(0, 0);
    cp_commit();

    for (int it = 0; it < nIter; it++) {
        __syncthreads();
        if (it + 1 < nIter) { stage((it + 1) << 5, (it + 1) & 1); cp_commit(); cp_wait<1>(); }
        else cp_wait<0>();
        __syncthreads();

        const float* pA = As + (it & 1) * 128 * ASTR;
        const float* pB = Bs + (it & 1) * 2304;
        const int k0 = it << 5;

#pragma unroll
        for (int ks = 0; ks < 4; ks++) {
            const int kb = ks * 8;
            float aH[2][4], aL[2][4];
            float ab0 = 0.f, ab1 = 0.f;
            if (HASAB) { ab0 = ab_s[k0 + kb + t]; ab1 = ab_s[k0 + kb + t + 4]; }
#pragma unroll
            for (int mt = 0; mt < 2; mt++) {
                int r0 = (wm * 32 + mt * 16 + g) * ASTR + kb;
                int r1 = r0 + 8 * ASTR;
                float v0 = pA[r0 + t] + ab0;
                float v1 = pA[r1 + t] + ab0;
                float v2 = pA[r0 + t + 4] + ab1;
                float v3 = pA[r1 + t + 4] + ab1;
                aH[mt][0] = tf32_hi(v0); aL[mt][0] = v0 - aH[mt][0];
                aH[mt][1] = tf32_hi(v1); aL[mt][1] = v1 - aH[mt][1];
                aH[mt][2] = tf32_hi(v2); aL[mt][2] = v2 - aH[mt][2];
                aH[mt][3] = tf32_hi(v3); aL[mt][3] = v3 - aH[mt][3];
            }
#pragma unroll
            for (int nt = 0; nt < 4; nt++) {
                int col = wn * 32 + nt * 8 + g;
                float r0, r1;
                if (!TRANSB) {
                    r0 = pB[(kb + t) * BSTR + col];
                    r1 = pB[(kb + t + 4) * BSTR + col];
                } else {
                    r0 = pB[col * TSTR + kb + t];
                    r1 = pB[col * TSTR + kb + t + 4];
                }
                float bh0 = tf32_hi(r0), bl0 = r0 - bh0;
                float bh1 = tf32_hi(r1), bl1 = r1 - bh1;
#pragma unroll
                for (int mt = 0; mt < 2; mt++) {
                    mma_tf32(d[mt][nt], aH[mt], bh0, bh1);
                    mma_tf32(d[mt][nt], aH[mt], bl0, bl1);
                    mma_tf32(d[mt][nt], aL[mt], bh0, bh1);
                }
            }
        }
    }

    float* Cz = C + (ll)b * sCb + (ll)h * sCh;
#pragma unroll
    for (int mt = 0; mt < 2; mt++) {
        int row = m0 + wm * 32 + mt * 16 + g;
#pragma unroll
        for (int nt = 0; nt < 4; nt++) {
            int col = n0 + wn * 32 + nt * 8 + 2 * t;
            float b0 = (bias && col < N) ? bias[col] : 0.f;
            float b1 = (bias && col + 1 < N) ? bias[col + 1] : 0.f;
            if (row < M) {
                if (col < N)     Cz[(ll)row * ldc + col]     = d[mt][nt][0] + b0;
                if (col + 1 < N) Cz[(ll)row * ldc + col + 1] = d[mt][nt][1] + b1;
            }
            if (row + 8 < M) {
                if (col < N)     Cz[(ll)(row + 8) * ldc + col]     = d[mt][nt][2] + b0;
                if (col + 1 < N) Cz[(ll)(row + 8) * ldc + col + 1] = d[mt][nt][3] + b1;
            }
        }
    }
}

// ---------------- fused flash attention: bf16x2 m16n8k16 ----------------
// grid(16, 32): x = Q-block (64 rows), y = z=(b,h). 128 threads, 4 warps x 16 rows.
#define PSTR 36
#define FL_SMEM (8 * 2304 * 4)   // 4 arrays x 2 bufs x [64][36] uint

__global__ void __launch_bounds__(128, 3) flash_attn(
    const float* __restrict__ Q,
    const unsigned int* __restrict__ Kph, const unsigned int* __restrict__ Kpl,
    const unsigned int* __restrict__ VTh, const unsigned int* __restrict__ VTl,
    const float* __restrict__ pbu, const float* __restrict__ Rr,
    const unsigned int* __restrict__ mbits, float* __restrict__ Og)
{
    extern __shared__ uint32_t smu[];
    uint32_t* KH = smu;               // [2][64*36]
    uint32_t* KL = smu + 2 * 2304;
    uint32_t* VH = smu + 4 * 2304;
    uint32_t* VL = smu + 6 * 2304;

    const int z = blockIdx.y, b = z >> 3, h = z & 7;
    const int t0 = blockIdx.x * 64;
    const int tid = threadIdx.x, lane = tid & 31, w = tid >> 5;
    const int g = lane >> 2, t = lane & 3;

    const float* Qb = Q + ((ll)(b * TT + t0)) * DM + h * DK;
    const ll rb = (ll)z * 512 * RSTR;

    // ---- Q fragments: bf16 hi/lo packed, k-pairs. 4 k16-steps x 4 regs ----
    uint32_t qh[4][4], ql[4][4];
    {
        const int r0 = w * 16 + g, r1 = r0 + 8;
#pragma unroll
        for (int ks = 0; ks < 4; ks++) {
#pragma unroll
            for (int half = 0; half < 2; half++) {
                int c = 16 * ks + 8 * half + 2 * t;
                float u0 = pbu[h * DK + c], u1 = pbu[h * DK + c + 1];
                float x0 = Qb[(ll)r0 * DM + c] + u0;
                float x1 = Qb[(ll)r0 * DM + c + 1] + u1;
                float y0 = Qb[(ll)r1 * DM + c] + u0;
                float y1 = Qb[(ll)r1 * DM + c + 1] + u1;
                float hx0 = bf16_hi(x0), hx1 = bf16_hi(x1);
                float hy0 = bf16_hi(y0), hy1 = bf16_hi(y1);
                qh[ks][2 * half + 0] = pack_bf16(x0, x1);
                qh[ks][2 * half + 1] = pack_bf16(y0, y1);
                ql[ks][2 * half + 0] = pack_bf16(x0 - hx0, x1 - hx1);
                ql[ks][2 * half + 1] = pack_bf16(y0 - hy0, y1 - hy1);
            }
        }
    }

    float o[8][4];
#pragma unroll
    for (int i = 0; i < 8; i++)
#pragma unroll
        for (int j = 0; j < 4; j++) o[i][j] = 0.f;
    float mx0 = -1e30f, mx1 = -1e30f, l0 = 0.f, l1 = 0.f;

    uint32_t sBase = (uint32_t)__cvta_generic_to_shared(smu);

    auto loadKV = [&](int st, int buf) {
        const unsigned int* kh = Kph + ((ll)z * 1024 + st * 64) * 32;
        const unsigned int* kl = Kpl + ((ll)z * 1024 + st * 64) * 32;
        const unsigned int* vh = VTh + (ll)z * 64 * 512 + st * 32;
        const unsigned int* vl = VTl + (ll)z * 64 * 512 + st * 32;
        uint32_t o0 = sBase + (uint32_t)(buf * 2304) * 4;
#pragma unroll
        for (int i = 0; i < 4; i++) {
            int idx = tid + 128 * i;
            int row = idx >> 3, c4 = (idx & 7) << 2;
            uint32_t soff = (uint32_t)(row * PSTR + c4) * 4;
            cp_async16(o0 + soff,                kh + (ll)row * 32 + c4, true);
            cp_async16(o0 + 2 * 2304 * 4 + soff, kl + (ll)row * 32 + c4, true);
            cp_async16(o0 + 4 * 2304 * 4 + soff, vh + (ll)row * 512 + c4, true);
            cp_async16(o0 + 6 * 2304 * 4 + soff, vl + (ll)row * 512 + c4, true);
        }
    };

    loadKV(0, 0);
    cp_commit();

    const int tg0 = t0 + w * 16 + g, tg1 = tg0 + 8;
    const float* R0 = Rr + rb + (ll)(tg0 >> 1) * RSTR;
    const float* R1 = Rr + rb + (ll)(tg1 >> 1) * RSTR;
    const int p0 = (tg0 & 1) << 10, p1 = (tg1 & 1) << 10;
    const uint2* mrow0 = (const uint2*)(mbits + ((ll)b * TT + tg0) * 32);
    const uint2* mrow1 = (const uint2*)(mbits + ((ll)b * TT + tg1) * 32);

    for (int st = 0; st < 16; st++) {
        const int buf = st & 1;
        cp_wait<0>();
        __syncthreads();
        if (st + 1 < 16) { loadKV(st + 1, 1 - buf); cp_commit(); }

        const uint32_t* pKH = KH + buf * 2304;
        const uint32_t* pKL = KL + buf * 2304;
        const uint32_t* pVH = VH + buf * 2304;
        const uint32_t* pVL = VL + buf * 2304;

        // ---- scores = Q @ K^T (bf16x2: 3 products, m16n8k16) ----
        float sc[8][4];
#pragma unroll
        for (int i = 0; i < 8; i++)
#pragma unroll
            for (int j = 0; j < 4; j++) sc[i][j] = 0.f;
#pragma unroll
        for (int nt = 0; nt < 8; nt++) {
            const int srow = (nt * 8 + g) * PSTR;
#pragma unroll
            for (int ks = 0; ks < 4; ks++) {
                uint32_t b0h = pKH[srow + 8 * ks + t];
                uint32_t b1h = pKH[srow + 8 * ks + 4 + t];
                uint32_t b0l = pKL[srow + 8 * ks + t];
                uint32_t b1l = pKL[srow + 8 * ks + 4 + t];
                mma_bf16(sc[nt], qh[ks], b0h, b1h);
                mma_bf16(sc[nt], ql[ks], b0h, b1h);
                mma_bf16(sc[nt], qh[ks], b0l, b1l);
            }
        }

        // ---- pos + scale + mask ----
        const int s0 = st * 64;
#pragma unroll
        for (int nt = 0; nt < 8; nt++) {
            int s_ = s0 + nt * 8 + 2 * t;
            int la = s_ + p0, lb = s_ + p1;
            float2 va = *(const float2*)(R0 + la);
            float2 vb = *(const float2*)(R1 + lb);
            float pa1 = (la + 1 == LL) ? 0.f : va.y;
            float pb1 = (lb + 1 == LL) ? 0.f : vb.y;
            sc[nt][0] = (sc[nt][0] + va.x) * 0.125f;
            sc[nt][1] = (sc[nt][1] + pa1) * 0.125f;
            sc[nt][2] = (sc[nt][2] + vb.x) * 0.125f;
            sc[nt][3] = (sc[nt][3] + pb1) * 0.125f;
        }
        {
            uint2 w0 = mrow0[st], w1 = mrow1[st];
            u64 m0 = (u64)w0.x | ((u64)w0.y << 32);
            u64 m1 = (u64)w1.x | ((u64)w1.y << 32);
            if (m0 | m1) {
#pragma unroll
                for (int nt = 0; nt < 8; nt++) {
                    int p = nt * 8 + 2 * t;
                    if ((m0 >> p) & 1)       sc[nt][0] = -1e9f;
                    if ((m0 >> (p + 1)) & 1) sc[nt][1] = -1e9f;
                    if ((m1 >> p) & 1)       sc[nt][2] = -1e9f;
                    if ((m1 >> (p + 1)) & 1) sc[nt][3] = -1e9f;
                }
            }
        }

        // ---- online softmax ----
        float rmx0 = -1e30f, rmx1 = -1e30f;
#pragma unroll
        for (int nt = 0; nt < 8; nt++) {
            rmx0 = fmaxf(rmx0, fmaxf(sc[nt][0], sc[nt][1]));
            rmx1 = fmaxf(rmx1, fmaxf(sc[nt][2], sc[nt][3]));
        }
        rmx0 = fmaxf(rmx0, __shfl_xor_sync(0xffffffffu, rmx0, 1));
        rmx0 = fmaxf(rmx0, __shfl_xor_sync(0xffffffffu, rmx0, 2));
        rmx1 = fmaxf(rmx1, __shfl_xor_sync(0xffffffffu, rmx1, 1));
        rmx1 = fmaxf(rmx1, __shfl_xor_sync(0xffffffffu, rmx1, 2));

        float mn0 = fmaxf(mx0, rmx0), mn1 = fmaxf(mx1, rmx1);
        float al0 = __expf(mx0 - mn0), al1 = __expf(mx1 - mn1);
        float rs0 = 0.f, rs1 = 0.f;
#pragma unroll
        for (int nt = 0; nt < 8; nt++) {
            sc[nt][0] = __expf(sc[nt][0] - mn0);
            sc[nt][1] = __expf(sc[nt][1] - mn0);
            sc[nt][2] = __expf(sc[nt][2] - mn1);
            sc[nt][3] = __expf(sc[nt][3] - mn1);
            rs0 += sc[nt][0] + sc[nt][1];
            rs1 += sc[nt][2] + sc[nt][3];
        }
        rs0 += __shfl_xor_sync(0xffffffffu, rs0, 1);
        rs0 += __shfl_xor_sync(0xffffffffu, rs0, 2);
        rs1 += __shfl_xor_sync(0xffffffffu, rs1, 1);
        rs1 += __shfl_xor_sync(0xffffffffu, rs1, 2);
        l0 = l0 * al0 + rs0;
        l1 = l1 * al1 + rs1;
        mx0 = mn0; mx1 = mn1;
#pragma unroll
        for (int dt = 0; dt < 8; dt++) {
            o[dt][0] *= al0; o[dt][1] *= al0;
            o[dt][2] *= al1; o[dt][3] *= al1;
        }

        // ---- O += P @ V (m16n8k16, P packed from accumulators) ----
#pragma unroll
        for (int j = 0; j < 4; j++) {
            uint32_t aPh[4], aPl[4];
            {
                float x0 = sc[2 * j][0],     x1 = sc[2 * j][1];
                float y0 = sc[2 * j][2],     y1 = sc[2 * j][3];
                float u0 = sc[2 * j + 1][0], u1 = sc[2 * j + 1][1];
                float v0 = sc[2 * j + 1][2], v1 = sc[2 * j + 1][3];
                float hx0 = bf16_hi(x0), hx1 = bf16_hi(x1);
                float hy0 = bf16_hi(y0), hy1 = bf16_hi(y1);
                float hu0 = bf16_hi(u0), hu1 = bf16_hi(u1);
                float hv0 = bf16_hi(v0), hv1 = bf16_hi(v1);
                aPh[0] = pack_bf16(x0, x1); aPh[1] = pack_bf16(y0, y1);
                aPh[2] = pack_bf16(u0, u1); aPh[3] = pack_bf16(v0, v1);
                aPl[0] = pack_bf16(x0 - hx0, x1 - hx1);
                aPl[1] = pack_bf16(y0 - hy0, y1 - hy1);
                aPl[2] = pack_bf16(u0 - hu0, u1 - hu1);
                aPl[3] = pack_bf16(v0 - hv0, v1 - hv1);
            }
#pragma unroll
            for (int dt = 0; dt < 8; dt++) {
                const int vrow = (dt * 8 + g) * PSTR;
                uint32_t b0h = pVH[vrow + 8 * j + t];
                uint32_t b1h = pVH[vrow + 8 * j + 4 + t];
                uint32_t b0l = pVL[vrow + 8 * j + t];
                uint32_t b1l = pVL[vrow + 8 * j + 4 + t];
                mma_bf16(o[dt], aPh, b0h, b1h);
                mma_bf16(o[dt], aPl, b0h, b1h);
                mma_bf16(o[dt], aPh, b0l, b1l);
            }
        }
    }

    float inv0 = 1.f / l0, inv1 = 1.f / l1;
    float* o0 = Og + ((ll)(b * TT + tg0)) * DM + h * DK;
    float* o1 = Og + ((ll)(b * TT + tg1)) * DM + h * DK;
#pragma unroll
    for (int dt = 0; dt < 8; dt++) {
        int d0 = dt * 8 + 2 * t;
        o0[d0] = o[dt][0] * inv0; o0[d0 + 1] = o[dt][1] * inv0;
        o1[d0] = o[dt][2] * inv1; o1[d0 + 1] = o[dt][3] * inv1;
    }
}

// ---------------- launch ----------------
extern "C" void kernel_launch(void* const* d_in, const int* in_sizes, int n_in,
                              void* d_out, int out_size)
{
    const float* x   = (const float*)d_in[0];
    const float* pos = (const float*)d_in[1];
    const unsigned char* mask = (const unsigned char*)d_in[2];
    const float* Wq = (const float*)d_in[3];  const float* bq = (const float*)d_in[4];
    const float* Wk = (const float*)d_in[5];  const float* bk = (const float*)d_in[6];
    const float* Wv = (const float*)d_in[7];  const float* bv = (const float*)d_in[8];
    const float* Wp = (const float*)d_in[9];  const float* bp = (const float*)d_in[10];
    const float* Wo = (const float*)d_in[11]; const float* bo = (const float*)d_in[12];
    const float* pbu = (const float*)d_in[13];
    const float* pbv = (const float*)d_in[14];
    float* out = (float*)d_out;

    float *Q, *K, *V, *P, *R, *O;
    unsigned int *Mb, *Kph, *Kpl, *VTh, *VTl;
    cudaGetSymbolAddress((void**)&Q, g_Q);
    cudaGetSymbolAddress((void**)&K, g_K);
    cudaGetSymbolAddress((void**)&V, g_V);
    cudaGetSymbolAddress((void**)&P, g_P);
    cudaGetSymbolAddress((void**)&R, g_R);
    cudaGetSymbolAddress((void**)&O, g_O);
    cudaGetSymbolAddress((void**)&Mb, g_Mb);
    cudaGetSymbolAddress((void**)&Kph, g_Kph);
    cudaGetSymbolAddress((void**)&Kpl, g_Kpl);
    cudaGetSymbolAddress((void**)&VTh, g_VTh);
    cudaGetSymbolAddress((void**)&VTl, g_VTl);

    cudaFuncSetAttribute(mma_gemm<0, 0>, cudaFuncAttributeMaxDynamicSharedMemorySize, GEMM_SMEM);
    cudaFuncSetAttribute(mma_gemm<1, 1>, cudaFuncAttributeMaxDynamicSharedMemorySize, GEMM_SMEM);
    cudaFuncSetAttribute(flash_attn, cudaFuncAttributeMaxDynamicSharedMemorySize, FL_SMEM);

    dim3 blk(256);

    mask_pack<<<512, 256>>>(mask, Mb);

    // projections
    mma_gemm<0, 0><<<dim3(8, 32, 1), blk, GEMM_SMEM>>>(
        x, DM, 0, 0, Wq, DM, 0, 0, Q, DM, 0, 0, NB * TT, DM, DM, bq, nullptr);
    mma_gemm<0, 0><<<dim3(8, 32, 1), blk, GEMM_SMEM>>>(
        x, DM, 0, 0, Wk, DM, 0, 0, K, DM, 0, 0, NB * TT, DM, DM, bk, nullptr);
    mma_gemm<0, 0><<<dim3(8, 32, 1), blk, GEMM_SMEM>>>(
        x, DM, 0, 0, Wv, DM, 0, 0, V, DM, 0, 0, NB * TT, DM, DM, bv, nullptr);
    mma_gemm<0, 0><<<dim3(8, 16, 1), blk, GEMM_SMEM>>>(
        pos, DM, 0, 0, Wp, DM, 0, 0, P, DM, 0, 0, LL, DM, DM, bp, nullptr);

    // bf16 split-pack of K and V (+ V transpose)
    kv_pack<<<dim3(16, 32), 256>>>(K, V, Kph, Kpl, VTh, VTl);

    // R = (Q[512:] + pos_bias_v) @ P^T per (b,h)  (padded ldc=2048)
    mma_gemm<1, 1><<<dim3(32, 4, 32), blk, GEMM_SMEM>>>(
        Q + 512 * DM, DM, (ll)TT * DM, DK,
        P, DM, 0, DK,
        R, RSTR, 8LL * 512 * RSTR, (ll)512 * RSTR,
        512, LL, DK, nullptr, pbv);

    // fused scores + softmax + AV
    flash_attn<<<dim3(16, 32), dim3(128), FL_SMEM>>>(Q, Kph, Kpl, VTh, VTl, pbu, R, Mb, O);

    // out = O @ Wo + bo
    mma_gemm<0, 0><<<dim3(8, 32, 1), blk, GEMM_SMEM>>>(
        O, DM, 0, 0, Wo, DM, 0, 0, out, DM, 0, 0,
        NB * TT, DM, DM, bo, nullptr);
}

// round 7
// speedup vs baseline: 1.8797x; 1.2102x over previous
#include <cuda_runtime.h>
#include <cuda_bf16.h>
#include <cstdint>

#define TT 1024
#define DM 512
#define NB 4
#define NH 8
#define DK 64
#define LL 2047   // 2*T - 1
#define RSTR 2048 // padded R row stride
typedef long long ll;
typedef unsigned long long u64;

// ---------------- scratch ----------------
__device__ float g_Q[NB * TT * DM];
__device__ float g_K[NB * TT * DM];
__device__ float g_V[NB * TT * DM];
__device__ float g_P[2048 * DM];
__device__ float g_R[32LL * 512 * RSTR];
__device__ unsigned int g_Mb[NB * TT * 32];
__device__ unsigned int g_Kph[32LL * 1024 * 32];
__device__ unsigned int g_Kpl[32LL * 1024 * 32];
__device__ unsigned int g_VTh[32LL * 64 * 512];
__device__ unsigned int g_VTl[32LL * 64 * 512];
// packed bf16 hi/lo pair arrays (pairs along contraction dim)
__device__ unsigned int g_xph[NB * TT * 256],  g_xpl[NB * TT * 256];
__device__ unsigned int g_pph[2047 * 256],     g_ppl[2047 * 256];
__device__ unsigned int g_Wqh[256 * 512], g_Wql[256 * 512];
__device__ unsigned int g_Wkh[256 * 512], g_Wkl[256 * 512];
__device__ unsigned int g_Wvh[256 * 512], g_Wvl[256 * 512];
__device__ unsigned int g_Wph[256 * 512], g_Wpl[256 * 512];
__device__ unsigned int g_Woh[256 * 512], g_Wol[256 * 512];
__device__ unsigned int g_Pph[2047 * 256], g_Ppl[2047 * 256];
__device__ unsigned int g_QRh[32LL * 512 * 32], g_QRl[32LL * 512 * 32];
__device__ unsigned int g_Oph[NB * TT * 256], g_Opl[NB * TT * 256];

// ---------------- helpers ----------------
__device__ __forceinline__ float bf16_hi(float x) {
    return __bfloat162float(__float2bfloat16(x));
}
__device__ __forceinline__ uint32_t pack_bf16(float lo_elem, float hi_elem) {
    uint32_t r;
    asm("cvt.rn.bf16x2.f32 %0, %1, %2;" : "=r"(r) : "f"(hi_elem), "f"(lo_elem));
    return r;
}
__device__ __forceinline__ void split_pack(float a, float b, uint32_t& ph, uint32_t& pl) {
    float ha = bf16_hi(a), hb = bf16_hi(b);
    ph = pack_bf16(a, b);
    pl = pack_bf16(a - ha, b - hb);
}

__device__ __forceinline__ void mma_bf16(float* d, const uint32_t* a, uint32_t b0, uint32_t b1) {
    asm volatile(
        "mma.sync.aligned.m16n8k16.row.col.f32.bf16.bf16.f32 "
        "{%0,%1,%2,%3}, {%4,%5,%6,%7}, {%8,%9}, {%0,%1,%2,%3};\n"
        : "+f"(d[0]), "+f"(d[1]), "+f"(d[2]), "+f"(d[3])
        : "r"(a[0]), "r"(a[1]), "r"(a[2]), "r"(a[3]), "r"(b0), "r"(b1));
}

__device__ __forceinline__ void cp_async16(uint32_t dst, const void* src, bool p) {
    asm volatile("cp.async.cg.shared.global [%0], [%1], 16, %2;\n"
                 :: "r"(dst), "l"(src), "r"(p ? 16 : 0));
}
__device__ __forceinline__ void cp_commit() { asm volatile("cp.async.commit_group;\n"); }
template <int N>
__device__ __forceinline__ void cp_wait() { asm volatile("cp.async.wait_group %0;\n" :: "n"(N)); }

// ---------------- packing kernels ----------------
__global__ void __launch_bounds__(256) mask_pack(const unsigned char* __restrict__ m,
                                                 unsigned int* __restrict__ out)
{
    int i = blockIdx.x * 256 + threadIdx.x;
    const uchar4* p = (const uchar4*)(m + (ll)i * 32);
    unsigned int bits = 0;
#pragma unroll
    for (int j = 0; j < 8; j++) {
        uchar4 v = p[j];
        unsigned int q = (v.x ? 1u : 0u) | (v.y ? 2u : 0u) | (v.z ? 4u : 0u) | (v.w ? 8u : 0u);
        bits |= q << (4 * j);
    }
    out[i] = bits;
}

// contiguous pairs: src [n][2] floats -> ph/pl [n]
__global__ void __launch_bounds__(256) pack_pairs(const float* __restrict__ src,
                                                  unsigned int* __restrict__ ph,
                                                  unsigned int* __restrict__ pl)
{
    ll i = (ll)blockIdx.x * 256 + threadIdx.x;
    float2 v = *(const float2*)(src + 2 * i);
    split_pack(v.x, v.y, ph[i], pl[i]);
}

// weight pack: W [512][512] k-major rows -> Wp [256][512], pair = rows (2r, 2r+1)
__global__ void __launch_bounds__(256) pack_w(const float* __restrict__ W,
                                              unsigned int* __restrict__ ph,
                                              unsigned int* __restrict__ pl)
{
    int i = blockIdx.x * 256 + threadIdx.x;   // [0, 131072)
    int r = i >> 9, n = i & 511;
    float a = W[(2 * r) * 512 + n], b = W[(2 * r + 1) * 512 + n];
    split_pack(a, b, ph[i], pl[i]);
}

// QR pack: (Q[b][512+m][h*64+d] + pbv[h][d]) -> QRp [z][512][32]
__global__ void __launch_bounds__(256) pack_qr(const float* __restrict__ Q,
                                               const float* __restrict__ pbv,
                                               unsigned int* __restrict__ ph,
                                               unsigned int* __restrict__ pl)
{
    int i = blockIdx.x * 256 + threadIdx.x;   // [0, 524288)
    int z = i >> 14, rem = i & 16383;
    int m = rem >> 5, j = rem & 31;
    int b = z >> 3, h = z & 7;
    float2 q = *(const float2*)(Q + ((ll)(b * TT + 512 + m)) * DM + h * DK + 2 * j);
    float2 u = *(const float2*)(pbv + h * DK + 2 * j);
    split_pack(q.x + u.x, q.y + u.y, ph[i], pl[i]);
}

// K/V pack for flash (from fp32 K, V)
__global__ void __launch_bounds__(256) kv_pack(
    const float* __restrict__ Kf, const float* __restrict__ Vf,
    unsigned int* __restrict__ Kph, unsigned int* __restrict__ Kpl,
    unsigned int* __restrict__ VTh, unsigned int* __restrict__ VTl)
{
    __shared__ float sv[64][65];
    const int z = blockIdx.y, b = z >> 3, h = z & 7;
    const int s0 = blockIdx.x * 64;
    const int tid = threadIdx.x;
    const int row = tid >> 2, cq = (tid & 3) << 4;

    {
        const float* kr = Kf + ((ll)(b * TT + s0 + row)) * DM + h * DK + cq;
        float v[16];
#pragma unroll
        for (int i = 0; i < 4; i++) {
            float4 f = *(const float4*)(kr + 4 * i);
            v[4 * i] = f.x; v[4 * i + 1] = f.y; v[4 * i + 2] = f.z; v[4 * i + 3] = f.w;
        }
        ll base = ((ll)z * 1024 + s0 + row) * 32 + (cq >> 1);
#pragma unroll
        for (int j = 0; j < 8; j++)
            split_pack(v[2 * j], v[2 * j + 1], Kph[base + j], Kpl[base + j]);
    }
    {
        const float* vr = Vf + ((ll)(b * TT + s0 + row)) * DM + h * DK + cq;
#pragma unroll
        for (int i = 0; i < 4; i++) {
            float4 f = *(const float4*)(vr + 4 * i);
            sv[row][cq + 4 * i] = f.x; sv[row][cq + 4 * i + 1] = f.y;
            sv[row][cq + 4 * i + 2] = f.z; sv[row][cq + 4 * i + 3] = f.w;
        }
    }
    __syncthreads();
    {
        const int d = tid >> 2, sq = (tid & 3) << 4;
        ll base = ((ll)z * 64 + d) * 512 + ((s0 + sq) >> 1);
#pragma unroll
        for (int j = 0; j < 8; j++)
            split_pack(sv[sq + 2 * j][d], sv[sq + 2 * j + 1][d], VTh[base + j], VTl[base + j]);
    }
}

// ---------------- bf16x2 pipelined GEMM ----------------
// C[M,N] = A @ op(B) + bias. A packed [M][Kp] (pairs along k). 128x64 tile, BK=16 pairs.
// TRANSB=0: B packed [Kp][Nfull] (k-pair rows).  TRANSB=1: B packed [N][Kp] (C = A@B^T).
#define A_STR 20
#define BN_STR 72
#define BT_STR 20
#define G2_SMEM ((4 * 2560 + 4 * 1280) * 4)   // A: 2buf x2 x 128x20; B: max(16x72,64x20)=1280

template <int TRANSB>
__global__ void __launch_bounds__(256) bf16_gemm(
    const unsigned int* __restrict__ Aph, const unsigned int* __restrict__ Apl,
    int ldap, ll sAb, ll sAh,
    const unsigned int* __restrict__ Bph, const unsigned int* __restrict__ Bpl,
    int ldbp, ll sBb, ll sBh,
    float* __restrict__ C, int ldc, ll sCb, ll sCh,
    int M, int N, int Kp, const float* __restrict__ bias)
{
    extern __shared__ uint32_t su[];
    uint32_t* AH = su;              // [2][2560]
    uint32_t* ALo = su + 5120;      // [2][2560]
    uint32_t* BH = su + 10240;      // [2][1280]
    uint32_t* BLo = su + 12800;     // [2][1280]

    const int z = blockIdx.z, b = z >> 3, h = z & 7;
    Aph += (ll)b * sAb + (ll)h * sAh;
    Apl += (ll)b * sAb + (ll)h * sAh;
    Bph += (ll)b * sBb + (ll)h * sBh;
    Bpl += (ll)b * sBb + (ll)h * sBh;

    const int tid = threadIdx.x;
    const int lane = tid & 31, wid = tid >> 5;
    const int g = lane >> 2, t = lane & 3;
    const int wm = wid & 3, wn = wid >> 2;
    const int m0 = blockIdx.y * 128, n0 = blockIdx.x * 64;

    uint32_t sBase = (uint32_t)__cvta_generic_to_shared(su);

    auto stage = [&](int k0p, int stg) {
        // A: 128 rows x 16 pairs, both arrays
#pragma unroll
        for (int i = 0; i < 2; i++) {
            int idx = tid + 256 * i;
            int row = idx >> 2, c4 = (idx & 3) << 2;
            bool p = (m0 + row) < M;
            const ll off = (ll)(m0 + row) * ldap + k0p + c4;
            uint32_t d0 = sBase + (uint32_t)(stg * 2560 + row * A_STR + c4) * 4;
            cp_async16(d0, Aph + off, p);
            cp_async16(d0 + 5120 * 4, Apl + off, p);
        }
        if (!TRANSB) {
            int row = tid >> 4, c4 = (tid & 15) << 2;     // 16 x 64
            const ll off = (ll)(k0p + row) * ldbp + n0 + c4;
            uint32_t d0 = sBase + (uint32_t)(10240 + stg * 1280 + row * BN_STR + c4) * 4;
            cp_async16(d0, Bph + off, true);
            cp_async16(d0 + 2560 * 4, Bpl + off, true);
        } else {
            int row = tid >> 2, c4 = (tid & 3) << 2;      // 64 x 16
            bool p = (n0 + row) < N;
            const ll off = (ll)(n0 + row) * ldbp + k0p + c4;
            uint32_t d0 = sBase + (uint32_t)(10240 + stg * 1280 + row * BT_STR + c4) * 4;
            cp_async16(d0, Bph + off, p);
            cp_async16(d0 + 2560 * 4, Bpl + off, p);
        }
    };

    float d[2][4][4];
#pragma unroll
    for (int i = 0; i < 2; i++)
#pragma unroll
        for (int j = 0; j < 4; j++)
#pragma unroll
            for (int c = 0; c < 4; c++) d[i][j][c] = 0.f;

    const int nIter = Kp >> 4;
    stage(0, 0);
    cp_commit();

    for (int it = 0; it < nIter; it++) {
        __syncthreads();
        if (it + 1 < nIter) { stage((it + 1) << 4, (it + 1) & 1); cp_commit(); cp_wait<1>(); }
        else cp_wait<0>();
        __syncthreads();

        const uint32_t* pAH = AH + (it & 1) * 2560;
        const uint32_t* pAL = ALo + (it & 1) * 2560;
        const uint32_t* pBH = BH + (it & 1) * 1280;
        const uint32_t* pBL = BLo + (it & 1) * 1280;

#pragma unroll
        for (int ck = 0; ck < 2; ck++) {
            const int kb = ck * 8;
            uint32_t aH[2][4], aL[2][4];
#pragma unroll
            for (int mt = 0; mt < 2; mt++) {
                int base = (wm * 32 + mt * 16 + g) * A_STR + kb;
                aH[mt][0] = pAH[base + t];
                aH[mt][1] = pAH[base + 8 * A_STR + t];
                aH[mt][2] = pAH[base + t + 4];
                aH[mt][3] = pAH[base + 8 * A_STR + t + 4];
                aL[mt][0] = pAL[base + t];
                aL[mt][1] = pAL[base + 8 * A_STR + t];
                aL[mt][2] = pAL[base + t + 4];
                aL[mt][3] = pAL[base + 8 * A_STR + t + 4];
            }
#pragma unroll
            for (int nt = 0; nt < 4; nt++) {
                int col = wn * 32 + nt * 8 + g;
                int i0, i1;
                if (!TRANSB) { i0 = (kb + t) * BN_STR + col; i1 = (kb + t + 4) * BN_STR + col; }
                else         { i0 = col * BT_STR + kb + t;   i1 = col * BT_STR + kb + t + 4; }
                uint32_t b0h = pBH[i0], b1h = pBH[i1];
                uint32_t b0l = pBL[i0], b1l = pBL[i1];
#pragma unroll
                for (int mt = 0; mt < 2; mt++) {
                    mma_bf16(d[mt][nt], aH[mt], b0h, b1h);
                    mma_bf16(d[mt][nt], aL[mt], b0h, b1h);
                    mma_bf16(d[mt][nt], aH[mt], b0l, b1l);
                }
            }
        }
    }

    float* Cz = C + (ll)b * sCb + (ll)h * sCh;
#pragma unroll
    for (int mt = 0; mt < 2; mt++) {
        int row = m0 + wm * 32 + mt * 16 + g;
#pragma unroll
        for (int nt = 0; nt < 4; nt++) {
            int col = n0 + wn * 32 + nt * 8 + 2 * t;
            float b0 = (bias && col < N) ? bias[col] : 0.f;
            float b1 = (bias && col + 1 < N) ? bias[col + 1] : 0.f;
            if (row < M) {
                if (col < N)     Cz[(ll)row * ldc + col]     = d[mt][nt][0] + b0;
                if (col + 1 < N) Cz[(ll)row * ldc + col + 1] = d[mt][nt][1] + b1;
            }
            if (row + 8 < M) {
                if (col < N)     Cz[(ll)(row + 8) * ldc + col]     = d[mt][nt][2] + b0;
                if (col + 1 < N) Cz[(ll)(row + 8) * ldc + col + 1] = d[mt][nt][3] + b1;
            }
        }
    }
}

// ---------------- fused flash attention: bf16x2 m16n8k16, packed O out ----------------
#define PSTR 36
#define FL_SMEM (8 * 2304 * 4)

__global__ void __launch_bounds__(128, 3) flash_attn(
    const float* __restrict__ Q,
    const unsigned int* __restrict__ Kph, const unsigned int* __restrict__ Kpl,
    const unsigned int* __restrict__ VTh, const unsigned int* __restrict__ VTl,
    const float* __restrict__ pbu, const float* __restrict__ Rr,
    const unsigned int* __restrict__ mbits,
    unsigned int* __restrict__ Oph, unsigned int* __restrict__ Opl)
{
    extern __shared__ uint32_t smu[];
    uint32_t* KH = smu;
    uint32_t* KL = smu + 2 * 2304;
    uint32_t* VH = smu + 4 * 2304;
    uint32_t* VL = smu + 6 * 2304;

    const int z = blockIdx.y, b = z >> 3, h = z & 7;
    const int t0 = blockIdx.x * 64;
    const int tid = threadIdx.x, lane = tid & 31, w = tid >> 5;
    const int g = lane >> 2, t = lane & 3;

    const float* Qb = Q + ((ll)(b * TT + t0)) * DM + h * DK;
    const ll rb = (ll)z * 512 * RSTR;

    uint32_t qh[4][4], ql[4][4];
    {
        const int r0 = w * 16 + g, r1 = r0 + 8;
#pragma unroll
        for (int ks = 0; ks < 4; ks++) {
#pragma unroll
            for (int half = 0; half < 2; half++) {
                int c = 16 * ks + 8 * half + 2 * t;
                float u0 = pbu[h * DK + c], u1 = pbu[h * DK + c + 1];
                float x0 = Qb[(ll)r0 * DM + c] + u0;
                float x1 = Qb[(ll)r0 * DM + c + 1] + u1;
                float y0 = Qb[(ll)r1 * DM + c] + u0;
                float y1 = Qb[(ll)r1 * DM + c + 1] + u1;
                split_pack(x0, x1, qh[ks][2 * half + 0], ql[ks][2 * half + 0]);
                split_pack(y0, y1, qh[ks][2 * half + 1], ql[ks][2 * half + 1]);
            }
        }
    }

    float o[8][4];
#pragma unroll
    for (int i = 0; i < 8; i++)
#pragma unroll
        for (int j = 0; j < 4; j++) o[i][j] = 0.f;
    float mx0 = -1e30f, mx1 = -1e30f, l0 = 0.f, l1 = 0.f;

    uint32_t sBase = (uint32_t)__cvta_generic_to_shared(smu);

    auto loadKV = [&](int st, int buf) {
        const unsigned int* kh = Kph + ((ll)z * 1024 + st * 64) * 32;
        const unsigned int* kl = Kpl + ((ll)z * 1024 + st * 64) * 32;
        const unsigned int* vh = VTh + (ll)z * 64 * 512 + st * 32;
        const unsigned int* vl = VTl + (ll)z * 64 * 512 + st * 32;
        uint32_t o0 = sBase + (uint32_t)(buf * 2304) * 4;
#pragma unroll
        for (int i = 0; i < 4; i++) {
            int idx = tid + 128 * i;
            int row = idx >> 3, c4 = (idx & 7) << 2;
            uint32_t soff = (uint32_t)(row * PSTR + c4) * 4;
            cp_async16(o0 + soff,                kh + (ll)row * 32 + c4, true);
            cp_async16(o0 + 2 * 2304 * 4 + soff, kl + (ll)row * 32 + c4, true);
            cp_async16(o0 + 4 * 2304 * 4 + soff, vh + (ll)row * 512 + c4, true);
            cp_async16(o0 + 6 * 2304 * 4 + soff, vl + (ll)row * 512 + c4, true);
        }
    };

    loadKV(0, 0);
    cp_commit();

    const int tg0 = t0 + w * 16 + g, tg1 = tg0 + 8;
    const float* R0 = Rr + rb + (ll)(tg0 >> 1) * RSTR;
    const float* R1 = Rr + rb + (ll)(tg1 >> 1) * RSTR;
    const int p0 = (tg0 & 1) << 10, p1 = (tg1 & 1) << 10;
    const uint2* mrow0 = (const uint2*)(mbits + ((ll)b * TT + tg0) * 32);
    const uint2* mrow1 = (const uint2*)(mbits + ((ll)b * TT + tg1) * 32);

    for (int st = 0; st < 16; st++) {
        const int buf = st & 1;
        cp_wait<0>();
        __syncthreads();
        if (st + 1 < 16) { loadKV(st + 1, 1 - buf); cp_commit(); }

        const uint32_t* pKH = KH + buf * 2304;
        const uint32_t* pKL = KL + buf * 2304;
        const uint32_t* pVH = VH + buf * 2304;
        const uint32_t* pVL = VL + buf * 2304;

        float sc[8][4];
#pragma unroll
        for (int i = 0; i < 8; i++)
#pragma unroll
            for (int j = 0; j < 4; j++) sc[i][j] = 0.f;
#pragma unroll
        for (int nt = 0; nt < 8; nt++) {
            const int srow = (nt * 8 + g) * PSTR;
#pragma unroll
            for (int ks = 0; ks < 4; ks++) {
                uint32_t b0h = pKH[srow + 8 * ks + t];
                uint32_t b1h = pKH[srow + 8 * ks + 4 + t];
                uint32_t b0l = pKL[srow + 8 * ks + t];
                uint32_t b1l = pKL[srow + 8 * ks + 4 + t];
                mma_bf16(sc[nt], qh[ks], b0h, b1h);
                mma_bf16(sc[nt], ql[ks], b0h, b1h);
                mma_bf16(sc[nt], qh[ks], b0l, b1l);
            }
        }

        const int s0 = st * 64;
#pragma unroll
        for (int nt = 0; nt < 8; nt++) {
            int s_ = s0 + nt * 8 + 2 * t;
            int la = s_ + p0, lb = s_ + p1;
            float2 va = *(const float2*)(R0 + la);
            float2 vb = *(const float2*)(R1 + lb);
            float pa1 = (la + 1 == LL) ? 0.f : va.y;
            float pb1 = (lb + 1 == LL) ? 0.f : vb.y;
            sc[nt][0] = (sc[nt][0] + va.x) * 0.125f;
            sc[nt][1] = (sc[nt][1] + pa1) * 0.125f;
            sc[nt][2] = (sc[nt][2] + vb.x) * 0.125f;
            sc[nt][3] = (sc[nt][3] + pb1) * 0.125f;
        }
        {
            uint2 w0 = mrow0[st], w1 = mrow1[st];
            u64 m0 = (u64)w0.x | ((u64)w0.y << 32);
            u64 m1 = (u64)w1.x | ((u64)w1.y << 32);
            if (m0 | m1) {
#pragma unroll
                for (int nt = 0; nt < 8; nt++) {
                    int p = nt * 8 + 2 * t;
                    if ((m0 >> p) & 1)       sc[nt][0] = -1e9f;
                    if ((m0 >> (p + 1)) & 1) sc[nt][1] = -1e9f;
                    if ((m1 >> p) & 1)       sc[nt][2] = -1e9f;
                    if ((m1 >> (p + 1)) & 1) sc[nt][3] = -1e9f;
                }
            }
        }

        float rmx0 = -1e30f, rmx1 = -1e30f;
#pragma unroll
        for (int nt = 0; nt < 8; nt++) {
            rmx0 = fmaxf(rmx0, fmaxf(sc[nt][0], sc[nt][1]));
            rmx1 = fmaxf(rmx1, fmaxf(sc[nt][2], sc[nt][3]));
        }
        rmx0 = fmaxf(rmx0, __shfl_xor_sync(0xffffffffu, rmx0, 1));
        rmx0 = fmaxf(rmx0, __shfl_xor_sync(0xffffffffu, rmx0, 2));
        rmx1 = fmaxf(rmx1, __shfl_xor_sync(0xffffffffu, rmx1, 1));
        rmx1 = fmaxf(rmx1, __shfl_xor_sync(0xffffffffu, rmx1, 2));

        float mn0 = fmaxf(mx0, rmx0), mn1 = fmaxf(mx1, rmx1);
        float al0 = __expf(mx0 - mn0), al1 = __expf(mx1 - mn1);
        float rs0 = 0.f, rs1 = 0.f;
#pragma unroll
        for (int nt = 0; nt < 8; nt++) {
            sc[nt][0] = __expf(sc[nt][0] - mn0);
            sc[nt][1] = __expf(sc[nt][1] - mn0);
            sc[nt][2] = __expf(sc[nt][2] - mn1);
            sc[nt][3] = __expf(sc[nt][3] - mn1);
            rs0 += sc[nt][0] + sc[nt][1];
            rs1 += sc[nt][2] + sc[nt][3];
        }
        rs0 += __shfl_xor_sync(0xffffffffu, rs0, 1);
        rs0 += __shfl_xor_sync(0xffffffffu, rs0, 2);
        rs1 += __shfl_xor_sync(0xffffffffu, rs1, 1);
        rs1 += __shfl_xor_sync(0xffffffffu, rs1, 2);
        l0 = l0 * al0 + rs0;
        l1 = l1 * al1 + rs1;
        mx0 = mn0; mx1 = mn1;
#pragma unroll
        for (int dt = 0; dt < 8; dt++) {
            o[dt][0] *= al0; o[dt][1] *= al0;
            o[dt][2] *= al1; o[dt][3] *= al1;
        }

#pragma unroll
        for (int j = 0; j < 4; j++) {
            uint32_t aPh[4], aPl[4];
            split_pack(sc[2 * j][0],     sc[2 * j][1],     aPh[0], aPl[0]);
            split_pack(sc[2 * j][2],     sc[2 * j][3],     aPh[1], aPl[1]);
            split_pack(sc[2 * j + 1][0], sc[2 * j + 1][1], aPh[2], aPl[2]);
            split_pack(sc[2 * j + 1][2], sc[2 * j + 1][3], aPh[3], aPl[3]);
#pragma unroll
            for (int dt = 0; dt < 8; dt++) {
                const int vrow = (dt * 8 + g) * PSTR;
                uint32_t b0h = pVH[vrow + 8 * j + t];
                uint32_t b1h = pVH[vrow + 8 * j + 4 + t];
                uint32_t b0l = pVL[vrow + 8 * j + t];
                uint32_t b1l = pVL[vrow + 8 * j + 4 + t];
                mma_bf16(o[dt], aPh, b0h, b1h);
                mma_bf16(o[dt], aPl, b0h, b1h);
                mma_bf16(o[dt], aPh, b0l, b1l);
            }
        }
    }

    // packed bf16 hi/lo output (pairs along d)
    float inv0 = 1.f / l0, inv1 = 1.f / l1;
    ll base0 = ((ll)(b * TT + tg0)) * 256 + h * 32;
    ll base1 = ((ll)(b * TT + tg1)) * 256 + h * 32;
#pragma unroll
    for (int dt = 0; dt < 8; dt++) {
        int pj = dt * 4 + t;
        split_pack(o[dt][0] * inv0, o[dt][1] * inv0, Oph[base0 + pj], Opl[base0 + pj]);
        split_pack(o[dt][2] * inv1, o[dt][3] * inv1, Oph[base1 + pj], Opl[base1 + pj]);
    }
}

// ---------------- launch ----------------
extern "C" void kernel_launch(void* const* d_in, const int* in_sizes, int n_in,
                              void* d_out, int out_size)
{
    const float* x   = (const float*)d_in[0];
    const float* pos = (const float*)d_in[1];
    const unsigned char* mask = (const unsigned char*)d_in[2];
    const float* Wq = (const float*)d_in[3];  const float* bq = (const float*)d_in[4];
    const float* Wk = (const float*)d_in[5];  const float* bk = (const float*)d_in[6];
    const float* Wv = (const float*)d_in[7];  const float* bv = (const float*)d_in[8];
    const float* Wp = (const float*)d_in[9];  const float* bp = (const float*)d_in[10];
    const float* Wo = (const float*)d_in[11]; const float* bo = (const float*)d_in[12];
    const float* pbu = (const float*)d_in[13];
    const float* pbv = (const float*)d_in[14];
    float* out = (float*)d_out;

    float *Q, *K, *V, *P, *R;
    unsigned int *Mb, *Kph, *Kpl, *VTh, *VTl;
    unsigned int *xph, *xpl, *pph, *ppl, *Pph, *Ppl, *QRh, *QRl, *Oph, *Opl;
    unsigned int *Wqh, *Wql, *Wkh, *Wkl, *Wvh, *Wvl, *Wph_, *Wpl_, *Woh, *Wol;
    cudaGetSymbolAddress((void**)&Q, g_Q);
    cudaGetSymbolAddress((void**)&K, g_K);
    cudaGetSymbolAddress((void**)&V, g_V);
    cudaGetSymbolAddress((void**)&P, g_P);
    cudaGetSymbolAddress((void**)&R, g_R);
    cudaGetSymbolAddress((void**)&Mb, g_Mb);
    cudaGetSymbolAddress((void**)&Kph, g_Kph);
    cudaGetSymbolAddress((void**)&Kpl, g_Kpl);
    cudaGetSymbolAddress((void**)&VTh, g_VTh);
    cudaGetSymbolAddress((void**)&VTl, g_VTl);
    cudaGetSymbolAddress((void**)&xph, g_xph);
    cudaGetSymbolAddress((void**)&xpl, g_xpl);
    cudaGetSymbolAddress((void**)&pph, g_pph);
    cudaGetSymbolAddress((void**)&ppl, g_ppl);
    cudaGetSymbolAddress((void**)&Pph, g_Pph);
    cudaGetSymbolAddress((void**)&Ppl, g_Ppl);
    cudaGetSymbolAddress((void**)&QRh, g_QRh);
    cudaGetSymbolAddress((void**)&QRl, g_QRl);
    cudaGetSymbolAddress((void**)&Oph, g_Oph);
    cudaGetSymbolAddress((void**)&Opl, g_Opl);
    cudaGetSymbolAddress((void**)&Wqh, g_Wqh); cudaGetSymbolAddress((void**)&Wql, g_Wql);
    cudaGetSymbolAddress((void**)&Wkh, g_Wkh); cudaGetSymbolAddress((void**)&Wkl, g_Wkl);
    cudaGetSymbolAddress((void**)&Wvh, g_Wvh); cudaGetSymbolAddress((void**)&Wvl, g_Wvl);
    cudaGetSymbolAddress((void**)&Wph_, g_Wph); cudaGetSymbolAddress((void**)&Wpl_, g_Wpl);
    cudaGetSymbolAddress((void**)&Woh, g_Woh); cudaGetSymbolAddress((void**)&Wol, g_Wol);

    cudaFuncSetAttribute(bf16_gemm<0>, cudaFuncAttributeMaxDynamicSharedMemorySize, G2_SMEM);
    cudaFuncSetAttribute(bf16_gemm<1>, cudaFuncAttributeMaxDynamicSharedMemorySize, G2_SMEM);
    cudaFuncSetAttribute(flash_attn, cudaFuncAttributeMaxDynamicSharedMemorySize, FL_SMEM);

    dim3 blk(256);

    // ---- packs ----
    mask_pack<<<512, 256>>>(mask, Mb);
    pack_pairs<<<4096, 256>>>(x, xph, xpl);          // 4096x256 pairs
    pack_pairs<<<2047, 256>>>(pos, pph, ppl);        // 2047x256 pairs
    pack_w<<<512, 256>>>(Wq, Wqh, Wql);
    pack_w<<<512, 256>>>(Wk, Wkh, Wkl);
    pack_w<<<512, 256>>>(Wv, Wvh, Wvl);
    pack_w<<<512, 256>>>(Wp, Wph_, Wpl_);
    pack_w<<<512, 256>>>(Wo, Woh, Wol);

    // ---- projections (bf16x2) ----
    bf16_gemm<0><<<dim3(8, 32, 1), blk, G2_SMEM>>>(
        xph, xpl, 256, 0, 0, Wqh, Wql, 512, 0, 0,
        Q, DM, 0, 0, NB * TT, DM, 256, bq);
    bf16_gemm<0><<<dim3(8, 32, 1), blk, G2_SMEM>>>(
        xph, xpl, 256, 0, 0, Wkh, Wkl, 512, 0, 0,
        K, DM, 0, 0, NB * TT, DM, 256, bk);
    bf16_gemm<0><<<dim3(8, 32, 1), blk, G2_SMEM>>>(
        xph, xpl, 256, 0, 0, Wvh, Wvl, 512, 0, 0,
        V, DM, 0, 0, NB * TT, DM, 256, bv);
    bf16_gemm<0><<<dim3(8, 16, 1), blk, G2_SMEM>>>(
        pph, ppl, 256, 0, 0, Wph_, Wpl_, 512, 0, 0,
        P, DM, 0, 0, LL, DM, 256, bp);

    // ---- dependent packs ----
    kv_pack<<<dim3(16, 32), 256>>>(K, V, Kph, Kpl, VTh, VTl);
    pack_pairs<<<2047, 256>>>(P, Pph, Ppl);          // P -> pairs along d
    pack_qr<<<2048, 256>>>(Q, pbv, QRh, QRl);        // (Q[512:]+pbv) packed per z

    // ---- R = (Q[512:]+pbv) @ P^T per (b,h): M=512, N=2047, Kp=32 ----
    bf16_gemm<1><<<dim3(32, 4, 32), blk, G2_SMEM>>>(
        QRh, QRl, 32, 8LL * 512 * 32, 512 * 32,
        Pph, Ppl, 256, 0, 32,
        R, RSTR, 8LL * 512 * RSTR, (ll)512 * RSTR,
        512, LL, 32, nullptr);

    // ---- flash (packed O out) ----
    flash_attn<<<dim3(16, 32), dim3(128), FL_SMEM>>>(
        Q, Kph, Kpl, VTh, VTl, pbu, R, Mb, Oph, Opl);

    // ---- out = O @ Wo + bo ----
    bf16_gemm<0><<<dim3(8, 32, 1), blk, G2_SMEM>>>(
        Oph, Opl, 256, 0, 0, Woh, Wol, 512, 0, 0,
        out, DM, 0, 0, NB * TT, DM, 256, bo);
}

// round 9
// speedup vs baseline: 1.9490x; 1.0369x over previous
#include <cuda_runtime.h>
#include <cuda_bf16.h>
#include <cstdint>

#define TT 1024
#define DM 512
#define NB 4
#define NH 8
#define DK 64
#define LL 2047   // 2*T - 1
#define RSTR 2048
typedef long long ll;
typedef unsigned long long u64;

// ---------------- scratch ----------------
__device__ float g_QKV[3LL * NB * TT * DM];     // Q | K | V contiguous
__device__ float g_P[2048 * DM];
__device__ float g_R[32LL * 512 * RSTR];
__device__ unsigned int g_Mb[NB * TT * 32];
__device__ unsigned int g_Kph[32LL * 1024 * 32];
__device__ unsigned int g_Kpl[32LL * 1024 * 32];
__device__ unsigned int g_VTh[32LL * 64 * 512];
__device__ unsigned int g_VTl[32LL * 64 * 512];
__device__ unsigned int g_xph[NB * TT * 256],  g_xpl[NB * TT * 256];
__device__ unsigned int g_pph[2047 * 256],     g_ppl[2047 * 256];
__device__ unsigned int g_Wqkvh[3 * 256 * 512], g_Wqkvl[3 * 256 * 512];
__device__ unsigned int g_Wph[256 * 512], g_Wpl[256 * 512];
__device__ unsigned int g_Woh[256 * 512], g_Wol[256 * 512];
__device__ unsigned int g_Pph[2047 * 256], g_Ppl[2047 * 256];
__device__ unsigned int g_QRh[32LL * 512 * 32], g_QRl[32LL * 512 * 32];
__device__ unsigned int g_Oph[NB * TT * 256], g_Opl[NB * TT * 256];

// ---------------- helpers ----------------
__device__ __forceinline__ float bf16_hi(float x) {
    return __bfloat162float(__float2bfloat16(x));
}
__device__ __forceinline__ uint32_t pack_bf16(float lo_elem, float hi_elem) {
    uint32_t r;
    asm("cvt.rn.bf16x2.f32 %0, %1, %2;" : "=r"(r) : "f"(hi_elem), "f"(lo_elem));
    return r;
}
__device__ __forceinline__ void split_pack(float a, float b, uint32_t& ph, uint32_t& pl) {
    float ha = bf16_hi(a), hb = bf16_hi(b);
    ph = pack_bf16(a, b);
    pl = pack_bf16(a - ha, b - hb);
}
__device__ __forceinline__ void mma_bf16(float* d, const uint32_t* a, uint32_t b0, uint32_t b1) {
    asm volatile(
        "mma.sync.aligned.m16n8k16.row.col.f32.bf16.bf16.f32 "
        "{%0,%1,%2,%3}, {%4,%5,%6,%7}, {%8,%9}, {%0,%1,%2,%3};\n"
        : "+f"(d[0]), "+f"(d[1]), "+f"(d[2]), "+f"(d[3])
        : "r"(a[0]), "r"(a[1]), "r"(a[2]), "r"(a[3]), "r"(b0), "r"(b1));
}
__device__ __forceinline__ void cp_async16(uint32_t dst, const void* src, bool p) {
    asm volatile("cp.async.cg.shared.global [%0], [%1], 16, %2;\n"
                 :: "r"(dst), "l"(src), "r"(p ? 16 : 0));
}
__device__ __forceinline__ void cp_commit() { asm volatile("cp.async.commit_group;\n"); }
template <int N>
__device__ __forceinline__ void cp_wait() { asm volatile("cp.async.wait_group %0;\n" :: "n"(N)); }

// ---------------- mega-pack 1: all input-only packs, grid (4096,1,8) ----------------
__global__ void __launch_bounds__(256) megapack1(
    const float* __restrict__ x, const float* __restrict__ pos,
    const unsigned char* __restrict__ mask,
    const float* __restrict__ Wq, const float* __restrict__ Wk,
    const float* __restrict__ Wv, const float* __restrict__ Wp,
    const float* __restrict__ Wo,
    unsigned int* __restrict__ Wqkvh, unsigned int* __restrict__ Wqkvl,
    unsigned int* __restrict__ Wph, unsigned int* __restrict__ Wpl,
    unsigned int* __restrict__ Woh, unsigned int* __restrict__ Wol,
    unsigned int* __restrict__ xph, unsigned int* __restrict__ xpl,
    unsigned int* __restrict__ pph, unsigned int* __restrict__ ppl,
    unsigned int* __restrict__ Mb)
{
    const int zz = blockIdx.z, bx = blockIdx.x, tid = threadIdx.x;
    if (zz < 5) {
        if (bx >= 512) return;
        int i = bx * 256 + tid;
        int r = i >> 9, n = i & 511;
        const float* W = zz == 0 ? Wq : zz == 1 ? Wk : zz == 2 ? Wv : zz == 3 ? Wp : Wo;
        unsigned int *ph, *pl;
        if (zz < 3)      { ph = Wqkvh + zz * 131072; pl = Wqkvl + zz * 131072; }
        else if (zz == 3){ ph = Wph; pl = Wpl; }
        else             { ph = Woh; pl = Wol; }
        split_pack(W[(2 * r) * 512 + n], W[(2 * r + 1) * 512 + n], ph[i], pl[i]);
    } else if (zz == 5) {
        ll i = (ll)bx * 256 + tid;
        float2 v = *(const float2*)(x + 2 * i);
        split_pack(v.x, v.y, xph[i], xpl[i]);
    } else if (zz == 6) {
        if (bx >= 2047) return;
        ll i = (ll)bx * 256 + tid;
        float2 v = *(const float2*)(pos + 2 * i);
        split_pack(v.x, v.y, pph[i], ppl[i]);
    } else {
        if (bx >= 512) return;
        int i = bx * 256 + tid;
        const uchar4* p = (const uchar4*)(mask + (ll)i * 32);
        unsigned int bits = 0;
#pragma unroll
        for (int j = 0; j < 8; j++) {
            uchar4 v = p[j];
            unsigned int q = (v.x ? 1u : 0u) | (v.y ? 2u : 0u) | (v.z ? 4u : 0u) | (v.w ? 8u : 0u);
            bits |= q << (4 * j);
        }
        Mb[i] = bits;
    }
}

// ---------------- mega-pack 2: dependent packs, grid (2048,1,3) ----------------
__global__ void __launch_bounds__(256) megapack2(
    const float* __restrict__ QKV, const float* __restrict__ P,
    const float* __restrict__ pbv,
    unsigned int* __restrict__ Kph, unsigned int* __restrict__ Kpl,
    unsigned int* __restrict__ VTh, unsigned int* __restrict__ VTl,
    unsigned int* __restrict__ Pph, unsigned int* __restrict__ Ppl,
    unsigned int* __restrict__ QRh, unsigned int* __restrict__ QRl)
{
    __shared__ float sv[64][65];
    const int zz = blockIdx.z, bx = blockIdx.x, tid = threadIdx.x;
    if (zz == 0) {
        if (bx >= 512) return;
        const int z = bx >> 4, b = z >> 3, h = z & 7;
        const int s0 = (bx & 15) * 64;
        const int row = tid >> 2, cq = (tid & 3) << 4;
        const float* Kf = QKV + 2097152;
        const float* Vf = QKV + 4194304;
        {
            const float* kr = Kf + ((ll)(b * TT + s0 + row)) * DM + h * DK + cq;
            float v[16];
#pragma unroll
            for (int i = 0; i < 4; i++) {
                float4 f = *(const float4*)(kr + 4 * i);
                v[4 * i] = f.x; v[4 * i + 1] = f.y; v[4 * i + 2] = f.z; v[4 * i + 3] = f.w;
            }
            ll base = ((ll)z * 1024 + s0 + row) * 32 + (cq >> 1);
#pragma unroll
            for (int j = 0; j < 8; j++)
                split_pack(v[2 * j], v[2 * j + 1], Kph[base + j], Kpl[base + j]);
        }
        {
            const float* vr = Vf + ((ll)(b * TT + s0 + row)) * DM + h * DK + cq;
#pragma unroll
            for (int i = 0; i < 4; i++) {
                float4 f = *(const float4*)(vr + 4 * i);
                sv[row][cq + 4 * i] = f.x; sv[row][cq + 4 * i + 1] = f.y;
                sv[row][cq + 4 * i + 2] = f.z; sv[row][cq + 4 * i + 3] = f.w;
            }
        }
        __syncthreads();
        {
            const int d = tid >> 2, sq = (tid & 3) << 4;
            ll base = ((ll)z * 64 + d) * 512 + ((s0 + sq) >> 1);
#pragma unroll
            for (int j = 0; j < 8; j++)
                split_pack(sv[sq + 2 * j][d], sv[sq + 2 * j + 1][d], VTh[base + j], VTl[base + j]);
        }
    } else if (zz == 1) {
        if (bx >= 2047) return;
        ll i = (ll)bx * 256 + tid;
        float2 v = *(const float2*)(P + 2 * i);
        split_pack(v.x, v.y, Pph[i], Ppl[i]);
    } else {
        int i = bx * 256 + tid;
        int z = i >> 14, rem = i & 16383;
        int m = rem >> 5, j = rem & 31;
        int b = z >> 3, h = z & 7;
        float2 q = *(const float2*)(QKV + ((ll)(b * TT + 512 + m)) * DM + h * DK + 2 * j);
        float2 u = *(const float2*)(pbv + h * DK + 2 * j);
        split_pack(q.x + u.x, q.y + u.y, QRh[i], QRl[i]);
    }
}

// ---------------- bf16x2 pipelined GEMM ----------------
#define A_STR 20
#define BN_STR 72
#define BT_STR 20
#define G2_SMEM ((4 * 2560 + 4 * 1280) * 4)

template <int TRANSB>
__global__ void __launch_bounds__(256) bf16_gemm(
    const unsigned int* __restrict__ Aph, const unsigned int* __restrict__ Apl,
    int ldap, ll sAb, ll sAh,
    const unsigned int* __restrict__ Bph, const unsigned int* __restrict__ Bpl,
    int ldbp, ll sBb, ll sBh,
    float* __restrict__ C, int ldc, ll sCb, ll sCh,
    int M, int N, int Kp,
    const float* __restrict__ bias0, const float* __restrict__ bias1,
    const float* __restrict__ bias2)
{
    extern __shared__ uint32_t su[];
    uint32_t* AH = su;
    uint32_t* ALo = su + 5120;
    uint32_t* BH = su + 10240;
    uint32_t* BLo = su + 12800;

    const int z = blockIdx.z, b = z >> 3, h = z & 7;
    const float* bias = (h == 0) ? bias0 : (h == 1) ? bias1 : bias2;
    Aph += (ll)b * sAb + (ll)h * sAh;
    Apl += (ll)b * sAb + (ll)h * sAh;
    Bph += (ll)b * sBb + (ll)h * sBh;
    Bpl += (ll)b * sBb + (ll)h * sBh;

    const int tid = threadIdx.x;
    const int lane = tid & 31, wid = tid >> 5;
    const int g = lane >> 2, t = lane & 3;
    const int wm = wid & 3, wn = wid >> 2;
    const int m0 = blockIdx.y * 128, n0 = blockIdx.x * 64;

    uint32_t sBase = (uint32_t)__cvta_generic_to_shared(su);

    auto stage = [&](int k0p, int stg) {
#pragma unroll
        for (int i = 0; i < 2; i++) {
            int idx = tid + 256 * i;
            int row = idx >> 2, c4 = (idx & 3) << 2;
            bool p = (m0 + row) < M;
            const ll off = (ll)(m0 + row) * ldap + k0p + c4;
            uint32_t d0 = sBase + (uint32_t)(stg * 2560 + row * A_STR + c4) * 4;
            cp_async16(d0, Aph + off, p);
            cp_async16(d0 + 5120 * 4, Apl + off, p);
        }
        if (!TRANSB) {
            int row = tid >> 4, c4 = (tid & 15) << 2;
            const ll off = (ll)(k0p + row) * ldbp + n0 + c4;
            uint32_t d0 = sBase + (uint32_t)(10240 + stg * 1280 + row * BN_STR + c4) * 4;
            cp_async16(d0, Bph + off, true);
            cp_async16(d0 + 2560 * 4, Bpl + off, true);
        } else {
            int row = tid >> 2, c4 = (tid & 3) << 2;
            bool p = (n0 + row) < N;
            const ll off = (ll)(n0 + row) * ldbp + k0p + c4;
            uint32_t d0 = sBase + (uint32_t)(10240 + stg * 1280 + row * BT_STR + c4) * 4;
            cp_async16(d0, Bph + off, p);
            cp_async16(d0 + 2560 * 4, Bpl + off, p);
        }
    };

    float d[2][4][4];
#pragma unroll
    for (int i = 0; i < 2; i++)
#pragma unroll
        for (int j = 0; j < 4; j++)
#pragma unroll
            for (int c = 0; c < 4; c++) d[i][j][c] = 0.f;

    const int nIter = Kp >> 4;
    stage(0, 0);
    cp_commit();

    for (int it = 0; it < nIter; it++) {
        __syncthreads();
        if (it + 1 < nIter) { stage((it + 1) << 4, (it + 1) & 1); cp_commit(); cp_wait<1>(); }
        else cp_wait<0>();
        __syncthreads();

        const uint32_t* pAH = AH + (it & 1) * 2560;
        const uint32_t* pAL = ALo + (it & 1) * 2560;
        const uint32_t* pBH = BH + (it & 1) * 1280;
        const uint32_t* pBL = BLo + (it & 1) * 1280;

#pragma unroll
        for (int ck = 0; ck < 2; ck++) {
            const int kb = ck * 8;
            uint32_t aH[2][4], aL[2][4];
#pragma unroll
            for (int mt = 0; mt < 2; mt++) {
                int base = (wm * 32 + mt * 16 + g) * A_STR + kb;
                aH[mt][0] = pAH[base + t];
                aH[mt][1] = pAH[base + 8 * A_STR + t];
                aH[mt][2] = pAH[base + t + 4];
                aH[mt][3] = pAH[base + 8 * A_STR + t + 4];
                aL[mt][0] = pAL[base + t];
                aL[mt][1] = pAL[base + 8 * A_STR + t];
                aL[mt][2] = pAL[base + t + 4];
                aL[mt][3] = pAL[base + 8 * A_STR + t + 4];
            }
#pragma unroll
            for (int nt = 0; nt < 4; nt++) {
                int col = wn * 32 + nt * 8 + g;
                int i0, i1;
                if (!TRANSB) { i0 = (kb + t) * BN_STR + col; i1 = (kb + t + 4) * BN_STR + col; }
                else         { i0 = col * BT_STR + kb + t;   i1 = col * BT_STR + kb + t + 4; }
                uint32_t b0h = pBH[i0], b1h = pBH[i1];
                uint32_t b0l = pBL[i0], b1l = pBL[i1];
#pragma unroll
                for (int mt = 0; mt < 2; mt++) {
                    mma_bf16(d[mt][nt], aH[mt], b0h, b1h);
                    mma_bf16(d[mt][nt], aL[mt], b0h, b1h);
                    mma_bf16(d[mt][nt], aH[mt], b0l, b1l);
                }
            }
        }
    }

    float* Cz = C + (ll)b * sCb + (ll)h * sCh;
#pragma unroll
    for (int mt = 0; mt < 2; mt++) {
        int row = m0 + wm * 32 + mt * 16 + g;
#pragma unroll
        for (int nt = 0; nt < 4; nt++) {
            int col = n0 + wn * 32 + nt * 8 + 2 * t;
            float b0 = (bias && col < N) ? bias[col] : 0.f;
            float b1 = (bias && col + 1 < N) ? bias[col + 1] : 0.f;
            if (row < M) {
                if (col < N)     Cz[(ll)row * ldc + col]     = d[mt][nt][0] + b0;
                if (col + 1 < N) Cz[(ll)row * ldc + col + 1] = d[mt][nt][1] + b1;
            }
            if (row + 8 < M) {
                if (col < N)     Cz[(ll)(row + 8) * ldc + col]     = d[mt][nt][2] + b0;
                if (col + 1 < N) Cz[(ll)(row + 8) * ldc + col + 1] = d[mt][nt][3] + b1;
            }
        }
    }
}

// ---------------- fused flash attention: bf16x2, 3-term QK and PV ----------------
#define PSTR 36
#define FL_SMEM (8 * 2304 * 4)   // KH[2], KL[2], VH[2], VL[2] x [64][36]

__global__ void __launch_bounds__(128, 3) flash_attn(
    const float* __restrict__ Q,
    const unsigned int* __restrict__ Kph, const unsigned int* __restrict__ Kpl,
    const unsigned int* __restrict__ VTh, const unsigned int* __restrict__ VTl,
    const float* __restrict__ pbu, const float* __restrict__ Rr,
    const unsigned int* __restrict__ mbits,
    unsigned int* __restrict__ Oph, unsigned int* __restrict__ Opl)
{
    extern __shared__ uint32_t smu[];
    uint32_t* KH = smu;               // [2][2304]
    uint32_t* KL = smu + 2 * 2304;
    uint32_t* VH = smu + 4 * 2304;
    uint32_t* VL = smu + 6 * 2304;

    const int z = blockIdx.y, b = z >> 3, h = z & 7;
    const int t0 = blockIdx.x * 64;
    const int tid = threadIdx.x, lane = tid & 31, w = tid >> 5;
    const int g = lane >> 2, t = lane & 3;

    const float* Qb = Q + ((ll)(b * TT + t0)) * DM + h * DK;
    const ll rb = (ll)z * 512 * RSTR;

    uint32_t qh[4][4], ql[4][4];
    {
        const int r0 = w * 16 + g, r1 = r0 + 8;
#pragma unroll
        for (int ks = 0; ks < 4; ks++) {
#pragma unroll
            for (int half = 0; half < 2; half++) {
                int c = 16 * ks + 8 * half + 2 * t;
                float u0 = pbu[h * DK + c], u1 = pbu[h * DK + c + 1];
                float x0 = Qb[(ll)r0 * DM + c] + u0;
                float x1 = Qb[(ll)r0 * DM + c + 1] + u1;
                float y0 = Qb[(ll)r1 * DM + c] + u0;
                float y1 = Qb[(ll)r1 * DM + c + 1] + u1;
                split_pack(x0, x1, qh[ks][2 * half + 0], ql[ks][2 * half + 0]);
                split_pack(y0, y1, qh[ks][2 * half + 1], ql[ks][2 * half + 1]);
            }
        }
    }

    float o[8][4];
#pragma unroll
    for (int i = 0; i < 8; i++)
#pragma unroll
        for (int j = 0; j < 4; j++) o[i][j] = 0.f;
    float mx0 = -1e30f, mx1 = -1e30f, l0 = 0.f, l1 = 0.f;

    uint32_t sBase = (uint32_t)__cvta_generic_to_shared(smu);

    auto loadKV = [&](int st, int buf) {
        const unsigned int* kh = Kph + ((ll)z * 1024 + st * 64) * 32;
        const unsigned int* kl = Kpl + ((ll)z * 1024 + st * 64) * 32;
        const unsigned int* vh = VTh + (ll)z * 64 * 512 + st * 32;
        const unsigned int* vl = VTl + (ll)z * 64 * 512 + st * 32;
        uint32_t o0 = sBase + (uint32_t)(buf * 2304) * 4;
#pragma unroll
        for (int i = 0; i < 4; i++) {
            int idx = tid + 128 * i;
            int row = idx >> 3, c4 = (idx & 7) << 2;
            uint32_t soff = (uint32_t)(row * PSTR + c4) * 4;
            cp_async16(o0 + soff,                kh + (ll)row * 32 + c4, true);
            cp_async16(o0 + 2 * 2304 * 4 + soff, kl + (ll)row * 32 + c4, true);
            cp_async16(o0 + 4 * 2304 * 4 + soff, vh + (ll)row * 512 + c4, true);
            cp_async16(o0 + 6 * 2304 * 4 + soff, vl + (ll)row * 512 + c4, true);
        }
    };

    loadKV(0, 0);
    cp_commit();

    const int tg0 = t0 + w * 16 + g, tg1 = tg0 + 8;
    const float* R0 = Rr + rb + (ll)(tg0 >> 1) * RSTR;
    const float* R1 = Rr + rb + (ll)(tg1 >> 1) * RSTR;
    const int p0 = (tg0 & 1) << 10, p1 = (tg1 & 1) << 10;
    const uint2* mrow0 = (const uint2*)(mbits + ((ll)b * TT + tg0) * 32);
    const uint2* mrow1 = (const uint2*)(mbits + ((ll)b * TT + tg1) * 32);

    for (int st = 0; st < 16; st++) {
        const int buf = st & 1;
        cp_wait<0>();
        __syncthreads();
        if (st + 1 < 16) { loadKV(st + 1, 1 - buf); cp_commit(); }

        const uint32_t* pKH = KH + buf * 2304;
        const uint32_t* pKL = KL + buf * 2304;
        const uint32_t* pVH = VH + buf * 2304;
        const uint32_t* pVL = VL + buf * 2304;

        float sc[8][4];
#pragma unroll
        for (int i = 0; i < 8; i++)
#pragma unroll
            for (int j = 0; j < 4; j++) sc[i][j] = 0.f;
#pragma unroll
        for (int nt = 0; nt < 8; nt++) {
            const int srow = (nt * 8 + g) * PSTR;
#pragma unroll
            for (int ks = 0; ks < 4; ks++) {
                uint32_t b0h = pKH[srow + 8 * ks + t];
                uint32_t b1h = pKH[srow + 8 * ks + 4 + t];
                uint32_t b0l = pKL[srow + 8 * ks + t];
                uint32_t b1l = pKL[srow + 8 * ks + 4 + t];
                mma_bf16(sc[nt], qh[ks], b0h, b1h);
                mma_bf16(sc[nt], ql[ks], b0h, b1h);
                mma_bf16(sc[nt], qh[ks], b0l, b1l);
            }
        }

        const int s0 = st * 64;
#pragma unroll
        for (int nt = 0; nt < 8; nt++) {
            int s_ = s0 + nt * 8 + 2 * t;
            int la = s_ + p0, lb = s_ + p1;
            float2 va = *(const float2*)(R0 + la);
            float2 vb = *(const float2*)(R1 + lb);
            float pa1 = (la + 1 == LL) ? 0.f : va.y;
            float pb1 = (lb + 1 == LL) ? 0.f : vb.y;
            sc[nt][0] = (sc[nt][0] + va.x) * 0.125f;
            sc[nt][1] = (sc[nt][1] + pa1) * 0.125f;
            sc[nt][2] = (sc[nt][2] + vb.x) * 0.125f;
            sc[nt][3] = (sc[nt][3] + pb1) * 0.125f;
        }
        {
            uint2 w0 = mrow0[st], w1 = mrow1[st];
            u64 m0 = (u64)w0.x | ((u64)w0.y << 32);
            u64 m1 = (u64)w1.x | ((u64)w1.y << 32);
            if (m0 | m1) {
#pragma unroll
                for (int nt = 0; nt < 8; nt++) {
                    int p = nt * 8 + 2 * t;
                    if ((m0 >> p) & 1)       sc[nt][0] = -1e9f;
                    if ((m0 >> (p + 1)) & 1) sc[nt][1] = -1e9f;
                    if ((m1 >> p) & 1)       sc[nt][2] = -1e9f;
                    if ((m1 >> (p + 1)) & 1) sc[nt][3] = -1e9f;
                }
            }
        }

        float rmx0 = -1e30f, rmx1 = -1e30f;
#pragma unroll
        for (int nt = 0; nt < 8; nt++) {
            rmx0 = fmaxf(rmx0, fmaxf(sc[nt][0], sc[nt][1]));
            rmx1 = fmaxf(rmx1, fmaxf(sc[nt][2], sc[nt][3]));
        }
        rmx0 = fmaxf(rmx0, __shfl_xor_sync(0xffffffffu, rmx0, 1));
        rmx0 = fmaxf(rmx0, __shfl_xor_sync(0xffffffffu, rmx0, 2));
        rmx1 = fmaxf(rmx1, __shfl_xor_sync(0xffffffffu, rmx1, 1));
        rmx1 = fmaxf(rmx1, __shfl_xor_sync(0xffffffffu, rmx1, 2));

        float mn0 = fmaxf(mx0, rmx0), mn1 = fmaxf(mx1, rmx1);
        float al0 = __expf(mx0 - mn0), al1 = __expf(mx1 - mn1);
        float rs0 = 0.f, rs1 = 0.f;
#pragma unroll
        for (int nt = 0; nt < 8; nt++) {
            sc[nt][0] = __expf(sc[nt][0] - mn0);
            sc[nt][1] = __expf(sc[nt][1] - mn0);
            sc[nt][2] = __expf(sc[nt][2] - mn1);
            sc[nt][3] = __expf(sc[nt][3] - mn1);
            rs0 += sc[nt][0] + sc[nt][1];
            rs1 += sc[nt][2] + sc[nt][3];
        }
        rs0 += __shfl_xor_sync(0xffffffffu, rs0, 1);
        rs0 += __shfl_xor_sync(0xffffffffu, rs0, 2);
        rs1 += __shfl_xor_sync(0xffffffffu, rs1, 1);
        rs1 += __shfl_xor_sync(0xffffffffu, rs1, 2);
        l0 = l0 * al0 + rs0;
        l1 = l1 * al1 + rs1;
        mx0 = mn0; mx1 = mn1;
#pragma unroll
        for (int dt = 0; dt < 8; dt++) {
            o[dt][0] *= al0; o[dt][1] *= al0;
            o[dt][2] *= al1; o[dt][3] *= al1;
        }

#pragma unroll
        for (int j = 0; j < 4; j++) {
            uint32_t aPh[4], aPl[4];
            split_pack(sc[2 * j][0],     sc[2 * j][1],     aPh[0], aPl[0]);
            split_pack(sc[2 * j][2],     sc[2 * j][3],     aPh[1], aPl[1]);
            split_pack(sc[2 * j + 1][0], sc[2 * j + 1][1], aPh[2], aPl[2]);
            split_pack(sc[2 * j + 1][2], sc[2 * j + 1][3], aPh[3], aPl[3]);
#pragma unroll
            for (int dt = 0; dt < 8; dt++) {
                const int vrow = (dt * 8 + g) * PSTR;
                uint32_t b0h = pVH[vrow + 8 * j + t];
                uint32_t b1h = pVH[vrow + 8 * j + 4 + t];
                uint32_t b0l = pVL[vrow + 8 * j + t];
                uint32_t b1l = pVL[vrow + 8 * j + 4 + t];
                mma_bf16(o[dt], aPh, b0h, b1h);
                mma_bf16(o[dt], aPl, b0h, b1h);
                mma_bf16(o[dt], aPh, b0l, b1l);
            }
        }
    }

    float inv0 = 1.f / l0, inv1 = 1.f / l1;
    ll base0 = ((ll)(b * TT + tg0)) * 256 + h * 32;
    ll base1 = ((ll)(b * TT + tg1)) * 256 + h * 32;
#pragma unroll
    for (int dt = 0; dt < 8; dt++) {
        int pj = dt * 4 + t;
        split_pack(o[dt][0] * inv0, o[dt][1] * inv0, Oph[base0 + pj], Opl[base0 + pj]);
        split_pack(o[dt][2] * inv1, o[dt][3] * inv1, Oph[base1 + pj], Opl[base1 + pj]);
    }
}

// ---------------- launch ----------------
extern "C" void kernel_launch(void* const* d_in, const int* in_sizes, int n_in,
                              void* d_out, int out_size)
{
    const float* x   = (const float*)d_in[0];
    const float* pos = (const float*)d_in[1];
    const unsigned char* mask = (const unsigned char*)d_in[2];
    const float* Wq = (const float*)d_in[3];  const float* bq = (const float*)d_in[4];
    const float* Wk = (const float*)d_in[5];  const float* bk = (const float*)d_in[6];
    const float* Wv = (const float*)d_in[7];  const float* bv = (const float*)d_in[8];
    const float* Wp = (const float*)d_in[9];  const float* bp = (const float*)d_in[10];
    const float* Wo = (const float*)d_in[11]; const float* bo = (const float*)d_in[12];
    const float* pbu = (const float*)d_in[13];
    const float* pbv = (const float*)d_in[14];
    float* out = (float*)d_out;

    float *QKV, *P, *R;
    unsigned int *Mb, *Kph, *Kpl, *VTh, *VTl;
    unsigned int *xph, *xpl, *pph, *ppl, *Pph, *Ppl, *QRh, *QRl, *Oph, *Opl;
    unsigned int *Wqkvh, *Wqkvl, *Wph_, *Wpl_, *Woh, *Wol;
    cudaGetSymbolAddress((void**)&QKV, g_QKV);
    cudaGetSymbolAddress((void**)&P, g_P);
    cudaGetSymbolAddress((void**)&R, g_R);
    cudaGetSymbolAddress((void**)&Mb, g_Mb);
    cudaGetSymbolAddress((void**)&Kph, g_Kph);
    cudaGetSymbolAddress((void**)&Kpl, g_Kpl);
    cudaGetSymbolAddress((void**)&VTh, g_VTh);
    cudaGetSymbolAddress((void**)&VTl, g_VTl);
    cudaGetSymbolAddress((void**)&xph, g_xph);
    cudaGetSymbolAddress((void**)&xpl, g_xpl);
    cudaGetSymbolAddress((void**)&pph, g_pph);
    cudaGetSymbolAddress((void**)&ppl, g_ppl);
    cudaGetSymbolAddress((void**)&Pph, g_Pph);
    cudaGetSymbolAddress((void**)&Ppl, g_Ppl);
    cudaGetSymbolAddress((void**)&QRh, g_QRh);
    cudaGetSymbolAddress((void**)&QRl, g_QRl);
    cudaGetSymbolAddress((void**)&Oph, g_Oph);
    cudaGetSymbolAddress((void**)&Opl, g_Opl);
    cudaGetSymbolAddress((void**)&Wqkvh, g_Wqkvh);
    cudaGetSymbolAddress((void**)&Wqkvl, g_Wqkvl);
    cudaGetSymbolAddress((void**)&Wph_, g_Wph);
    cudaGetSymbolAddress((void**)&Wpl_, g_Wpl);
    cudaGetSymbolAddress((void**)&Woh, g_Woh);
    cudaGetSymbolAddress((void**)&Wol, g_Wol);

    cudaFuncSetAttribute(bf16_gemm<0>, cudaFuncAttributeMaxDynamicSharedMemorySize, G2_SMEM);
    cudaFuncSetAttribute(bf16_gemm<1>, cudaFuncAttributeMaxDynamicSharedMemorySize, G2_SMEM);
    cudaFuncSetAttribute(flash_attn, cudaFuncAttributeMaxDynamicSharedMemorySize, FL_SMEM);

    dim3 blk(256);

    // 1) all independent packs
    megapack1<<<dim3(4096, 1, 8), blk>>>(
        x, pos, mask, Wq, Wk, Wv, Wp, Wo,
        Wqkvh, Wqkvl, Wph_, Wpl_, Woh, Wol, xph, xpl, pph, ppl, Mb);

    // 2) fused Q/K/V projection
    bf16_gemm<0><<<dim3(8, 32, 3), blk, G2_SMEM>>>(
        xph, xpl, 256, 0, 0,
        Wqkvh, Wqkvl, 512, 0, 131072,
        QKV, DM, 0, 2097152,
        NB * TT, DM, 256, bq, bk, bv);

    // 3) P projection
    bf16_gemm<0><<<dim3(8, 16, 1), blk, G2_SMEM>>>(
        pph, ppl, 256, 0, 0, Wph_, Wpl_, 512, 0, 0,
        P, DM, 0, 0, LL, DM, 256, bp, bp, bp);

    // 4) dependent packs
    megapack2<<<dim3(2048, 1, 3), blk>>>(
        QKV, P, pbv, Kph, Kpl, VTh, VTl, Pph, Ppl, QRh, QRl);

    // 5) R = (Q[512:]+pbv) @ P^T per (b,h)
    bf16_gemm<1><<<dim3(32, 4, 32), blk, G2_SMEM>>>(
        QRh, QRl, 32, 8LL * 512 * 32, 512 * 32,
        Pph, Ppl, 256, 0, 32,
        R, RSTR, 8LL * 512 * RSTR, (ll)512 * RSTR,
        512, LL, 32, nullptr, nullptr, nullptr);

    // 6) flash attention
    flash_attn<<<dim3(16, 32), dim3(128), FL_SMEM>>>(
        QKV, Kph, Kpl, VTh, VTl, pbu, R, Mb, Oph, Opl);

    // 7) out = O @ Wo + bo
    bf16_gemm<0><<<dim3(8, 32, 1), blk, G2_SMEM>>>(
        Oph, Opl, 256, 0, 0, Woh, Wol, 512, 0, 0,
        out, DM, 0, 0, NB * TT, DM, 256, bo, bo, bo);
}

// round 10
// speedup vs baseline: 1.9809x; 1.0164x over previous
#include <cuda_runtime.h>
#include <cuda_bf16.h>
#include <cstdint>

#define TT 1024
#define DM 512
#define NB 4
#define NH 8
#define DK 64
#define LL 2047   // 2*T - 1
#define RSTR 2048
typedef long long ll;
typedef unsigned long long u64;

// ---------------- scratch ----------------
__device__ float g_QKV[3LL * NB * TT * DM];     // Q | (K unused) | V
__device__ float g_R[32LL * 512 * RSTR];
__device__ unsigned int g_Mb[NB * TT * 32];
__device__ unsigned int g_Kph[32LL * 1024 * 32];
__device__ unsigned int g_Kpl[32LL * 1024 * 32];
__device__ unsigned int g_VTh[32LL * 64 * 512];
__device__ unsigned int g_VTl[32LL * 64 * 512];
__device__ unsigned int g_xph[NB * TT * 256],  g_xpl[NB * TT * 256];
__device__ unsigned int g_pph[2047 * 256],     g_ppl[2047 * 256];
__device__ unsigned int g_Wqkvh[3 * 256 * 512], g_Wqkvl[3 * 256 * 512];
__device__ unsigned int g_Wph[256 * 512], g_Wpl[256 * 512];
__device__ unsigned int g_Woh[256 * 512], g_Wol[256 * 512];
__device__ unsigned int g_Pph[2047 * 256], g_Ppl[2047 * 256];
__device__ unsigned int g_QRh[32LL * 512 * 32], g_QRl[32LL * 512 * 32];
__device__ unsigned int g_Oph[NB * TT * 256], g_Opl[NB * TT * 256];

// ---------------- helpers ----------------
__device__ __forceinline__ float bf16_hi(float x) {
    return __bfloat162float(__float2bfloat16(x));
}
__device__ __forceinline__ uint32_t pack_bf16(float lo_elem, float hi_elem) {
    uint32_t r;
    asm("cvt.rn.bf16x2.f32 %0, %1, %2;" : "=r"(r) : "f"(hi_elem), "f"(lo_elem));
    return r;
}
__device__ __forceinline__ void split_pack(float a, float b, uint32_t& ph, uint32_t& pl) {
    float ha = bf16_hi(a), hb = bf16_hi(b);
    ph = pack_bf16(a, b);
    pl = pack_bf16(a - ha, b - hb);
}
__device__ __forceinline__ void mma_bf16(float* d, const uint32_t* a, uint32_t b0, uint32_t b1) {
    asm volatile(
        "mma.sync.aligned.m16n8k16.row.col.f32.bf16.bf16.f32 "
        "{%0,%1,%2,%3}, {%4,%5,%6,%7}, {%8,%9}, {%0,%1,%2,%3};\n"
        : "+f"(d[0]), "+f"(d[1]), "+f"(d[2]), "+f"(d[3])
        : "r"(a[0]), "r"(a[1]), "r"(a[2]), "r"(a[3]), "r"(b0), "r"(b1));
}
__device__ __forceinline__ void cp_async16(uint32_t dst, const void* src, bool p) {
    asm volatile("cp.async.cg.shared.global [%0], [%1], 16, %2;\n"
                 :: "r"(dst), "l"(src), "r"(p ? 16 : 0));
}
__device__ __forceinline__ void cp_commit() { asm volatile("cp.async.commit_group;\n"); }
template <int N>
__device__ __forceinline__ void cp_wait() { asm volatile("cp.async.wait_group %0;\n" :: "n"(N)); }

// ---------------- mega-pack 1: all input-only packs, grid (4096,1,8) ----------------
__global__ void __launch_bounds__(256) megapack1(
    const float* __restrict__ x, const float* __restrict__ pos,
    const unsigned char* __restrict__ mask,
    const float* __restrict__ Wq, const float* __restrict__ Wk,
    const float* __restrict__ Wv, const float* __restrict__ Wp,
    const float* __restrict__ Wo,
    unsigned int* __restrict__ Wqkvh, unsigned int* __restrict__ Wqkvl,
    unsigned int* __restrict__ Wph, unsigned int* __restrict__ Wpl,
    unsigned int* __restrict__ Woh, unsigned int* __restrict__ Wol,
    unsigned int* __restrict__ xph, unsigned int* __restrict__ xpl,
    unsigned int* __restrict__ pph, unsigned int* __restrict__ ppl,
    unsigned int* __restrict__ Mb)
{
    const int zz = blockIdx.z, bx = blockIdx.x, tid = threadIdx.x;
    if (zz < 5) {
        if (bx >= 512) return;
        int i = bx * 256 + tid;
        int r = i >> 9, n = i & 511;
        const float* W = zz == 0 ? Wq : zz == 1 ? Wk : zz == 2 ? Wv : zz == 3 ? Wp : Wo;
        unsigned int *ph, *pl;
        if (zz < 3)      { ph = Wqkvh + zz * 131072; pl = Wqkvl + zz * 131072; }
        else if (zz == 3){ ph = Wph; pl = Wpl; }
        else             { ph = Woh; pl = Wol; }
        split_pack(W[(2 * r) * 512 + n], W[(2 * r + 1) * 512 + n], ph[i], pl[i]);
    } else if (zz == 5) {
        ll i = (ll)bx * 256 + tid;
        float2 v = *(const float2*)(x + 2 * i);
        split_pack(v.x, v.y, xph[i], xpl[i]);
    } else if (zz == 6) {
        if (bx >= 2047) return;
        ll i = (ll)bx * 256 + tid;
        float2 v = *(const float2*)(pos + 2 * i);
        split_pack(v.x, v.y, pph[i], ppl[i]);
    } else {
        if (bx >= 512) return;
        int i = bx * 256 + tid;
        const uchar4* p = (const uchar4*)(mask + (ll)i * 32);
        unsigned int bits = 0;
#pragma unroll
        for (int j = 0; j < 8; j++) {
            uchar4 v = p[j];
            unsigned int q = (v.x ? 1u : 0u) | (v.y ? 2u : 0u) | (v.z ? 4u : 0u) | (v.w ? 8u : 0u);
            bits |= q << (4 * j);
        }
        Mb[i] = bits;
    }
}

// ---------------- mega-pack 2: V transpose-pack + QR pack, grid (2048,1,2) ----------------
__global__ void __launch_bounds__(256) megapack2(
    const float* __restrict__ QKV, const float* __restrict__ pbv,
    unsigned int* __restrict__ VTh, unsigned int* __restrict__ VTl,
    unsigned int* __restrict__ QRh, unsigned int* __restrict__ QRl)
{
    __shared__ float sv[64][65];
    const int zz = blockIdx.z, bx = blockIdx.x, tid = threadIdx.x;
    if (zz == 0) {
        if (bx >= 512) return;
        const int z = bx >> 4, b = z >> 3, h = z & 7;
        const int s0 = (bx & 15) * 64;
        const int row = tid >> 2, cq = (tid & 3) << 4;
        const float* Vf = QKV + 4194304;
        {
            const float* vr = Vf + ((ll)(b * TT + s0 + row)) * DM + h * DK + cq;
#pragma unroll
            for (int i = 0; i < 4; i++) {
                float4 f = *(const float4*)(vr + 4 * i);
                sv[row][cq + 4 * i] = f.x; sv[row][cq + 4 * i + 1] = f.y;
                sv[row][cq + 4 * i + 2] = f.z; sv[row][cq + 4 * i + 3] = f.w;
            }
        }
        __syncthreads();
        {
            const int d = tid >> 2, sq = (tid & 3) << 4;
            ll base = ((ll)z * 64 + d) * 512 + ((s0 + sq) >> 1);
#pragma unroll
            for (int j = 0; j < 8; j++)
                split_pack(sv[sq + 2 * j][d], sv[sq + 2 * j + 1][d], VTh[base + j], VTl[base + j]);
        }
    } else {
        int i = bx * 256 + tid;
        int z = i >> 14, rem = i & 16383;
        int m = rem >> 5, j = rem & 31;
        int b = z >> 3, h = z & 7;
        float2 q = *(const float2*)(QKV + ((ll)(b * TT + 512 + m)) * DM + h * DK + 2 * j);
        float2 u = *(const float2*)(pbv + h * DK + 2 * j);
        split_pack(q.x + u.x, q.y + u.y, QRh[i], QRl[i]);
    }
}

// ---------------- bf16x2 pipelined GEMM ----------------
// EPACK=0: fp32 C. EPACK=1: h==1 slab emits packed K pairs (others fp32). EPACK=2: packed P pairs.
#define A_STR 20
#define BN_STR 72
#define BT_STR 20
#define G2_SMEM ((4 * 2560 + 4 * 1280) * 4)

template <int TRANSB, int EPACK>
__global__ void __launch_bounds__(256) bf16_gemm(
    const unsigned int* __restrict__ Aph, const unsigned int* __restrict__ Apl,
    int ldap, ll sAb, ll sAh,
    const unsigned int* __restrict__ Bph, const unsigned int* __restrict__ Bpl,
    int ldbp, ll sBb, ll sBh,
    float* __restrict__ C, int ldc, ll sCb, ll sCh,
    int M, int N, int Kp,
    const float* __restrict__ bias0, const float* __restrict__ bias1,
    const float* __restrict__ bias2,
    unsigned int* __restrict__ Ph, unsigned int* __restrict__ Pl)
{
    extern __shared__ uint32_t su[];
    uint32_t* AH = su;
    uint32_t* ALo = su + 5120;
    uint32_t* BH = su + 10240;
    uint32_t* BLo = su + 12800;

    const int z = blockIdx.z, b = z >> 3, h = z & 7;
    const float* bias = (h == 0) ? bias0 : (h == 1) ? bias1 : bias2;
    Aph += (ll)b * sAb + (ll)h * sAh;
    Apl += (ll)b * sAb + (ll)h * sAh;
    Bph += (ll)b * sBb + (ll)h * sBh;
    Bpl += (ll)b * sBb + (ll)h * sBh;

    const int tid = threadIdx.x;
    const int lane = tid & 31, wid = tid >> 5;
    const int g = lane >> 2, t = lane & 3;
    const int wm = wid & 3, wn = wid >> 2;
    const int m0 = blockIdx.y * 128, n0 = blockIdx.x * 64;

    uint32_t sBase = (uint32_t)__cvta_generic_to_shared(su);

    auto stage = [&](int k0p, int stg) {
#pragma unroll
        for (int i = 0; i < 2; i++) {
            int idx = tid + 256 * i;
            int row = idx >> 2, c4 = (idx & 3) << 2;
            bool p = (m0 + row) < M;
            const ll off = (ll)(m0 + row) * ldap + k0p + c4;
            uint32_t d0 = sBase + (uint32_t)(stg * 2560 + row * A_STR + c4) * 4;
            cp_async16(d0, Aph + off, p);
            cp_async16(d0 + 5120 * 4, Apl + off, p);
        }
        if (!TRANSB) {
            int row = tid >> 4, c4 = (tid & 15) << 2;
            const ll off = (ll)(k0p + row) * ldbp + n0 + c4;
            uint32_t d0 = sBase + (uint32_t)(10240 + stg * 1280 + row * BN_STR + c4) * 4;
            cp_async16(d0, Bph + off, true);
            cp_async16(d0 + 2560 * 4, Bpl + off, true);
        } else {
            int row = tid >> 2, c4 = (tid & 3) << 2;
            bool p = (n0 + row) < N;
            const ll off = (ll)(n0 + row) * ldbp + k0p + c4;
            uint32_t d0 = sBase + (uint32_t)(10240 + stg * 1280 + row * BT_STR + c4) * 4;
            cp_async16(d0, Bph + off, p);
            cp_async16(d0 + 2560 * 4, Bpl + off, p);
        }
    };

    float d[2][4][4];
#pragma unroll
    for (int i = 0; i < 2; i++)
#pragma unroll
        for (int j = 0; j < 4; j++)
#pragma unroll
            for (int c = 0; c < 4; c++) d[i][j][c] = 0.f;

    const int nIter = Kp >> 4;
    stage(0, 0);
    cp_commit();

    for (int it = 0; it < nIter; it++) {
        __syncthreads();
        if (it + 1 < nIter) { stage((it + 1) << 4, (it + 1) & 1); cp_commit(); cp_wait<1>(); }
        else cp_wait<0>();
        __syncthreads();

        const uint32_t* pAH = AH + (it & 1) * 2560;
        const uint32_t* pAL = ALo + (it & 1) * 2560;
        const uint32_t* pBH = BH + (it & 1) * 1280;
        const uint32_t* pBL = BLo + (it & 1) * 1280;

#pragma unroll
        for (int ck = 0; ck < 2; ck++) {
            const int kb = ck * 8;
            uint32_t aH[2][4], aL[2][4];
#pragma unroll
            for (int mt = 0; mt < 2; mt++) {
                int base = (wm * 32 + mt * 16 + g) * A_STR + kb;
                aH[mt][0] = pAH[base + t];
                aH[mt][1] = pAH[base + 8 * A_STR + t];
                aH[mt][2] = pAH[base + t + 4];
                aH[mt][3] = pAH[base + 8 * A_STR + t + 4];
                aL[mt][0] = pAL[base + t];
                aL[mt][1] = pAL[base + 8 * A_STR + t];
                aL[mt][2] = pAL[base + t + 4];
                aL[mt][3] = pAL[base + 8 * A_STR + t + 4];
            }
#pragma unroll
            for (int nt = 0; nt < 4; nt++) {
                int col = wn * 32 + nt * 8 + g;
                int i0, i1;
                if (!TRANSB) { i0 = (kb + t) * BN_STR + col; i1 = (kb + t + 4) * BN_STR + col; }
                else         { i0 = col * BT_STR + kb + t;   i1 = col * BT_STR + kb + t + 4; }
                uint32_t b0h = pBH[i0], b1h = pBH[i1];
                uint32_t b0l = pBL[i0], b1l = pBL[i1];
#pragma unroll
                for (int mt = 0; mt < 2; mt++) {
                    mma_bf16(d[mt][nt], aH[mt], b0h, b1h);
                    mma_bf16(d[mt][nt], aL[mt], b0h, b1h);
                    mma_bf16(d[mt][nt], aH[mt], b0l, b1l);
                }
            }
        }
    }

    // ---- epilogue ----
    const bool packK = (EPACK == 1 && h == 1);
    if (EPACK == 2 || packK) {
#pragma unroll
        for (int mt = 0; mt < 2; mt++) {
#pragma unroll
            for (int nt = 0; nt < 4; nt++) {
                int col = n0 + wn * 32 + nt * 8 + 2 * t;
                float b0 = bias ? bias[col] : 0.f;
                float b1 = bias ? bias[col + 1] : 0.f;
#pragma unroll
                for (int rr = 0; rr < 2; rr++) {
                    int row = m0 + wm * 32 + mt * 16 + g + 8 * rr;
                    if (row >= M) continue;
                    float v0 = d[mt][nt][2 * rr + 0] + b0;
                    float v1 = d[mt][nt][2 * rr + 1] + b1;
                    ll idx;
                    if (EPACK == 2) {
                        idx = (ll)row * 256 + (col >> 1);
                    } else {
                        int zk = ((row >> 10) << 3) + (col >> 6);
                        idx = ((ll)zk * 1024 + (row & 1023)) * 32 + ((col & 63) >> 1);
                    }
                    split_pack(v0, v1, Ph[idx], Pl[idx]);
                }
            }
        }
        return;
    }

    float* Cz = C + (ll)b * sCb + (ll)h * sCh;
#pragma unroll
    for (int mt = 0; mt < 2; mt++) {
        int row = m0 + wm * 32 + mt * 16 + g;
#pragma unroll
        for (int nt = 0; nt < 4; nt++) {
            int col = n0 + wn * 32 + nt * 8 + 2 * t;
            float b0 = (bias && col < N) ? bias[col] : 0.f;
            float b1 = (bias && col + 1 < N) ? bias[col + 1] : 0.f;
            if (row < M) {
                if (col < N)     Cz[(ll)row * ldc + col]     = d[mt][nt][0] + b0;
                if (col + 1 < N) Cz[(ll)row * ldc + col + 1] = d[mt][nt][1] + b1;
            }
            if (row + 8 < M) {
                if (col < N)     Cz[(ll)(row + 8) * ldc + col]     = d[mt][nt][2] + b0;
                if (col + 1 < N) Cz[(ll)(row + 8) * ldc + col + 1] = d[mt][nt][3] + b1;
            }
        }
    }
}

// ---------------- fused flash attention: bf16x2, 3-term QK and PV ----------------
#define PSTR 36
#define FL_SMEM (8 * 2304 * 4)

__global__ void __launch_bounds__(128, 3) flash_attn(
    const float* __restrict__ Q,
    const unsigned int* __restrict__ Kph, const unsigned int* __restrict__ Kpl,
    const unsigned int* __restrict__ VTh, const unsigned int* __restrict__ VTl,
    const float* __restrict__ pbu, const float* __restrict__ Rr,
    const unsigned int* __restrict__ mbits,
    unsigned int* __restrict__ Oph, unsigned int* __restrict__ Opl)
{
    extern __shared__ uint32_t smu[];
    uint32_t* KH = smu;
    uint32_t* KL = smu + 2 * 2304;
    uint32_t* VH = smu + 4 * 2304;
    uint32_t* VL = smu + 6 * 2304;

    const int z = blockIdx.y, b = z >> 3, h = z & 7;
    const int t0 = blockIdx.x * 64;
    const int tid = threadIdx.x, lane = tid & 31, w = tid >> 5;
    const int g = lane >> 2, t = lane & 3;

    const float* Qb = Q + ((ll)(b * TT + t0)) * DM + h * DK;
    const ll rb = (ll)z * 512 * RSTR;

    uint32_t qh[4][4], ql[4][4];
    {
        const int r0 = w * 16 + g, r1 = r0 + 8;
#pragma unroll
        for (int ks = 0; ks < 4; ks++) {
#pragma unroll
            for (int half = 0; half < 2; half++) {
                int c = 16 * ks + 8 * half + 2 * t;
                float u0 = pbu[h * DK + c], u1 = pbu[h * DK + c + 1];
                float x0 = Qb[(ll)r0 * DM + c] + u0;
                float x1 = Qb[(ll)r0 * DM + c + 1] + u1;
                float y0 = Qb[(ll)r1 * DM + c] + u0;
                float y1 = Qb[(ll)r1 * DM + c + 1] + u1;
                split_pack(x0, x1, qh[ks][2 * half + 0], ql[ks][2 * half + 0]);
                split_pack(y0, y1, qh[ks][2 * half + 1], ql[ks][2 * half + 1]);
            }
        }
    }

    float o[8][4];
#pragma unroll
    for (int i = 0; i < 8; i++)
#pragma unroll
        for (int j = 0; j < 4; j++) o[i][j] = 0.f;
    float mx0 = -1e30f, mx1 = -1e30f, l0 = 0.f, l1 = 0.f;

    uint32_t sBase = (uint32_t)__cvta_generic_to_shared(smu);

    auto loadKV = [&](int st, int buf) {
        const unsigned int* kh = Kph + ((ll)z * 1024 + st * 64) * 32;
        const unsigned int* kl = Kpl + ((ll)z * 1024 + st * 64) * 32;
        const unsigned int* vh = VTh + (ll)z * 64 * 512 + st * 32;
        const unsigned int* vl = VTl + (ll)z * 64 * 512 + st * 32;
        uint32_t o0 = sBase + (uint32_t)(buf * 2304) * 4;
#pragma unroll
        for (int i = 0; i < 4; i++) {
            int idx = tid + 128 * i;
            int row = idx >> 3, c4 = (idx & 7) << 2;
            uint32_t soff = (uint32_t)(row * PSTR + c4) * 4;
            cp_async16(o0 + soff,                kh + (ll)row * 32 + c4, true);
            cp_async16(o0 + 2 * 2304 * 4 + soff, kl + (ll)row * 32 + c4, true);
            cp_async16(o0 + 4 * 2304 * 4 + soff, vh + (ll)row * 512 + c4, true);
            cp_async16(o0 + 6 * 2304 * 4 + soff, vl + (ll)row * 512 + c4, true);
        }
    };

    loadKV(0, 0);
    cp_commit();

    const int tg0 = t0 + w * 16 + g, tg1 = tg0 + 8;
    const float* R0 = Rr + rb + (ll)(tg0 >> 1) * RSTR;
    const float* R1 = Rr + rb + (ll)(tg1 >> 1) * RSTR;
    const int p0 = (tg0 & 1) << 10, p1 = (tg1 & 1) << 10;
    const uint2* mrow0 = (const uint2*)(mbits + ((ll)b * TT + tg0) * 32);
    const uint2* mrow1 = (const uint2*)(mbits + ((ll)b * TT + tg1) * 32);

    for (int st = 0; st < 16; st++) {
        const int buf = st & 1;
        cp_wait<0>();
        __syncthreads();
        if (st + 1 < 16) { loadKV(st + 1, 1 - buf); cp_commit(); }

        const uint32_t* pKH = KH + buf * 2304;
        const uint32_t* pKL = KL + buf * 2304;
        const uint32_t* pVH = VH + buf * 2304;
        const uint32_t* pVL = VL + buf * 2304;

        float sc[8][4];
#pragma unroll
        for (int i = 0; i < 8; i++)
#pragma unroll
            for (int j = 0; j < 4; j++) sc[i][j] = 0.f;
#pragma unroll
        for (int nt = 0; nt < 8; nt++) {
            const int srow = (nt * 8 + g) * PSTR;
#pragma unroll
            for (int ks = 0; ks < 4; ks++) {
                uint32_t b0h = pKH[srow + 8 * ks + t];
                uint32_t b1h = pKH[srow + 8 * ks + 4 + t];
                uint32_t b0l = pKL[srow + 8 * ks + t];
                uint32_t b1l = pKL[srow + 8 * ks + 4 + t];
                mma_bf16(sc[nt], qh[ks], b0h, b1h);
                mma_bf16(sc[nt], ql[ks], b0h, b1h);
                mma_bf16(sc[nt], qh[ks], b0l, b1l);
            }
        }

        const int s0 = st * 64;
#pragma unroll
        for (int nt = 0; nt < 8; nt++) {
            int s_ = s0 + nt * 8 + 2 * t;
            int la = s_ + p0, lb = s_ + p1;
            float2 va = *(const float2*)(R0 + la);
            float2 vb = *(const float2*)(R1 + lb);
            float pa1 = (la + 1 == LL) ? 0.f : va.y;
            float pb1 = (lb + 1 == LL) ? 0.f : vb.y;
            sc[nt][0] = (sc[nt][0] + va.x) * 0.125f;
            sc[nt][1] = (sc[nt][1] + pa1) * 0.125f;
            sc[nt][2] = (sc[nt][2] + vb.x) * 0.125f;
            sc[nt][3] = (sc[nt][3] + pb1) * 0.125f;
        }
        {
            uint2 w0 = mrow0[st], w1 = mrow1[st];
            u64 m0 = (u64)w0.x | ((u64)w0.y << 32);
            u64 m1 = (u64)w1.x | ((u64)w1.y << 32);
            if (m0 | m1) {
#pragma unroll
                for (int nt = 0; nt < 8; nt++) {
                    int p = nt * 8 + 2 * t;
                    if ((m0 >> p) & 1)       sc[nt][0] = -1e9f;
                    if ((m0 >> (p + 1)) & 1) sc[nt][1] = -1e9f;
                    if ((m1 >> p) & 1)       sc[nt][2] = -1e9f;
                    if ((m1 >> (p + 1)) & 1) sc[nt][3] = -1e9f;
                }
            }
        }

        float rmx0 = -1e30f, rmx1 = -1e30f;
#pragma unroll
        for (int nt = 0; nt < 8; nt++) {
            rmx0 = fmaxf(rmx0, fmaxf(sc[nt][0], sc[nt][1]));
            rmx1 = fmaxf(rmx1, fmaxf(sc[nt][2], sc[nt][3]));
        }
        rmx0 = fmaxf(rmx0, __shfl_xor_sync(0xffffffffu, rmx0, 1));
        rmx0 = fmaxf(rmx0, __shfl_xor_sync(0xffffffffu, rmx0, 2));
        rmx1 = fmaxf(rmx1, __shfl_xor_sync(0xffffffffu, rmx1, 1));
        rmx1 = fmaxf(rmx1, __shfl_xor_sync(0xffffffffu, rmx1, 2));

        float mn0 = fmaxf(mx0, rmx0), mn1 = fmaxf(mx1, rmx1);
        float al0 = __expf(mx0 - mn0), al1 = __expf(mx1 - mn1);
        float rs0 = 0.f, rs1 = 0.f;
#pragma unroll
        for (int nt = 0; nt < 8; nt++) {
            sc[nt][0] = __expf(sc[nt][0] - mn0);
            sc[nt][1] = __expf(sc[nt][1] - mn0);
            sc[nt][2] = __expf(sc[nt][2] - mn1);
            sc[nt][3] = __expf(sc[nt][3] - mn1);
            rs0 += sc[nt][0] + sc[nt][1];
            rs1 += sc[nt][2] + sc[nt][3];
        }
        rs0 += __shfl_xor_sync(0xffffffffu, rs0, 1);
        rs0 += __shfl_xor_sync(0xffffffffu, rs0, 2);
        rs1 += __shfl_xor_sync(0xffffffffu, rs1, 1);
        rs1 += __shfl_xor_sync(0xffffffffu, rs1, 2);
        l0 = l0 * al0 + rs0;
        l1 = l1 * al1 + rs1;
        mx0 = mn0; mx1 = mn1;
#pragma unroll
        for (int dt = 0; dt < 8; dt++) {
            o[dt][0] *= al0; o[dt][1] *= al0;
            o[dt][2] *= al1; o[dt][3] *= al1;
        }

#pragma unroll
        for (int j = 0; j < 4; j++) {
            uint32_t aPh[4], aPl[4];
            split_pack(sc[2 * j][0],     sc[2 * j][1],     aPh[0], aPl[0]);
            split_pack(sc[2 * j][2],     sc[2 * j][3],     aPh[1], aPl[1]);
            split_pack(sc[2 * j + 1][0], sc[2 * j + 1][1], aPh[2], aPl[2]);
            split_pack(sc[2 * j + 1][2], sc[2 * j + 1][3], aPh[3], aPl[3]);
#pragma unroll
            for (int dt = 0; dt < 8; dt++) {
                const int vrow = (dt * 8 + g) * PSTR;
                uint32_t b0h = pVH[vrow + 8 * j + t];
                uint32_t b1h = pVH[vrow + 8 * j + 4 + t];
                uint32_t b0l = pVL[vrow + 8 * j + t];
                uint32_t b1l = pVL[vrow + 8 * j + 4 + t];
                mma_bf16(o[dt], aPh, b0h, b1h);
                mma_bf16(o[dt], aPl, b0h, b1h);
                mma_bf16(o[dt], aPh, b0l, b1l);
            }
        }
    }

    float inv0 = 1.f / l0, inv1 = 1.f / l1;
    ll base0 = ((ll)(b * TT + tg0)) * 256 + h * 32;
    ll base1 = ((ll)(b * TT + tg1)) * 256 + h * 32;
#pragma unroll
    for (int dt = 0; dt < 8; dt++) {
        int pj = dt * 4 + t;
        split_pack(o[dt][0] * inv0, o[dt][1] * inv0, Oph[base0 + pj], Opl[base0 + pj]);
        split_pack(o[dt][2] * inv1, o[dt][3] * inv1, Oph[base1 + pj], Opl[base1 + pj]);
    }
}

// ---------------- launch ----------------
extern "C" void kernel_launch(void* const* d_in, const int* in_sizes, int n_in,
                              void* d_out, int out_size)
{
    const float* x   = (const float*)d_in[0];
    const float* pos = (const float*)d_in[1];
    const unsigned char* mask = (const unsigned char*)d_in[2];
    const float* Wq = (const float*)d_in[3];  const float* bq = (const float*)d_in[4];
    const float* Wk = (const float*)d_in[5];  const float* bk = (const float*)d_in[6];
    const float* Wv = (const float*)d_in[7];  const float* bv = (const float*)d_in[8];
    const float* Wp = (const float*)d_in[9];  const float* bp = (const float*)d_in[10];
    const float* Wo = (const float*)d_in[11]; const float* bo = (const float*)d_in[12];
    const float* pbu = (const float*)d_in[13];
    const float* pbv = (const float*)d_in[14];
    float* out = (float*)d_out;

    float *QKV, *R;
    unsigned int *Mb, *Kph, *Kpl, *VTh, *VTl;
    unsigned int *xph, *xpl, *pph, *ppl, *Pph, *Ppl, *QRh, *QRl, *Oph, *Opl;
    unsigned int *Wqkvh, *Wqkvl, *Wph_, *Wpl_, *Woh, *Wol;
    cudaGetSymbolAddress((void**)&QKV, g_QKV);
    cudaGetSymbolAddress((void**)&R, g_R);
    cudaGetSymbolAddress((void**)&Mb, g_Mb);
    cudaGetSymbolAddress((void**)&Kph, g_Kph);
    cudaGetSymbolAddress((void**)&Kpl, g_Kpl);
    cudaGetSymbolAddress((void**)&VTh, g_VTh);
    cudaGetSymbolAddress((void**)&VTl, g_VTl);
    cudaGetSymbolAddress((void**)&xph, g_xph);
    cudaGetSymbolAddress((void**)&xpl, g_xpl);
    cudaGetSymbolAddress((void**)&pph, g_pph);
    cudaGetSymbolAddress((void**)&ppl, g_ppl);
    cudaGetSymbolAddress((void**)&Pph, g_Pph);
    cudaGetSymbolAddress((void**)&Ppl, g_Ppl);
    cudaGetSymbolAddress((void**)&QRh, g_QRh);
    cudaGetSymbolAddress((void**)&QRl, g_QRl);
    cudaGetSymbolAddress((void**)&Oph, g_Oph);
    cudaGetSymbolAddress((void**)&Opl, g_Opl);
    cudaGetSymbolAddress((void**)&Wqkvh, g_Wqkvh);
    cudaGetSymbolAddress((void**)&Wqkvl, g_Wqkvl);
    cudaGetSymbolAddress((void**)&Wph_, g_Wph);
    cudaGetSymbolAddress((void**)&Wpl_, g_Wpl);
    cudaGetSymbolAddress((void**)&Woh, g_Woh);
    cudaGetSymbolAddress((void**)&Wol, g_Wol);

    cudaFuncSetAttribute((const void*)bf16_gemm<0, 0>, cudaFuncAttributeMaxDynamicSharedMemorySize, G2_SMEM);
    cudaFuncSetAttribute((const void*)bf16_gemm<0, 1>, cudaFuncAttributeMaxDynamicSharedMemorySize, G2_SMEM);
    cudaFuncSetAttribute((const void*)bf16_gemm<0, 2>, cudaFuncAttributeMaxDynamicSharedMemorySize, G2_SMEM);
    cudaFuncSetAttribute((const void*)bf16_gemm<1, 0>, cudaFuncAttributeMaxDynamicSharedMemorySize, G2_SMEM);
    cudaFuncSetAttribute((const void*)flash_attn, cudaFuncAttributeMaxDynamicSharedMemorySize, FL_SMEM);

    dim3 blk(256);

    // 1) all independent packs
    megapack1<<<dim3(4096, 1, 8), blk>>>(
        x, pos, mask, Wq, Wk, Wv, Wp, Wo,
        Wqkvh, Wqkvl, Wph_, Wpl_, Woh, Wol, xph, xpl, pph, ppl, Mb);

    // 2) fused Q/K/V projection; K slab (h==1) emits packed pairs directly
    bf16_gemm<0, 1><<<dim3(8, 32, 3), blk, G2_SMEM>>>(
        xph, xpl, 256, 0, 0,
        Wqkvh, Wqkvl, 512, 0, 131072,
        QKV, DM, 0, 2097152,
        NB * TT, DM, 256, bq, bk, bv, Kph, Kpl);

    // 3) P projection -> packed Pph/Ppl directly (no fp32 P)
    bf16_gemm<0, 2><<<dim3(8, 16, 1), blk, G2_SMEM>>>(
        pph, ppl, 256, 0, 0, Wph_, Wpl_, 512, 0, 0,
        nullptr, DM, 0, 0, LL, DM, 256, bp, bp, bp, Pph, Ppl);

    // 4) dependent packs (V transpose-pack + QR pack)
    megapack2<<<dim3(2048, 1, 2), blk>>>(QKV, pbv, VTh, VTl, QRh, QRl);

    // 5) R = (Q[512:]+pbv) @ P^T per (b,h)
    bf16_gemm<1, 0><<<dim3(32, 4, 32), blk, G2_SMEM>>>(
        QRh, QRl, 32, 8LL * 512 * 32, 512 * 32,
        Pph, Ppl, 256, 0, 32,
        R, RSTR, 8LL * 512 * RSTR, (ll)512 * RSTR,
        512, LL, 32, nullptr, nullptr, nullptr, nullptr, nullptr);

    // 6) flash attention
    flash_attn<<<dim3(16, 32), dim3(128), FL_SMEM>>>(
        QKV, Kph, Kpl, VTh, VTl, pbu, R, Mb, Oph, Opl);

    // 7) out = O @ Wo + bo
    bf16_gemm<0, 0><<<dim3(8, 32, 1), blk, G2_SMEM>>>(
        Oph, Opl, 256, 0, 0, Woh, Wol, 512, 0, 0,
        out, DM, 0, 0, NB * TT, DM, 256, bo, bo, bo, nullptr, nullptr);
}

// round 11
// speedup vs baseline: 1.9909x; 1.0051x over previous
#include <cuda_runtime.h>
#include <cuda_bf16.h>
#include <cstdint>

#define TT 1024
#define DM 512
#define NB 4
#define NH 8
#define DK 64
#define LL 2047   // 2*T - 1
#define RSTR 2048
typedef long long ll;
typedef unsigned long long u64;

// ---------------- scratch ----------------
__device__ float g_QKV[3LL * NB * TT * DM];     // Q | (K unused) | V
__device__ float g_R[32LL * 512 * RSTR];
__device__ unsigned int g_Mb[NB * TT * 32];
__device__ unsigned int g_Kph[32LL * 1024 * 32];
__device__ unsigned int g_Kpl[32LL * 1024 * 32];
__device__ unsigned int g_VTh[32LL * 64 * 512];
__device__ unsigned int g_VTl[32LL * 64 * 512];
__device__ unsigned int g_xph[NB * TT * 256],  g_xpl[NB * TT * 256];
__device__ unsigned int g_pph[2047 * 256],     g_ppl[2047 * 256];
__device__ unsigned int g_Wqkvh[3 * 256 * 512], g_Wqkvl[3 * 256 * 512];
__device__ unsigned int g_Wph[256 * 512], g_Wpl[256 * 512];
__device__ unsigned int g_Woh[256 * 512], g_Wol[256 * 512];
__device__ unsigned int g_Pph[2047 * 256], g_Ppl[2047 * 256];
__device__ unsigned int g_QRh[32LL * 512 * 32], g_QRl[32LL * 512 * 32];
__device__ unsigned int g_Oph[NB * TT * 256], g_Opl[NB * TT * 256];

// ---------------- helpers ----------------
__device__ __forceinline__ float bf16_hi(float x) {
    return __bfloat162float(__float2bfloat16(x));
}
__device__ __forceinline__ uint32_t pack_bf16(float lo_elem, float hi_elem) {
    uint32_t r;
    asm("cvt.rn.bf16x2.f32 %0, %1, %2;" : "=r"(r) : "f"(hi_elem), "f"(lo_elem));
    return r;
}
__device__ __forceinline__ void split_pack(float a, float b, uint32_t& ph, uint32_t& pl) {
    float ha = bf16_hi(a), hb = bf16_hi(b);
    ph = pack_bf16(a, b);
    pl = pack_bf16(a - ha, b - hb);
}
__device__ __forceinline__ void mma_bf16(float* d, const uint32_t* a, uint32_t b0, uint32_t b1) {
    asm volatile(
        "mma.sync.aligned.m16n8k16.row.col.f32.bf16.bf16.f32 "
        "{%0,%1,%2,%3}, {%4,%5,%6,%7}, {%8,%9}, {%0,%1,%2,%3};\n"
        : "+f"(d[0]), "+f"(d[1]), "+f"(d[2]), "+f"(d[3])
        : "r"(a[0]), "r"(a[1]), "r"(a[2]), "r"(a[3]), "r"(b0), "r"(b1));
}
__device__ __forceinline__ void ldsm_x4(uint32_t& r0, uint32_t& r1, uint32_t& r2, uint32_t& r3,
                                        uint32_t addr) {
    asm volatile("ldmatrix.sync.aligned.m8n8.x4.shared.b16 {%0,%1,%2,%3}, [%4];\n"
                 : "=r"(r0), "=r"(r1), "=r"(r2), "=r"(r3) : "r"(addr));
}
__device__ __forceinline__ void cp_async16(uint32_t dst, const void* src, bool p) {
    asm volatile("cp.async.cg.shared.global [%0], [%1], 16, %2;\n"
                 :: "r"(dst), "l"(src), "r"(p ? 16 : 0));
}
__device__ __forceinline__ void cp_commit() { asm volatile("cp.async.commit_group;\n"); }
template <int N>
__device__ __forceinline__ void cp_wait() { asm volatile("cp.async.wait_group %0;\n" :: "n"(N)); }

// ---------------- mega-pack 1: all input-only packs, grid (4096,1,8) ----------------
__global__ void __launch_bounds__(256) megapack1(
    const float* __restrict__ x, const float* __restrict__ pos,
    const unsigned char* __restrict__ mask,
    const float* __restrict__ Wq, const float* __restrict__ Wk,
    const float* __restrict__ Wv, const float* __restrict__ Wp,
    const float* __restrict__ Wo,
    unsigned int* __restrict__ Wqkvh, unsigned int* __restrict__ Wqkvl,
    unsigned int* __restrict__ Wph, unsigned int* __restrict__ Wpl,
    unsigned int* __restrict__ Woh, unsigned int* __restrict__ Wol,
    unsigned int* __restrict__ xph, unsigned int* __restrict__ xpl,
    unsigned int* __restrict__ pph, unsigned int* __restrict__ ppl,
    unsigned int* __restrict__ Mb)
{
    const int zz = blockIdx.z, bx = blockIdx.x, tid = threadIdx.x;
    if (zz < 5) {
        if (bx >= 512) return;
        int i = bx * 256 + tid;
        int r = i >> 9, n = i & 511;
        const float* W = zz == 0 ? Wq : zz == 1 ? Wk : zz == 2 ? Wv : zz == 3 ? Wp : Wo;
        unsigned int *ph, *pl;
        if (zz < 3)      { ph = Wqkvh + zz * 131072; pl = Wqkvl + zz * 131072; }
        else if (zz == 3){ ph = Wph; pl = Wpl; }
        else             { ph = Woh; pl = Wol; }
        split_pack(W[(2 * r) * 512 + n], W[(2 * r + 1) * 512 + n], ph[i], pl[i]);
    } else if (zz == 5) {
        ll i = (ll)bx * 256 + tid;
        float2 v = *(const float2*)(x + 2 * i);
        split_pack(v.x, v.y, xph[i], xpl[i]);
    } else if (zz == 6) {
        if (bx >= 2047) return;
        ll i = (ll)bx * 256 + tid;
        float2 v = *(const float2*)(pos + 2 * i);
        split_pack(v.x, v.y, pph[i], ppl[i]);
    } else {
        if (bx >= 512) return;
        int i = bx * 256 + tid;
        const uchar4* p = (const uchar4*)(mask + (ll)i * 32);
        unsigned int bits = 0;
#pragma unroll
        for (int j = 0; j < 8; j++) {
            uchar4 v = p[j];
            unsigned int q = (v.x ? 1u : 0u) | (v.y ? 2u : 0u) | (v.z ? 4u : 0u) | (v.w ? 8u : 0u);
            bits |= q << (4 * j);
        }
        Mb[i] = bits;
    }
}

// ---------------- mega-pack 2: V transpose-pack + QR pack, grid (2048,1,2) ----------------
__global__ void __launch_bounds__(256) megapack2(
    const float* __restrict__ QKV, const float* __restrict__ pbv,
    unsigned int* __restrict__ VTh, unsigned int* __restrict__ VTl,
    unsigned int* __restrict__ QRh, unsigned int* __restrict__ QRl)
{
    __shared__ float sv[64][65];
    const int zz = blockIdx.z, bx = blockIdx.x, tid = threadIdx.x;
    if (zz == 0) {
        if (bx >= 512) return;
        const int z = bx >> 4, b = z >> 3, h = z & 7;
        const int s0 = (bx & 15) * 64;
        const int row = tid >> 2, cq = (tid & 3) << 4;
        const float* Vf = QKV + 4194304;
        {
            const float* vr = Vf + ((ll)(b * TT + s0 + row)) * DM + h * DK + cq;
#pragma unroll
            for (int i = 0; i < 4; i++) {
                float4 f = *(const float4*)(vr + 4 * i);
                sv[row][cq + 4 * i] = f.x; sv[row][cq + 4 * i + 1] = f.y;
                sv[row][cq + 4 * i + 2] = f.z; sv[row][cq + 4 * i + 3] = f.w;
            }
        }
        __syncthreads();
        {
            const int d = tid >> 2, sq = (tid & 3) << 4;
            ll base = ((ll)z * 64 + d) * 512 + ((s0 + sq) >> 1);
#pragma unroll
            for (int j = 0; j < 8; j++)
                split_pack(sv[sq + 2 * j][d], sv[sq + 2 * j + 1][d], VTh[base + j], VTl[base + j]);
        }
    } else {
        int i = bx * 256 + tid;
        int z = i >> 14, rem = i & 16383;
        int m = rem >> 5, j = rem & 31;
        int b = z >> 3, h = z & 7;
        float2 q = *(const float2*)(QKV + ((ll)(b * TT + 512 + m)) * DM + h * DK + 2 * j);
        float2 u = *(const float2*)(pbv + h * DK + 2 * j);
        split_pack(q.x + u.x, q.y + u.y, QRh[i], QRl[i]);
    }
}

// ---------------- bf16x2 pipelined GEMM (ldmatrix fragments) ----------------
// EPACK=0: fp32 C. EPACK=1: h==1 slab emits packed K pairs. EPACK=2: packed P pairs.
#define A_STR 20
#define BN_STR 72
#define BT_STR 20
#define G2_SMEM ((4 * 2560 + 4 * 1280) * 4)

template <int TRANSB, int EPACK>
__global__ void __launch_bounds__(256) bf16_gemm(
    const unsigned int* __restrict__ Aph, const unsigned int* __restrict__ Apl,
    int ldap, ll sAb, ll sAh,
    const unsigned int* __restrict__ Bph, const unsigned int* __restrict__ Bpl,
    int ldbp, ll sBb, ll sBh,
    float* __restrict__ C, int ldc, ll sCb, ll sCh,
    int M, int N, int Kp,
    const float* __restrict__ bias0, const float* __restrict__ bias1,
    const float* __restrict__ bias2,
    unsigned int* __restrict__ Ph, unsigned int* __restrict__ Pl)
{
    extern __shared__ uint32_t su[];
    uint32_t* BH = su + 10240;
    uint32_t* BLo = su + 12800;

    const int z = blockIdx.z, b = z >> 3, h = z & 7;
    const float* bias = (h == 0) ? bias0 : (h == 1) ? bias1 : bias2;
    Aph += (ll)b * sAb + (ll)h * sAh;
    Apl += (ll)b * sAb + (ll)h * sAh;
    Bph += (ll)b * sBb + (ll)h * sBh;
    Bpl += (ll)b * sBb + (ll)h * sBh;

    const int tid = threadIdx.x;
    const int lane = tid & 31, wid = tid >> 5;
    const int g = lane >> 2, t = lane & 3;
    const int grp = lane >> 3, gi = lane & 7;
    const int wm = wid & 3, wn = wid >> 2;
    const int m0 = blockIdx.y * 128, n0 = blockIdx.x * 64;

    uint32_t sBase = (uint32_t)__cvta_generic_to_shared(su);

    auto stage = [&](int k0p, int stg) {
#pragma unroll
        for (int i = 0; i < 2; i++) {
            int idx = tid + 256 * i;
            int row = idx >> 2, c4 = (idx & 3) << 2;
            bool p = (m0 + row) < M;
            const ll off = (ll)(m0 + row) * ldap + k0p + c4;
            uint32_t d0 = sBase + (uint32_t)(stg * 2560 + row * A_STR + c4) * 4;
            cp_async16(d0, Aph + off, p);
            cp_async16(d0 + 5120 * 4, Apl + off, p);
        }
        if (!TRANSB) {
            int row = tid >> 4, c4 = (tid & 15) << 2;
            const ll off = (ll)(k0p + row) * ldbp + n0 + c4;
            uint32_t d0 = sBase + (uint32_t)(10240 + stg * 1280 + row * BN_STR + c4) * 4;
            cp_async16(d0, Bph + off, true);
            cp_async16(d0 + 2560 * 4, Bpl + off, true);
        } else {
            int row = tid >> 2, c4 = (tid & 3) << 2;
            bool p = (n0 + row) < N;
            const ll off = (ll)(n0 + row) * ldbp + k0p + c4;
            uint32_t d0 = sBase + (uint32_t)(10240 + stg * 1280 + row * BT_STR + c4) * 4;
            cp_async16(d0, Bph + off, p);
            cp_async16(d0 + 2560 * 4, Bpl + off, p);
        }
    };

    float d[2][4][4];
#pragma unroll
    for (int i = 0; i < 2; i++)
#pragma unroll
        for (int j = 0; j < 4; j++)
#pragma unroll
            for (int c = 0; c < 4; c++) d[i][j][c] = 0.f;

    const int nIter = Kp >> 4;
    stage(0, 0);
    cp_commit();

    for (int it = 0; it < nIter; it++) {
        __syncthreads();
        if (it + 1 < nIter) { stage((it + 1) << 4, (it + 1) & 1); cp_commit(); cp_wait<1>(); }
        else cp_wait<0>();
        __syncthreads();

        // ldmatrix per-lane base addresses (groups: A rows +0/+8, cols +0/+4)
        const uint32_t aBaseH = sBase +
            (uint32_t)(((it & 1) * 2560 + (wm * 32 + ((grp & 1) << 3) + gi) * A_STR + ((grp >> 1) << 2)) << 2);
        const uint32_t aBaseL = aBaseH + (5120u << 2);
        uint32_t bBaseT = 0;
        if (TRANSB)
            bBaseT = sBase + (uint32_t)((10240 + (grp < 2 ? 0 : 2560) + (it & 1) * 1280 +
                                         (wn * 32 + gi) * BT_STR + ((grp & 1) << 2)) << 2);
        const uint32_t* pBH = BH + (it & 1) * 1280;
        const uint32_t* pBL = BLo + (it & 1) * 1280;

#pragma unroll
        for (int ck = 0; ck < 2; ck++) {
            const int kb = ck * 8;
            uint32_t aH[2][4], aL[2][4];
#pragma unroll
            for (int mt = 0; mt < 2; mt++) {
                uint32_t off = (uint32_t)((mt * 16 * A_STR + kb) << 2);
                ldsm_x4(aH[mt][0], aH[mt][1], aH[mt][2], aH[mt][3], aBaseH + off);
                ldsm_x4(aL[mt][0], aL[mt][1], aL[mt][2], aL[mt][3], aBaseL + off);
            }
#pragma unroll
            for (int nt = 0; nt < 4; nt++) {
                uint32_t b0h, b1h, b0l, b1l;
                if (!TRANSB) {
                    int col = wn * 32 + nt * 8 + g;
                    int i0 = (kb + t) * BN_STR + col, i1 = (kb + t + 4) * BN_STR + col;
                    b0h = pBH[i0]; b1h = pBH[i1];
                    b0l = pBL[i0]; b1l = pBL[i1];
                } else {
                    ldsm_x4(b0h, b1h, b0l, b1l, bBaseT + (uint32_t)((nt * 8 * BT_STR + kb) << 2));
                }
#pragma unroll
                for (int mt = 0; mt < 2; mt++) {
                    mma_bf16(d[mt][nt], aH[mt], b0h, b1h);
                    mma_bf16(d[mt][nt], aL[mt], b0h, b1h);
                    mma_bf16(d[mt][nt], aH[mt], b0l, b1l);
                }
            }
        }
    }

    // ---- epilogue ----
    const bool packK = (EPACK == 1 && h == 1);
    if (EPACK == 2 || packK) {
#pragma unroll
        for (int mt = 0; mt < 2; mt++) {
#pragma unroll
            for (int nt = 0; nt < 4; nt++) {
                int col = n0 + wn * 32 + nt * 8 + 2 * t;
                float b0 = bias ? bias[col] : 0.f;
                float b1 = bias ? bias[col + 1] : 0.f;
#pragma unroll
                for (int rr = 0; rr < 2; rr++) {
                    int row = m0 + wm * 32 + mt * 16 + g + 8 * rr;
                    if (row >= M) continue;
                    float v0 = d[mt][nt][2 * rr + 0] + b0;
                    float v1 = d[mt][nt][2 * rr + 1] + b1;
                    ll idx;
                    if (EPACK == 2) {
                        idx = (ll)row * 256 + (col >> 1);
                    } else {
                        int zk = ((row >> 10) << 3) + (col >> 6);
                        idx = ((ll)zk * 1024 + (row & 1023)) * 32 + ((col & 63) >> 1);
                    }
                    split_pack(v0, v1, Ph[idx], Pl[idx]);
                }
            }
        }
        return;
    }

    float* Cz = C + (ll)b * sCb + (ll)h * sCh;
#pragma unroll
    for (int mt = 0; mt < 2; mt++) {
        int row = m0 + wm * 32 + mt * 16 + g;
#pragma unroll
        for (int nt = 0; nt < 4; nt++) {
            int col = n0 + wn * 32 + nt * 8 + 2 * t;
            float b0 = (bias && col < N) ? bias[col] : 0.f;
            float b1 = (bias && col + 1 < N) ? bias[col + 1] : 0.f;
            if (row < M) {
                if (col < N)     Cz[(ll)row * ldc + col]     = d[mt][nt][0] + b0;
                if (col + 1 < N) Cz[(ll)row * ldc + col + 1] = d[mt][nt][1] + b1;
            }
            if (row + 8 < M) {
                if (col < N)     Cz[(ll)(row + 8) * ldc + col]     = d[mt][nt][2] + b0;
                if (col + 1 < N) Cz[(ll)(row + 8) * ldc + col + 1] = d[mt][nt][3] + b1;
            }
        }
    }
}

// ---------------- fused flash attention: bf16x2, ldmatrix fragments ----------------
#define PSTR 36
#define FL_SMEM (8 * 2304 * 4)

__global__ void __launch_bounds__(128, 3) flash_attn(
    const float* __restrict__ Q,
    const unsigned int* __restrict__ Kph, const unsigned int* __restrict__ Kpl,
    const unsigned int* __restrict__ VTh, const unsigned int* __restrict__ VTl,
    const float* __restrict__ pbu, const float* __restrict__ Rr,
    const unsigned int* __restrict__ mbits,
    unsigned int* __restrict__ Oph, unsigned int* __restrict__ Opl)
{
    extern __shared__ uint32_t smu[];

    const int z = blockIdx.y, b = z >> 3, h = z & 7;
    const int t0 = blockIdx.x * 64;
    const int tid = threadIdx.x, lane = tid & 31, w = tid >> 5;
    const int g = lane >> 2, t = lane & 3;
    const int grp = lane >> 3, gi = lane & 7;

    const float* Qb = Q + ((ll)(b * TT + t0)) * DM + h * DK;
    const ll rb = (ll)z * 512 * RSTR;

    uint32_t qh[4][4], ql[4][4];
    {
        const int r0 = w * 16 + g, r1 = r0 + 8;
#pragma unroll
        for (int ks = 0; ks < 4; ks++) {
#pragma unroll
            for (int half = 0; half < 2; half++) {
                int c = 16 * ks + 8 * half + 2 * t;
                float u0 = pbu[h * DK + c], u1 = pbu[h * DK + c + 1];
                float x0 = Qb[(ll)r0 * DM + c] + u0;
                float x1 = Qb[(ll)r0 * DM + c + 1] + u1;
                float y0 = Qb[(ll)r1 * DM + c] + u0;
                float y1 = Qb[(ll)r1 * DM + c + 1] + u1;
                split_pack(x0, x1, qh[ks][2 * half + 0], ql[ks][2 * half + 0]);
                split_pack(y0, y1, qh[ks][2 * half + 1], ql[ks][2 * half + 1]);
            }
        }
    }

    float o[8][4];
#pragma unroll
    for (int i = 0; i < 8; i++)
#pragma unroll
        for (int j = 0; j < 4; j++) o[i][j] = 0.f;
    float mx0 = -1e30f, mx1 = -1e30f, l0 = 0.f, l1 = 0.f;

    uint32_t sBase = (uint32_t)__cvta_generic_to_shared(smu);

    auto loadKV = [&](int st, int buf) {
        const unsigned int* kh = Kph + ((ll)z * 1024 + st * 64) * 32;
        const unsigned int* kl = Kpl + ((ll)z * 1024 + st * 64) * 32;
        const unsigned int* vh = VTh + (ll)z * 64 * 512 + st * 32;
        const unsigned int* vl = VTl + (ll)z * 64 * 512 + st * 32;
        uint32_t o0 = sBase + (uint32_t)(buf * 2304) * 4;
#pragma unroll
        for (int i = 0; i < 4; i++) {
            int idx = tid + 128 * i;
            int row = idx >> 3, c4 = (idx & 7) << 2;
            uint32_t soff = (uint32_t)(row * PSTR + c4) * 4;
            cp_async16(o0 + soff,                kh + (ll)row * 32 + c4, true);
            cp_async16(o0 + 2 * 2304 * 4 + soff, kl + (ll)row * 32 + c4, true);
            cp_async16(o0 + 4 * 2304 * 4 + soff, vh + (ll)row * 512 + c4, true);
            cp_async16(o0 + 6 * 2304 * 4 + soff, vl + (ll)row * 512 + c4, true);
        }
    };

    loadKV(0, 0);
    cp_commit();

    const int tg0 = t0 + w * 16 + g, tg1 = tg0 + 8;
    const float* R0 = Rr + rb + (ll)(tg0 >> 1) * RSTR;
    const float* R1 = Rr + rb + (ll)(tg1 >> 1) * RSTR;
    const int p0 = (tg0 & 1) << 10, p1 = (tg1 & 1) << 10;
    const uint2* mrow0 = (const uint2*)(mbits + ((ll)b * TT + tg0) * 32);
    const uint2* mrow1 = (const uint2*)(mbits + ((ll)b * TT + tg1) * 32);

    for (int st = 0; st < 16; st++) {
        const int buf = st & 1;
        cp_wait<0>();
        __syncthreads();
        if (st + 1 < 16) { loadKV(st + 1, 1 - buf); cp_commit(); }

        // ldmatrix per-lane bases: groups 0/1 -> hi array (+0/+4 pairs), 2/3 -> lo array
        const uint32_t kAddr = sBase +
            (uint32_t)((((grp < 2 ? buf : 2 + buf) * 2304) + gi * PSTR + ((grp & 1) << 2)) << 2);
        const uint32_t vAddr = sBase +
            (uint32_t)((((grp < 2 ? 4 + buf : 6 + buf) * 2304) + gi * PSTR + ((grp & 1) << 2)) << 2);

        float sc[8][4];
#pragma unroll
        for (int i = 0; i < 8; i++)
#pragma unroll
            for (int j = 0; j < 4; j++) sc[i][j] = 0.f;
#pragma unroll
        for (int nt = 0; nt < 8; nt++) {
#pragma unroll
            for (int ks = 0; ks < 4; ks++) {
                uint32_t b0h, b1h, b0l, b1l;
                ldsm_x4(b0h, b1h, b0l, b1l, kAddr + (uint32_t)((nt * 8 * PSTR + 8 * ks) << 2));
                mma_bf16(sc[nt], qh[ks], b0h, b1h);
                mma_bf16(sc[nt], ql[ks], b0h, b1h);
                mma_bf16(sc[nt], qh[ks], b0l, b1l);
            }
        }

        const int s0 = st * 64;
#pragma unroll
        for (int nt = 0; nt < 8; nt++) {
            int s_ = s0 + nt * 8 + 2 * t;
            int la = s_ + p0, lb = s_ + p1;
            float2 va = *(const float2*)(R0 + la);
            float2 vb = *(const float2*)(R1 + lb);
            float pa1 = (la + 1 == LL) ? 0.f : va.y;
            float pb1 = (lb + 1 == LL) ? 0.f : vb.y;
            sc[nt][0] = (sc[nt][0] + va.x) * 0.125f;
            sc[nt][1] = (sc[nt][1] + pa1) * 0.125f;
            sc[nt][2] = (sc[nt][2] + vb.x) * 0.125f;
            sc[nt][3] = (sc[nt][3] + pb1) * 0.125f;
        }
        {
            uint2 w0 = mrow0[st], w1 = mrow1[st];
            u64 m0 = (u64)w0.x | ((u64)w0.y << 32);
            u64 m1 = (u64)w1.x | ((u64)w1.y << 32);
            if (m0 | m1) {
#pragma unroll
                for (int nt = 0; nt < 8; nt++) {
                    int p = nt * 8 + 2 * t;
                    if ((m0 >> p) & 1)       sc[nt][0] = -1e9f;
                    if ((m0 >> (p + 1)) & 1) sc[nt][1] = -1e9f;
                    if ((m1 >> p) & 1)       sc[nt][2] = -1e9f;
                    if ((m1 >> (p + 1)) & 1) sc[nt][3] = -1e9f;
                }
            }
        }

        float rmx0 = -1e30f, rmx1 = -1e30f;
#pragma unroll
        for (int nt = 0; nt < 8; nt++) {
            rmx0 = fmaxf(rmx0, fmaxf(sc[nt][0], sc[nt][1]));
            rmx1 = fmaxf(rmx1, fmaxf(sc[nt][2], sc[nt][3]));
        }
        rmx0 = fmaxf(rmx0, __shfl_xor_sync(0xffffffffu, rmx0, 1));
        rmx0 = fmaxf(rmx0, __shfl_xor_sync(0xffffffffu, rmx0, 2));
        rmx1 = fmaxf(rmx1, __shfl_xor_sync(0xffffffffu, rmx1, 1));
        rmx1 = fmaxf(rmx1, __shfl_xor_sync(0xffffffffu, rmx1, 2));

        float mn0 = fmaxf(mx0, rmx0), mn1 = fmaxf(mx1, rmx1);
        float al0 = __expf(mx0 - mn0), al1 = __expf(mx1 - mn1);
        float rs0 = 0.f, rs1 = 0.f;
#pragma unroll
        for (int nt = 0; nt < 8; nt++) {
            sc[nt][0] = __expf(sc[nt][0] - mn0);
            sc[nt][1] = __expf(sc[nt][1] - mn0);
            sc[nt][2] = __expf(sc[nt][2] - mn1);
            sc[nt][3] = __expf(sc[nt][3] - mn1);
            rs0 += sc[nt][0] + sc[nt][1];
            rs1 += sc[nt][2] + sc[nt][3];
        }
        rs0 += __shfl_xor_sync(0xffffffffu, rs0, 1);
        rs0 += __shfl_xor_sync(0xffffffffu, rs0, 2);
        rs1 += __shfl_xor_sync(0xffffffffu, rs1, 1);
        rs1 += __shfl_xor_sync(0xffffffffu, rs1, 2);
        l0 = l0 * al0 + rs0;
        l1 = l1 * al1 + rs1;
        mx0 = mn0; mx1 = mn1;
#pragma unroll
        for (int dt = 0; dt < 8; dt++) {
            o[dt][0] *= al0; o[dt][1] *= al0;
            o[dt][2] *= al1; o[dt][3] *= al1;
        }

#pragma unroll
        for (int j = 0; j < 4; j++) {
            uint32_t aPh[4], aPl[4];
            split_pack(sc[2 * j][0],     sc[2 * j][1],     aPh[0], aPl[0]);
            split_pack(sc[2 * j][2],     sc[2 * j][3],     aPh[1], aPl[1]);
            split_pack(sc[2 * j + 1][0], sc[2 * j + 1][1], aPh[2], aPl[2]);
            split_pack(sc[2 * j + 1][2], sc[2 * j + 1][3], aPh[3], aPl[3]);
#pragma unroll
            for (int dt = 0; dt < 8; dt++) {
                uint32_t b0h, b1h, b0l, b1l;
                ldsm_x4(b0h, b1h, b0l, b1l, vAddr + (uint32_t)((dt * 8 * PSTR + 8 * j) << 2));
                mma_bf16(o[dt], aPh, b0h, b1h);
                mma_bf16(o[dt], aPl, b0h, b1h);
                mma_bf16(o[dt], aPh, b0l, b1l);
            }
        }
    }

    float inv0 = 1.f / l0, inv1 = 1.f / l1;
    ll base0 = ((ll)(b * TT + tg0)) * 256 + h * 32;
    ll base1 = ((ll)(b * TT + tg1)) * 256 + h * 32;
#pragma unroll
    for (int dt = 0; dt < 8; dt++) {
        int pj = dt * 4 + t;
        split_pack(o[dt][0] * inv0, o[dt][1] * inv0, Oph[base0 + pj], Opl[base0 + pj]);
        split_pack(o[dt][2] * inv1, o[dt][3] * inv1, Oph[base1 + pj], Opl[base1 + pj]);
    }
}

// ---------------- launch ----------------
extern "C" void kernel_launch(void* const* d_in, const int* in_sizes, int n_in,
                              void* d_out, int out_size)
{
    const float* x   = (const float*)d_in[0];
    const float* pos = (const float*)d_in[1];
    const unsigned char* mask = (const unsigned char*)d_in[2];
    const float* Wq = (const float*)d_in[3];  const float* bq = (const float*)d_in[4];
    const float* Wk = (const float*)d_in[5];  const float* bk = (const float*)d_in[6];
    const float* Wv = (const float*)d_in[7];  const float* bv = (const float*)d_in[8];
    const float* Wp = (const float*)d_in[9];  const float* bp = (const float*)d_in[10];
    const float* Wo = (const float*)d_in[11]; const float* bo = (const float*)d_in[12];
    const float* pbu = (const float*)d_in[13];
    const float* pbv = (const float*)d_in[14];
    float* out = (float*)d_out;

    float *QKV, *R;
    unsigned int *Mb, *Kph, *Kpl, *VTh, *VTl;
    unsigned int *xph, *xpl, *pph, *ppl, *Pph, *Ppl, *QRh, *QRl, *Oph, *Opl;
    unsigned int *Wqkvh, *Wqkvl, *Wph_, *Wpl_, *Woh, *Wol;
    cudaGetSymbolAddress((void**)&QKV, g_QKV);
    cudaGetSymbolAddress((void**)&R, g_R);
    cudaGetSymbolAddress((void**)&Mb, g_Mb);
    cudaGetSymbolAddress((void**)&Kph, g_Kph);
    cudaGetSymbolAddress((void**)&Kpl, g_Kpl);
    cudaGetSymbolAddress((void**)&VTh, g_VTh);
    cudaGetSymbolAddress((void**)&VTl, g_VTl);
    cudaGetSymbolAddress((void**)&xph, g_xph);
    cudaGetSymbolAddress((void**)&xpl, g_xpl);
    cudaGetSymbolAddress((void**)&pph, g_pph);
    cudaGetSymbolAddress((void**)&ppl, g_ppl);
    cudaGetSymbolAddress((void**)&Pph, g_Pph);
    cudaGetSymbolAddress((void**)&Ppl, g_Ppl);
    cudaGetSymbolAddress((void**)&QRh, g_QRh);
    cudaGetSymbolAddress((void**)&QRl, g_QRl);
    cudaGetSymbolAddress((void**)&Oph, g_Oph);
    cudaGetSymbolAddress((void**)&Opl, g_Opl);
    cudaGetSymbolAddress((void**)&Wqkvh, g_Wqkvh);
    cudaGetSymbolAddress((void**)&Wqkvl, g_Wqkvl);
    cudaGetSymbolAddress((void**)&Wph_, g_Wph);
    cudaGetSymbolAddress((void**)&Wpl_, g_Wpl);
    cudaGetSymbolAddress((void**)&Woh, g_Woh);
    cudaGetSymbolAddress((void**)&Wol, g_Wol);

    cudaFuncSetAttribute((const void*)bf16_gemm<0, 0>, cudaFuncAttributeMaxDynamicSharedMemorySize, G2_SMEM);
    cudaFuncSetAttribute((const void*)bf16_gemm<0, 1>, cudaFuncAttributeMaxDynamicSharedMemorySize, G2_SMEM);
    cudaFuncSetAttribute((const void*)bf16_gemm<0, 2>, cudaFuncAttributeMaxDynamicSharedMemorySize, G2_SMEM);
    cudaFuncSetAttribute((const void*)bf16_gemm<1, 0>, cudaFuncAttributeMaxDynamicSharedMemorySize, G2_SMEM);
    cudaFuncSetAttribute((const void*)flash_attn, cudaFuncAttributeMaxDynamicSharedMemorySize, FL_SMEM);

    dim3 blk(256);

    // 1) all independent packs
    megapack1<<<dim3(4096, 1, 8), blk>>>(
        x, pos, mask, Wq, Wk, Wv, Wp, Wo,
        Wqkvh, Wqkvl, Wph_, Wpl_, Woh, Wol, xph, xpl, pph, ppl, Mb);

    // 2) fused Q/K/V projection; K slab (h==1) emits packed pairs directly
    bf16_gemm<0, 1><<<dim3(8, 32, 3), blk, G2_SMEM>>>(
        xph, xpl, 256, 0, 0,
        Wqkvh, Wqkvl, 512, 0, 131072,
        QKV, DM, 0, 2097152,
        NB * TT, DM, 256, bq, bk, bv, Kph, Kpl);

    // 3) P projection -> packed Pph/Ppl directly
    bf16_gemm<0, 2><<<dim3(8, 16, 1), blk, G2_SMEM>>>(
        pph, ppl, 256, 0, 0, Wph_, Wpl_, 512, 0, 0,
        nullptr, DM, 0, 0, LL, DM, 256, bp, bp, bp, Pph, Ppl);

    // 4) dependent packs (V transpose-pack + QR pack)
    megapack2<<<dim3(2048, 1, 2), blk>>>(QKV, pbv, VTh, VTl, QRh, QRl);

    // 5) R = (Q[512:]+pbv) @ P^T per (b,h)
    bf16_gemm<1, 0><<<dim3(32, 4, 32), blk, G2_SMEM>>>(
        QRh, QRl, 32, 8LL * 512 * 32, 512 * 32,
        Pph, Ppl, 256, 0, 32,
        R, RSTR, 8LL * 512 * RSTR, (ll)512 * RSTR,
        512, LL, 32, nullptr, nullptr, nullptr, nullptr, nullptr);

    // 6) flash attention
    flash_attn<<<dim3(16, 32), dim3(128), FL_SMEM>>>(
        QKV, Kph, Kpl, VTh, VTl, pbu, R, Mb, Oph, Opl);

    // 7) out = O @ Wo + bo
    bf16_gemm<0, 0><<<dim3(8, 32, 1), blk, G2_SMEM>>>(
        Oph, Opl, 256, 0, 0, Woh, Wol, 512, 0, 0,
        out, DM, 0, 0, NB * TT, DM, 256, bo, bo, bo, nullptr, nullptr);
}

// round 12
// speedup vs baseline: 2.0769x; 1.0432x over previous
#include <cuda_runtime.h>
#include <cuda_bf16.h>
#include <cuda_fp16.h>
#include <cstdint>

#define TT 1024
#define DM 512
#define NB 4
#define NH 8
#define DK 64
#define LL 2047   // 2*T - 1
#define RSTR 2048
typedef long long ll;
typedef unsigned long long u64;

// ---------------- scratch ----------------
__device__ float g_QKV[3LL * NB * TT * DM];     // Q | (K unused) | V
__device__ float g_R[32LL * 512 * RSTR];
__device__ unsigned int g_Mb[NB * TT * 32];
__device__ unsigned int g_Kph[32LL * 1024 * 32];
__device__ unsigned int g_Kpl[32LL * 1024 * 32];
__device__ unsigned int g_VTh[32LL * 64 * 512];   // fp16x2 pairs along s
__device__ unsigned int g_xph[NB * TT * 256],  g_xpl[NB * TT * 256];
__device__ unsigned int g_pph[2047 * 256],     g_ppl[2047 * 256];
__device__ unsigned int g_Wqkvh[3 * 256 * 512], g_Wqkvl[3 * 256 * 512];
__device__ unsigned int g_Wph[256 * 512], g_Wpl[256 * 512];
__device__ unsigned int g_Woh[256 * 512], g_Wol[256 * 512];
__device__ unsigned int g_Pph[2047 * 256], g_Ppl[2047 * 256];
__device__ unsigned int g_QRh[32LL * 512 * 32], g_QRl[32LL * 512 * 32];
__device__ unsigned int g_Oph[NB * TT * 256], g_Opl[NB * TT * 256];

// ---------------- helpers ----------------
__device__ __forceinline__ float bf16_hi(float x) {
    return __bfloat162float(__float2bfloat16(x));
}
__device__ __forceinline__ uint32_t pack_bf16(float lo_elem, float hi_elem) {
    uint32_t r;
    asm("cvt.rn.bf16x2.f32 %0, %1, %2;" : "=r"(r) : "f"(hi_elem), "f"(lo_elem));
    return r;
}
__device__ __forceinline__ void split_pack(float a, float b, uint32_t& ph, uint32_t& pl) {
    float ha = bf16_hi(a), hb = bf16_hi(b);
    ph = pack_bf16(a, b);
    pl = pack_bf16(a - ha, b - hb);
}
__device__ __forceinline__ float f16_hi(float x) {
    return __half2float(__float2half_rn(x));
}
__device__ __forceinline__ uint32_t pack_f16(float lo_elem, float hi_elem) {
    uint32_t r;
    asm("cvt.rn.f16x2.f32 %0, %1, %2;" : "=r"(r) : "f"(hi_elem), "f"(lo_elem));
    return r;
}
__device__ __forceinline__ void split_pack_f16(float a, float b, uint32_t& ph, uint32_t& pl) {
    float ha = f16_hi(a), hb = f16_hi(b);
    ph = pack_f16(a, b);
    pl = pack_f16(a - ha, b - hb);
}
__device__ __forceinline__ void mma_bf16(float* d, const uint32_t* a, uint32_t b0, uint32_t b1) {
    asm volatile(
        "mma.sync.aligned.m16n8k16.row.col.f32.bf16.bf16.f32 "
        "{%0,%1,%2,%3}, {%4,%5,%6,%7}, {%8,%9}, {%0,%1,%2,%3};\n"
        : "+f"(d[0]), "+f"(d[1]), "+f"(d[2]), "+f"(d[3])
        : "r"(a[0]), "r"(a[1]), "r"(a[2]), "r"(a[3]), "r"(b0), "r"(b1));
}
__device__ __forceinline__ void mma_f16(float* d, const uint32_t* a, uint32_t b0, uint32_t b1) {
    asm volatile(
        "mma.sync.aligned.m16n8k16.row.col.f32.f16.f16.f32 "
        "{%0,%1,%2,%3}, {%4,%5,%6,%7}, {%8,%9}, {%0,%1,%2,%3};\n"
        : "+f"(d[0]), "+f"(d[1]), "+f"(d[2]), "+f"(d[3])
        : "r"(a[0]), "r"(a[1]), "r"(a[2]), "r"(a[3]), "r"(b0), "r"(b1));
}
__device__ __forceinline__ void ldsm_x4(uint32_t& r0, uint32_t& r1, uint32_t& r2, uint32_t& r3,
                                        uint32_t addr) {
    asm volatile("ldmatrix.sync.aligned.m8n8.x4.shared.b16 {%0,%1,%2,%3}, [%4];\n"
                 : "=r"(r0), "=r"(r1), "=r"(r2), "=r"(r3) : "r"(addr));
}
__device__ __forceinline__ void cp_async16(uint32_t dst, const void* src, bool p) {
    asm volatile("cp.async.cg.shared.global [%0], [%1], 16, %2;\n"
                 :: "r"(dst), "l"(src), "r"(p ? 16 : 0));
}
__device__ __forceinline__ void cp_commit() { asm volatile("cp.async.commit_group;\n"); }
template <int N>
__device__ __forceinline__ void cp_wait() { asm volatile("cp.async.wait_group %0;\n" :: "n"(N)); }

// ---------------- mega-pack 1: all input-only packs, grid (4096,1,8) ----------------
__global__ void __launch_bounds__(256) megapack1(
    const float* __restrict__ x, const float* __restrict__ pos,
    const unsigned char* __restrict__ mask,
    const float* __restrict__ Wq, const float* __restrict__ Wk,
    const float* __restrict__ Wv, const float* __restrict__ Wp,
    const float* __restrict__ Wo,
    unsigned int* __restrict__ Wqkvh, unsigned int* __restrict__ Wqkvl,
    unsigned int* __restrict__ Wph, unsigned int* __restrict__ Wpl,
    unsigned int* __restrict__ Woh, unsigned int* __restrict__ Wol,
    unsigned int* __restrict__ xph, unsigned int* __restrict__ xpl,
    unsigned int* __restrict__ pph, unsigned int* __restrict__ ppl,
    unsigned int* __restrict__ Mb)
{
    const int zz = blockIdx.z, bx = blockIdx.x, tid = threadIdx.x;
    if (zz < 5) {
        if (bx >= 512) return;
        int i = bx * 256 + tid;
        int r = i >> 9, n = i & 511;
        const float* W = zz == 0 ? Wq : zz == 1 ? Wk : zz == 2 ? Wv : zz == 3 ? Wp : Wo;
        unsigned int *ph, *pl;
        if (zz < 3)      { ph = Wqkvh + zz * 131072; pl = Wqkvl + zz * 131072; }
        else if (zz == 3){ ph = Wph; pl = Wpl; }
        else             { ph = Woh; pl = Wol; }
        split_pack(W[(2 * r) * 512 + n], W[(2 * r + 1) * 512 + n], ph[i], pl[i]);
    } else if (zz == 5) {
        ll i = (ll)bx * 256 + tid;
        float2 v = *(const float2*)(x + 2 * i);
        split_pack(v.x, v.y, xph[i], xpl[i]);
    } else if (zz == 6) {
        if (bx >= 2047) return;
        ll i = (ll)bx * 256 + tid;
        float2 v = *(const float2*)(pos + 2 * i);
        split_pack(v.x, v.y, pph[i], ppl[i]);
    } else {
        if (bx >= 512) return;
        int i = bx * 256 + tid;
        const uchar4* p = (const uchar4*)(mask + (ll)i * 32);
        unsigned int bits = 0;
#pragma unroll
        for (int j = 0; j < 8; j++) {
            uchar4 v = p[j];
            unsigned int q = (v.x ? 1u : 0u) | (v.y ? 2u : 0u) | (v.z ? 4u : 0u) | (v.w ? 8u : 0u);
            bits |= q << (4 * j);
        }
        Mb[i] = bits;
    }
}

// ---------------- V transpose-pack (fp16), grid (512,1,1) ----------------
__global__ void __launch_bounds__(256) vt_pack(
    const float* __restrict__ QKV, unsigned int* __restrict__ VTh)
{
    __shared__ float sv[64][65];
    const int bx = blockIdx.x, tid = threadIdx.x;
    const int z = bx >> 4, b = z >> 3, h = z & 7;
    const int s0 = (bx & 15) * 64;
    const int row = tid >> 2, cq = (tid & 3) << 4;
    const float* Vf = QKV + 4194304;
    {
        const float* vr = Vf + ((ll)(b * TT + s0 + row)) * DM + h * DK + cq;
#pragma unroll
        for (int i = 0; i < 4; i++) {
            float4 f = *(const float4*)(vr + 4 * i);
            sv[row][cq + 4 * i] = f.x; sv[row][cq + 4 * i + 1] = f.y;
            sv[row][cq + 4 * i + 2] = f.z; sv[row][cq + 4 * i + 3] = f.w;
        }
    }
    __syncthreads();
    {
        const int d = tid >> 2, sq = (tid & 3) << 4;
        ll base = ((ll)z * 64 + d) * 512 + ((s0 + sq) >> 1);
#pragma unroll
        for (int j = 0; j < 8; j++)
            VTh[base + j] = pack_f16(sv[sq + 2 * j][d], sv[sq + 2 * j + 1][d]);
    }
}

// ---------------- bf16x2 pipelined GEMM (ldmatrix fragments) ----------------
// EPACK=0: fp32 C. EPACK=1: h==1 emits packed K; h==0 fp32 + QR pack (rows>=512). EPACK=2: packed P.
#define A_STR 20
#define BN_STR 72
#define BT_STR 20
#define G2_SMEM ((4 * 2560 + 4 * 1280) * 4)

template <int TRANSB, int EPACK>
__global__ void __launch_bounds__(256) bf16_gemm(
    const unsigned int* __restrict__ Aph, const unsigned int* __restrict__ Apl,
    int ldap, ll sAb, ll sAh,
    const unsigned int* __restrict__ Bph, const unsigned int* __restrict__ Bpl,
    int ldbp, ll sBb, ll sBh,
    float* __restrict__ C, int ldc, ll sCb, ll sCh,
    int M, int N, int Kp,
    const float* __restrict__ bias0, const float* __restrict__ bias1,
    const float* __restrict__ bias2,
    unsigned int* __restrict__ Ph, unsigned int* __restrict__ Pl,
    const float* __restrict__ pbv,
    unsigned int* __restrict__ QRh, unsigned int* __restrict__ QRl)
{
    extern __shared__ uint32_t su[];
    uint32_t* BH = su + 10240;
    uint32_t* BLo = su + 12800;

    const int z = blockIdx.z, b = z >> 3, h = z & 7;
    const float* bias = (h == 0) ? bias0 : (h == 1) ? bias1 : bias2;
    Aph += (ll)b * sAb + (ll)h * sAh;
    Apl += (ll)b * sAb + (ll)h * sAh;
    Bph += (ll)b * sBb + (ll)h * sBh;
    Bpl += (ll)b * sBb + (ll)h * sBh;

    const int tid = threadIdx.x;
    const int lane = tid & 31, wid = tid >> 5;
    const int g = lane >> 2, t = lane & 3;
    const int grp = lane >> 3, gi = lane & 7;
    const int wm = wid & 3, wn = wid >> 2;
    const int m0 = blockIdx.y * 128, n0 = blockIdx.x * 64;

    uint32_t sBase = (uint32_t)__cvta_generic_to_shared(su);

    auto stage = [&](int k0p, int stg) {
#pragma unroll
        for (int i = 0; i < 2; i++) {
            int idx = tid + 256 * i;
            int row = idx >> 2, c4 = (idx & 3) << 2;
            bool p = (m0 + row) < M;
            const ll off = (ll)(m0 + row) * ldap + k0p + c4;
            uint32_t d0 = sBase + (uint32_t)(stg * 2560 + row * A_STR + c4) * 4;
            cp_async16(d0, Aph + off, p);
            cp_async16(d0 + 5120 * 4, Apl + off, p);
        }
        if (!TRANSB) {
            int row = tid >> 4, c4 = (tid & 15) << 2;
            const ll off = (ll)(k0p + row) * ldbp + n0 + c4;
            uint32_t d0 = sBase + (uint32_t)(10240 + stg * 1280 + row * BN_STR + c4) * 4;
            cp_async16(d0, Bph + off, true);
            cp_async16(d0 + 2560 * 4, Bpl + off, true);
        } else {
            int row = tid >> 2, c4 = (tid & 3) << 2;
            bool p = (n0 + row) < N;
            const ll off = (ll)(n0 + row) * ldbp + k0p + c4;
            uint32_t d0 = sBase + (uint32_t)(10240 + stg * 1280 + row * BT_STR + c4) * 4;
            cp_async16(d0, Bph + off, p);
            cp_async16(d0 + 2560 * 4, Bpl + off, p);
        }
    };

    float d[2][4][4];
#pragma unroll
    for (int i = 0; i < 2; i++)
#pragma unroll
        for (int j = 0; j < 4; j++)
#pragma unroll
            for (int c = 0; c < 4; c++) d[i][j][c] = 0.f;

    const int nIter = Kp >> 4;
    stage(0, 0);
    cp_commit();

    for (int it = 0; it < nIter; it++) {
        __syncthreads();
        if (it + 1 < nIter) { stage((it + 1) << 4, (it + 1) & 1); cp_commit(); cp_wait<1>(); }
        else cp_wait<0>();
        __syncthreads();

        const uint32_t aBaseH = sBase +
            (uint32_t)(((it & 1) * 2560 + (wm * 32 + ((grp & 1) << 3) + gi) * A_STR + ((grp >> 1) << 2)) << 2);
        const uint32_t aBaseL = aBaseH + (5120u << 2);
        uint32_t bBaseT = 0;
        if (TRANSB)
            bBaseT = sBase + (uint32_t)((10240 + (grp < 2 ? 0 : 2560) + (it & 1) * 1280 +
                                         (wn * 32 + gi) * BT_STR + ((grp & 1) << 2)) << 2);
        const uint32_t* pBH = BH + (it & 1) * 1280;
        const uint32_t* pBL = BLo + (it & 1) * 1280;

#pragma unroll
        for (int ck = 0; ck < 2; ck++) {
            const int kb = ck * 8;
            uint32_t aH[2][4], aL[2][4];
#pragma unroll
            for (int mt = 0; mt < 2; mt++) {
                uint32_t off = (uint32_t)((mt * 16 * A_STR + kb) << 2);
                ldsm_x4(aH[mt][0], aH[mt][1], aH[mt][2], aH[mt][3], aBaseH + off);
                ldsm_x4(aL[mt][0], aL[mt][1], aL[mt][2], aL[mt][3], aBaseL + off);
            }
#pragma unroll
            for (int nt = 0; nt < 4; nt++) {
                uint32_t b0h, b1h, b0l, b1l;
                if (!TRANSB) {
                    int col = wn * 32 + nt * 8 + g;
                    int i0 = (kb + t) * BN_STR + col, i1 = (kb + t + 4) * BN_STR + col;
                    b0h = pBH[i0]; b1h = pBH[i1];
                    b0l = pBL[i0]; b1l = pBL[i1];
                } else {
                    ldsm_x4(b0h, b1h, b0l, b1l, bBaseT + (uint32_t)((nt * 8 * BT_STR + kb) << 2));
                }
#pragma unroll
                for (int mt = 0; mt < 2; mt++) {
                    mma_bf16(d[mt][nt], aH[mt], b0h, b1h);
                    mma_bf16(d[mt][nt], aL[mt], b0h, b1h);
                    mma_bf16(d[mt][nt], aH[mt], b0l, b1l);
                }
            }
        }
    }

    // ---- epilogue ----
    const bool packK = (EPACK == 1 && h == 1);
    if (EPACK == 2 || packK) {
#pragma unroll
        for (int mt = 0; mt < 2; mt++) {
#pragma unroll
            for (int nt = 0; nt < 4; nt++) {
                int col = n0 + wn * 32 + nt * 8 + 2 * t;
                float b0 = bias ? bias[col] : 0.f;
                float b1 = bias ? bias[col + 1] : 0.f;
#pragma unroll
                for (int rr = 0; rr < 2; rr++) {
                    int row = m0 + wm * 32 + mt * 16 + g + 8 * rr;
                    if (row >= M) continue;
                    float v0 = d[mt][nt][2 * rr + 0] + b0;
                    float v1 = d[mt][nt][2 * rr + 1] + b1;
                    ll idx;
                    if (EPACK == 2) {
                        idx = (ll)row * 256 + (col >> 1);
                    } else {
                        int zk = ((row >> 10) << 3) + (col >> 6);
                        idx = ((ll)zk * 1024 + (row & 1023)) * 32 + ((col & 63) >> 1);
                    }
                    split_pack(v0, v1, Ph[idx], Pl[idx]);
                }
            }
        }
        return;
    }

    float* Cz = C + (ll)b * sCb + (ll)h * sCh;
#pragma unroll
    for (int mt = 0; mt < 2; mt++) {
#pragma unroll
        for (int nt = 0; nt < 4; nt++) {
            int col = n0 + wn * 32 + nt * 8 + 2 * t;
            float b0 = (bias && col < N) ? bias[col] : 0.f;
            float b1 = (bias && col + 1 < N) ? bias[col + 1] : 0.f;
#pragma unroll
            for (int rr = 0; rr < 2; rr++) {
                int row = m0 + wm * 32 + mt * 16 + g + 8 * rr;
                if (row >= M) continue;
                float v0 = d[mt][nt][2 * rr + 0] + b0;
                float v1 = d[mt][nt][2 * rr + 1] + b1;
                if (col < N)     Cz[(ll)row * ldc + col]     = v0;
                if (col + 1 < N) Cz[(ll)row * ldc + col + 1] = v1;
                if (EPACK == 1 && h == 0) {
                    int tloc = row & 1023;
                    if (tloc >= 512) {
                        int zq = ((row >> 10) << 3) + (col >> 6);
                        ll qi = ((ll)zq * 512 + (tloc - 512)) * 32 + ((col & 63) >> 1);
                        split_pack(v0 + pbv[col], v1 + pbv[col + 1], QRh[qi], QRl[qi]);
                    }
                }
            }
        }
    }
}

// ---------------- fused flash attention: bf16x2 QK (3-term), fp16 PV (2-term) ----------------
#define PSTR 36
#define FL_SMEM (6 * 2304 * 4)   // KH[2], KL[2], VH[2]

__global__ void __launch_bounds__(128, 3) flash_attn(
    const float* __restrict__ Q,
    const unsigned int* __restrict__ Kph, const unsigned int* __restrict__ Kpl,
    const unsigned int* __restrict__ VTh,
    const float* __restrict__ pbu, const float* __restrict__ Rr,
    const unsigned int* __restrict__ mbits,
    unsigned int* __restrict__ Oph, unsigned int* __restrict__ Opl)
{
    extern __shared__ uint32_t smu[];
    uint32_t* VH = smu + 4 * 2304;

    const int z = blockIdx.y, b = z >> 3, h = z & 7;
    const int t0 = blockIdx.x * 64;
    const int tid = threadIdx.x, lane = tid & 31, w = tid >> 5;
    const int g = lane >> 2, t = lane & 3;
    const int grp = lane >> 3, gi = lane & 7;

    const float* Qb = Q + ((ll)(b * TT + t0)) * DM + h * DK;
    const ll rb = (ll)z * 512 * RSTR;

    uint32_t qh[4][4], ql[4][4];
    {
        const int r0 = w * 16 + g, r1 = r0 + 8;
#pragma unroll
        for (int ks = 0; ks < 4; ks++) {
#pragma unroll
            for (int half = 0; half < 2; half++) {
                int c = 16 * ks + 8 * half + 2 * t;
                float u0 = pbu[h * DK + c], u1 = pbu[h * DK + c + 1];
                float x0 = Qb[(ll)r0 * DM + c] + u0;
                float x1 = Qb[(ll)r0 * DM + c + 1] + u1;
                float y0 = Qb[(ll)r1 * DM + c] + u0;
                float y1 = Qb[(ll)r1 * DM + c + 1] + u1;
                split_pack(x0, x1, qh[ks][2 * half + 0], ql[ks][2 * half + 0]);
                split_pack(y0, y1, qh[ks][2 * half + 1], ql[ks][2 * half + 1]);
            }
        }
    }

    float o[8][4];
#pragma unroll
    for (int i = 0; i < 8; i++)
#pragma unroll
        for (int j = 0; j < 4; j++) o[i][j] = 0.f;
    float mx0 = -1e30f, mx1 = -1e30f, l0 = 0.f, l1 = 0.f;

    uint32_t sBase = (uint32_t)__cvta_generic_to_shared(smu);

    auto loadKV = [&](int st, int buf) {
        const unsigned int* kh = Kph + ((ll)z * 1024 + st * 64) * 32;
        const unsigned int* kl = Kpl + ((ll)z * 1024 + st * 64) * 32;
        const unsigned int* vh = VTh + (ll)z * 64 * 512 + st * 32;
        uint32_t o0 = sBase + (uint32_t)(buf * 2304) * 4;
#pragma unroll
        for (int i = 0; i < 4; i++) {
            int idx = tid + 128 * i;
            int row = idx >> 3, c4 = (idx & 7) << 2;
            uint32_t soff = (uint32_t)(row * PSTR + c4) * 4;
            cp_async16(o0 + soff,                kh + (ll)row * 32 + c4, true);
            cp_async16(o0 + 2 * 2304 * 4 + soff, kl + (ll)row * 32 + c4, true);
            cp_async16(o0 + 4 * 2304 * 4 + soff, vh + (ll)row * 512 + c4, true);
        }
    };

    loadKV(0, 0);
    cp_commit();

    const int tg0 = t0 + w * 16 + g, tg1 = tg0 + 8;
    const float* R0 = Rr + rb + (ll)(tg0 >> 1) * RSTR;
    const float* R1 = Rr + rb + (ll)(tg1 >> 1) * RSTR;
    const int p0 = (tg0 & 1) << 10, p1 = (tg1 & 1) << 10;
    const uint2* mrow0 = (const uint2*)(mbits + ((ll)b * TT + tg0) * 32);
    const uint2* mrow1 = (const uint2*)(mbits + ((ll)b * TT + tg1) * 32);

    for (int st = 0; st < 16; st++) {
        const int buf = st & 1;
        cp_wait<0>();
        __syncthreads();
        if (st + 1 < 16) { loadKV(st + 1, 1 - buf); cp_commit(); }

        const uint32_t kAddr = sBase +
            (uint32_t)((((grp < 2 ? buf : 2 + buf) * 2304) + gi * PSTR + ((grp & 1) << 2)) << 2);
        const uint32_t* pVH = VH + buf * 2304;

        float sc[8][4];
#pragma unroll
        for (int i = 0; i < 8; i++)
#pragma unroll
            for (int j = 0; j < 4; j++) sc[i][j] = 0.f;
#pragma unroll
        for (int nt = 0; nt < 8; nt++) {
#pragma unroll
            for (int ks = 0; ks < 4; ks++) {
                uint32_t b0h, b1h, b0l, b1l;
                ldsm_x4(b0h, b1h, b0l, b1l, kAddr + (uint32_t)((nt * 8 * PSTR + 8 * ks) << 2));
                mma_bf16(sc[nt], qh[ks], b0h, b1h);
                mma_bf16(sc[nt], ql[ks], b0h, b1h);
                mma_bf16(sc[nt], qh[ks], b0l, b1l);
            }
        }

        const int s0 = st * 64;
#pragma unroll
        for (int nt = 0; nt < 8; nt++) {
            int s_ = s0 + nt * 8 + 2 * t;
            int la = s_ + p0, lb = s_ + p1;
            float2 va = *(const float2*)(R0 + la);
            float2 vb = *(const float2*)(R1 + lb);
            float pa1 = (la + 1 == LL) ? 0.f : va.y;
            float pb1 = (lb + 1 == LL) ? 0.f : vb.y;
            sc[nt][0] = (sc[nt][0] + va.x) * 0.125f;
            sc[nt][1] = (sc[nt][1] + pa1) * 0.125f;
            sc[nt][2] = (sc[nt][2] + vb.x) * 0.125f;
            sc[nt][3] = (sc[nt][3] + pb1) * 0.125f;
        }
        {
            uint2 w0 = mrow0[st], w1 = mrow1[st];
            u64 m0 = (u64)w0.x | ((u64)w0.y << 32);
            u64 m1 = (u64)w1.x | ((u64)w1.y << 32);
            if (m0 | m1) {
#pragma unroll
                for (int nt = 0; nt < 8; nt++) {
                    int p = nt * 8 + 2 * t;
                    if ((m0 >> p) & 1)       sc[nt][0] = -1e9f;
                    if ((m0 >> (p + 1)) & 1) sc[nt][1] = -1e9f;
                    if ((m1 >> p) & 1)       sc[nt][2] = -1e9f;
                    if ((m1 >> (p + 1)) & 1) sc[nt][3] = -1e9f;
                }
            }
        }

        float rmx0 = -1e30f, rmx1 = -1e30f;
#pragma unroll
        for (int nt = 0; nt < 8; nt++) {
            rmx0 = fmaxf(rmx0, fmaxf(sc[nt][0], sc[nt][1]));
            rmx1 = fmaxf(rmx1, fmaxf(sc[nt][2], sc[nt][3]));
        }
        rmx0 = fmaxf(rmx0, __shfl_xor_sync(0xffffffffu, rmx0, 1));
        rmx0 = fmaxf(rmx0, __shfl_xor_sync(0xffffffffu, rmx0, 2));
        rmx1 = fmaxf(rmx1, __shfl_xor_sync(0xffffffffu, rmx1, 1));
        rmx1 = fmaxf(rmx1, __shfl_xor_sync(0xffffffffu, rmx1, 2));

        float mn0 = fmaxf(mx0, rmx0), mn1 = fmaxf(mx1, rmx1);
        float al0 = __expf(mx0 - mn0), al1 = __expf(mx1 - mn1);
        float rs0 = 0.f, rs1 = 0.f;
#pragma unroll
        for (int nt = 0; nt < 8; nt++) {
            sc[nt][0] = __expf(sc[nt][0] - mn0);
            sc[nt][1] = __expf(sc[nt][1] - mn0);
            sc[nt][2] = __expf(sc[nt][2] - mn1);
            sc[nt][3] = __expf(sc[nt][3] - mn1);
            rs0 += sc[nt][0] + sc[nt][1];
            rs1 += sc[nt][2] + sc[nt][3];
        }
        rs0 += __shfl_xor_sync(0xffffffffu, rs0, 1);
        rs0 += __shfl_xor_sync(0xffffffffu, rs0, 2);
        rs1 += __shfl_xor_sync(0xffffffffu, rs1, 1);
        rs1 += __shfl_xor_sync(0xffffffffu, rs1, 2);
        l0 = l0 * al0 + rs0;
        l1 = l1 * al1 + rs1;
        mx0 = mn0; mx1 = mn1;
#pragma unroll
        for (int dt = 0; dt < 8; dt++) {
            o[dt][0] *= al0; o[dt][1] *= al0;
            o[dt][2] *= al1; o[dt][3] *= al1;
        }

        // ---- O += P @ V : fp16 2-term (P split hi/lo, V single fp16) ----
#pragma unroll
        for (int j = 0; j < 4; j++) {
            uint32_t aPh[4], aPl[4];
            split_pack_f16(sc[2 * j][0],     sc[2 * j][1],     aPh[0], aPl[0]);
            split_pack_f16(sc[2 * j][2],     sc[2 * j][3],     aPh[1], aPl[1]);
            split_pack_f16(sc[2 * j + 1][0], sc[2 * j + 1][1], aPh[2], aPl[2]);
            split_pack_f16(sc[2 * j + 1][2], sc[2 * j + 1][3], aPh[3], aPl[3]);
#pragma unroll
            for (int dt = 0; dt < 8; dt++) {
                const int vrow = (dt * 8 + g) * PSTR;
                uint32_t b0h = pVH[vrow + 8 * j + t];
                uint32_t b1h = pVH[vrow + 8 * j + 4 + t];
                mma_f16(o[dt], aPh, b0h, b1h);
                mma_f16(o[dt], aPl, b0h, b1h);
            }
        }
    }

    float inv0 = 1.f / l0, inv1 = 1.f / l1;
    ll base0 = ((ll)(b * TT + tg0)) * 256 + h * 32;
    ll base1 = ((ll)(b * TT + tg1)) * 256 + h * 32;
#pragma unroll
    for (int dt = 0; dt < 8; dt++) {
        int pj = dt * 4 + t;
        split_pack(o[dt][0] * inv0, o[dt][1] * inv0, Oph[base0 + pj], Opl[base0 + pj]);
        split_pack(o[dt][2] * inv1, o[dt][3] * inv1, Oph[base1 + pj], Opl[base1 + pj]);
    }
}

// ---------------- launch ----------------
extern "C" void kernel_launch(void* const* d_in, const int* in_sizes, int n_in,
                              void* d_out, int out_size)
{
    const float* x   = (const float*)d_in[0];
    const float* pos = (const float*)d_in[1];
    const unsigned char* mask = (const unsigned char*)d_in[2];
    const float* Wq = (const float*)d_in[3];  const float* bq = (const float*)d_in[4];
    const float* Wk = (const float*)d_in[5];  const float* bk = (const float*)d_in[6];
    const float* Wv = (const float*)d_in[7];  const float* bv = (const float*)d_in[8];
    const float* Wp = (const float*)d_in[9];  const float* bp = (const float*)d_in[10];
    const float* Wo = (const float*)d_in[11]; const float* bo = (const float*)d_in[12];
    const float* pbu = (const float*)d_in[13];
    const float* pbv = (const float*)d_in[14];
    float* out = (float*)d_out;

    float *QKV, *R;
    unsigned int *Mb, *Kph, *Kpl, *VTh;
    unsigned int *xph, *xpl, *pph, *ppl, *Pph, *Ppl, *QRh, *QRl, *Oph, *Opl;
    unsigned int *Wqkvh, *Wqkvl, *Wph_, *Wpl_, *Woh, *Wol;
    cudaGetSymbolAddress((void**)&QKV, g_QKV);
    cudaGetSymbolAddress((void**)&R, g_R);
    cudaGetSymbolAddress((void**)&Mb, g_Mb);
    cudaGetSymbolAddress((void**)&Kph, g_Kph);
    cudaGetSymbolAddress((void**)&Kpl, g_Kpl);
    cudaGetSymbolAddress((void**)&VTh, g_VTh);
    cudaGetSymbolAddress((void**)&xph, g_xph);
    cudaGetSymbolAddress((void**)&xpl, g_xpl);
    cudaGetSymbolAddress((void**)&pph, g_pph);
    cudaGetSymbolAddress((void**)&ppl, g_ppl);
    cudaGetSymbolAddress((void**)&Pph, g_Pph);
    cudaGetSymbolAddress((void**)&Ppl, g_Ppl);
    cudaGetSymbolAddress((void**)&QRh, g_QRh);
    cudaGetSymbolAddress((void**)&QRl, g_QRl);
    cudaGetSymbolAddress((void**)&Oph, g_Oph);
    cudaGetSymbolAddress((void**)&Opl, g_Opl);
    cudaGetSymbolAddress((void**)&Wqkvh, g_Wqkvh);
    cudaGetSymbolAddress((void**)&Wqkvl, g_Wqkvl);
    cudaGetSymbolAddress((void**)&Wph_, g_Wph);
    cudaGetSymbolAddress((void**)&Wpl_, g_Wpl);
    cudaGetSymbolAddress((void**)&Woh, g_Woh);
    cudaGetSymbolAddress((void**)&Wol, g_Wol);

    cudaFuncSetAttribute((const void*)bf16_gemm<0, 0>, cudaFuncAttributeMaxDynamicSharedMemorySize, G2_SMEM);
    cudaFuncSetAttribute((const void*)bf16_gemm<0, 1>, cudaFuncAttributeMaxDynamicSharedMemorySize, G2_SMEM);
    cudaFuncSetAttribute((const void*)bf16_gemm<0, 2>, cudaFuncAttributeMaxDynamicSharedMemorySize, G2_SMEM);
    cudaFuncSetAttribute((const void*)bf16_gemm<1, 0>, cudaFuncAttributeMaxDynamicSharedMemorySize, G2_SMEM);
    cudaFuncSetAttribute((const void*)flash_attn, cudaFuncAttributeMaxDynamicSharedMemorySize, FL_SMEM);

    dim3 blk(256);

    // 1) all independent packs
    megapack1<<<dim3(4096, 1, 8), blk>>>(
        x, pos, mask, Wq, Wk, Wv, Wp, Wo,
        Wqkvh, Wqkvl, Wph_, Wpl_, Woh, Wol, xph, xpl, pph, ppl, Mb);

    // 2) fused Q/K/V projection; K slab -> packed K; Q slab also emits QR (rows>=512)
    bf16_gemm<0, 1><<<dim3(8, 32, 3), blk, G2_SMEM>>>(
        xph, xpl, 256, 0, 0,
        Wqkvh, Wqkvl, 512, 0, 131072,
        QKV, DM, 0, 2097152,
        NB * TT, DM, 256, bq, bk, bv, Kph, Kpl, pbv, QRh, QRl);

    // 3) P projection -> packed Pph/Ppl directly
    bf16_gemm<0, 2><<<dim3(8, 16, 1), blk, G2_SMEM>>>(
        pph, ppl, 256, 0, 0, Wph_, Wpl_, 512, 0, 0,
        nullptr, DM, 0, 0, LL, DM, 256, bp, bp, bp, Pph, Ppl, nullptr, nullptr, nullptr);

    // 4) V transpose-pack (fp16)
    vt_pack<<<512, blk>>>(QKV, VTh);

    // 5) R = (Q[512:]+pbv) @ P^T per (b,h)
    bf16_gemm<1, 0><<<dim3(32, 4, 32), blk, G2_SMEM>>>(
        QRh, QRl, 32, 8LL * 512 * 32, 512 * 32,
        Pph, Ppl, 256, 0, 32,
        R, RSTR, 8LL * 512 * RSTR, (ll)512 * RSTR,
        512, LL, 32, nullptr, nullptr, nullptr, nullptr, nullptr, nullptr, nullptr, nullptr);

    // 6) flash attention
    flash_attn<<<dim3(16, 32), dim3(128), FL_SMEM>>>(
        QKV, Kph, Kpl, VTh, pbu, R, Mb, Oph, Opl);

    // 7) out = O @ Wo + bo
    bf16_gemm<0, 0><<<dim3(8, 32, 1), blk, G2_SMEM>>>(
        Oph, Opl, 256, 0, 0, Woh, Wol, 512, 0, 0,
        out, DM, 0, 0, NB * TT, DM, 256, bo, bo, bo, nullptr, nullptr, nullptr, nullptr, nullptr);
}

// round 13
// speedup vs baseline: 2.4304x; 1.1702x over previous
#include <cuda_runtime.h>
#include <cuda_bf16.h>
#include <cuda_fp16.h>
#include <cstdint>

#define TT 1024
#define DM 512
#define NB 4
#define NH 8
#define DK 64
#define LL 2047   // 2*T - 1
#define RSTR 2048
typedef long long ll;
typedef unsigned long long u64;

// ---------------- scratch ----------------
__device__ float g_QKV[3LL * NB * TT * DM];     // Q | (K unused) | V
__device__ __half g_Rh[32LL * 512 * RSTR];      // R in fp16
__device__ unsigned int g_Mb[NB * TT * 32];
__device__ unsigned int g_Kph[32LL * 1024 * 32];
__device__ unsigned int g_Kpl[32LL * 1024 * 32];
__device__ unsigned int g_VTh[32LL * 64 * 512];   // fp16x2 pairs along s
__device__ unsigned int g_xph[NB * TT * 256],  g_xpl[NB * TT * 256];
__device__ unsigned int g_pph[2047 * 256],     g_ppl[2047 * 256];
__device__ unsigned int g_Wqkvh[3 * 256 * 512], g_Wqkvl[3 * 256 * 512];
__device__ unsigned int g_Wph[256 * 512], g_Wpl[256 * 512];
__device__ unsigned int g_Woh[256 * 512], g_Wol[256 * 512];
__device__ unsigned int g_Pph[2047 * 256], g_Ppl[2047 * 256];
__device__ unsigned int g_QRh[32LL * 512 * 32], g_QRl[32LL * 512 * 32];
__device__ unsigned int g_Oph[NB * TT * 256], g_Opl[NB * TT * 256];

// ---------------- helpers ----------------
__device__ __forceinline__ float bf16_hi(float x) {
    return __bfloat162float(__float2bfloat16(x));
}
__device__ __forceinline__ uint32_t pack_bf16(float lo_elem, float hi_elem) {
    uint32_t r;
    asm("cvt.rn.bf16x2.f32 %0, %1, %2;" : "=r"(r) : "f"(hi_elem), "f"(lo_elem));
    return r;
}
__device__ __forceinline__ void split_pack(float a, float b, uint32_t& ph, uint32_t& pl) {
    float ha = bf16_hi(a), hb = bf16_hi(b);
    ph = pack_bf16(a, b);
    pl = pack_bf16(a - ha, b - hb);
}
__device__ __forceinline__ float f16_hi(float x) {
    return __half2float(__float2half_rn(x));
}
__device__ __forceinline__ uint32_t pack_f16(float lo_elem, float hi_elem) {
    uint32_t r;
    asm("cvt.rn.f16x2.f32 %0, %1, %2;" : "=r"(r) : "f"(hi_elem), "f"(lo_elem));
    return r;
}
__device__ __forceinline__ void split_pack_f16(float a, float b, uint32_t& ph, uint32_t& pl) {
    float ha = f16_hi(a), hb = f16_hi(b);
    ph = pack_f16(a, b);
    pl = pack_f16(a - ha, b - hb);
}
__device__ __forceinline__ void mma_bf16(float* d, const uint32_t* a, uint32_t b0, uint32_t b1) {
    asm volatile(
        "mma.sync.aligned.m16n8k16.row.col.f32.bf16.bf16.f32 "
        "{%0,%1,%2,%3}, {%4,%5,%6,%7}, {%8,%9}, {%0,%1,%2,%3};\n"
        : "+f"(d[0]), "+f"(d[1]), "+f"(d[2]), "+f"(d[3])
        : "r"(a[0]), "r"(a[1]), "r"(a[2]), "r"(a[3]), "r"(b0), "r"(b1));
}
__device__ __forceinline__ void mma_f16(float* d, const uint32_t* a, uint32_t b0, uint32_t b1) {
    asm volatile(
        "mma.sync.aligned.m16n8k16.row.col.f32.f16.f16.f32 "
        "{%0,%1,%2,%3}, {%4,%5,%6,%7}, {%8,%9}, {%0,%1,%2,%3};\n"
        : "+f"(d[0]), "+f"(d[1]), "+f"(d[2]), "+f"(d[3])
        : "r"(a[0]), "r"(a[1]), "r"(a[2]), "r"(a[3]), "r"(b0), "r"(b1));
}
__device__ __forceinline__ void ldsm_x4(uint32_t& r0, uint32_t& r1, uint32_t& r2, uint32_t& r3,
                                        uint32_t addr) {
    asm volatile("ldmatrix.sync.aligned.m8n8.x4.shared.b16 {%0,%1,%2,%3}, [%4];\n"
                 : "=r"(r0), "=r"(r1), "=r"(r2), "=r"(r3) : "r"(addr));
}
__device__ __forceinline__ void cp_async16(uint32_t dst, const void* src, bool p) {
    asm volatile("cp.async.cg.shared.global [%0], [%1], 16, %2;\n"
                 :: "r"(dst), "l"(src), "r"(p ? 16 : 0));
}
__device__ __forceinline__ void cp_commit() { asm volatile("cp.async.commit_group;\n"); }
template <int N>
__device__ __forceinline__ void cp_wait() { asm volatile("cp.async.wait_group %0;\n" :: "n"(N)); }

// ---------------- mega-pack 1: all input-only packs, grid (4096,1,8) ----------------
__global__ void __launch_bounds__(256) megapack1(
    const float* __restrict__ x, const float* __restrict__ pos,
    const unsigned char* __restrict__ mask,
    const float* __restrict__ Wq, const float* __restrict__ Wk,
    const float* __restrict__ Wv, const float* __restrict__ Wp,
    const float* __restrict__ Wo,
    unsigned int* __restrict__ Wqkvh, unsigned int* __restrict__ Wqkvl,
    unsigned int* __restrict__ Wph, unsigned int* __restrict__ Wpl,
    unsigned int* __restrict__ Woh, unsigned int* __restrict__ Wol,
    unsigned int* __restrict__ xph, unsigned int* __restrict__ xpl,
    unsigned int* __restrict__ pph, unsigned int* __restrict__ ppl,
    unsigned int* __restrict__ Mb)
{
    const int zz = blockIdx.z, bx = blockIdx.x, tid = threadIdx.x;
    if (zz < 5) {
        if (bx >= 512) return;
        int i = bx * 256 + tid;
        int r = i >> 9, n = i & 511;
        const float* W = zz == 0 ? Wq : zz == 1 ? Wk : zz == 2 ? Wv : zz == 3 ? Wp : Wo;
        unsigned int *ph, *pl;
        if (zz < 3)      { ph = Wqkvh + zz * 131072; pl = Wqkvl + zz * 131072; }
        else if (zz == 3){ ph = Wph; pl = Wpl; }
        else             { ph = Woh; pl = Wol; }
        split_pack(W[(2 * r) * 512 + n], W[(2 * r + 1) * 512 + n], ph[i], pl[i]);
    } else if (zz == 5) {
        ll i = (ll)bx * 256 + tid;
        float2 v = *(const float2*)(x + 2 * i);
        split_pack(v.x, v.y, xph[i], xpl[i]);
    } else if (zz == 6) {
        if (bx >= 2047) return;
        ll i = (ll)bx * 256 + tid;
        float2 v = *(const float2*)(pos + 2 * i);
        split_pack(v.x, v.y, pph[i], ppl[i]);
    } else {
        if (bx >= 512) return;
        int i = bx * 256 + tid;
        const uchar4* p = (const uchar4*)(mask + (ll)i * 32);
        unsigned int bits = 0;
#pragma unroll
        for (int j = 0; j < 8; j++) {
            uchar4 v = p[j];
            unsigned int q = (v.x ? 1u : 0u) | (v.y ? 2u : 0u) | (v.z ? 4u : 0u) | (v.w ? 8u : 0u);
            bits |= q << (4 * j);
        }
        Mb[i] = bits;
    }
}

// ---------------- V transpose-pack (fp16), grid (512,1,1) ----------------
__global__ void __launch_bounds__(256) vt_pack(
    const float* __restrict__ QKV, unsigned int* __restrict__ VTh)
{
    __shared__ float sv[64][65];
    const int bx = blockIdx.x, tid = threadIdx.x;
    const int z = bx >> 4, b = z >> 3, h = z & 7;
    const int s0 = (bx & 15) * 64;
    const int row = tid >> 2, cq = (tid & 3) << 4;
    const float* Vf = QKV + 4194304;
    {
        const float* vr = Vf + ((ll)(b * TT + s0 + row)) * DM + h * DK + cq;
#pragma unroll
        for (int i = 0; i < 4; i++) {
            float4 f = *(const float4*)(vr + 4 * i);
            sv[row][cq + 4 * i] = f.x; sv[row][cq + 4 * i + 1] = f.y;
            sv[row][cq + 4 * i + 2] = f.z; sv[row][cq + 4 * i + 3] = f.w;
        }
    }
    __syncthreads();
    {
        const int d = tid >> 2, sq = (tid & 3) << 4;
        ll base = ((ll)z * 64 + d) * 512 + ((s0 + sq) >> 1);
#pragma unroll
        for (int j = 0; j < 8; j++)
            VTh[base + j] = pack_f16(sv[sq + 2 * j][d], sv[sq + 2 * j + 1][d]);
    }
}

// ---------------- bf16x2 pipelined GEMM (ldmatrix fragments) ----------------
// EPACK=0: fp32 C. EPACK=1: h==1 packed K; h==0 fp32 + QR pack. EPACK=2: packed P. EPACK=3: fp16 C.
#define A_STR 20
#define BN_STR 72
#define BT_STR 20
#define G2_SMEM ((4 * 2560 + 4 * 1280) * 4)

template <int TRANSB, int EPACK>
__global__ void __launch_bounds__(256) bf16_gemm(
    const unsigned int* __restrict__ Aph, const unsigned int* __restrict__ Apl,
    int ldap, ll sAb, ll sAh,
    const unsigned int* __restrict__ Bph, const unsigned int* __restrict__ Bpl,
    int ldbp, ll sBb, ll sBh,
    float* __restrict__ C, int ldc, ll sCb, ll sCh,
    int M, int N, int Kp,
    const float* __restrict__ bias0, const float* __restrict__ bias1,
    const float* __restrict__ bias2,
    unsigned int* __restrict__ Ph, unsigned int* __restrict__ Pl,
    const float* __restrict__ pbv,
    unsigned int* __restrict__ QRh, unsigned int* __restrict__ QRl)
{
    extern __shared__ uint32_t su[];
    uint32_t* BH = su + 10240;
    uint32_t* BLo = su + 12800;

    const int z = blockIdx.z, b = z >> 3, h = z & 7;
    const float* bias = (h == 0) ? bias0 : (h == 1) ? bias1 : bias2;
    Aph += (ll)b * sAb + (ll)h * sAh;
    Apl += (ll)b * sAb + (ll)h * sAh;
    Bph += (ll)b * sBb + (ll)h * sBh;
    Bpl += (ll)b * sBb + (ll)h * sBh;

    const int tid = threadIdx.x;
    const int lane = tid & 31, wid = tid >> 5;
    const int g = lane >> 2, t = lane & 3;
    const int grp = lane >> 3, gi = lane & 7;
    const int wm = wid & 3, wn = wid >> 2;
    const int m0 = blockIdx.y * 128, n0 = blockIdx.x * 64;

    uint32_t sBase = (uint32_t)__cvta_generic_to_shared(su);

    auto stage = [&](int k0p, int stg) {
#pragma unroll
        for (int i = 0; i < 2; i++) {
            int idx = tid + 256 * i;
            int row = idx >> 2, c4 = (idx & 3) << 2;
            bool p = (m0 + row) < M;
            const ll off = (ll)(m0 + row) * ldap + k0p + c4;
            uint32_t d0 = sBase + (uint32_t)(stg * 2560 + row * A_STR + c4) * 4;
            cp_async16(d0, Aph + off, p);
            cp_async16(d0 + 5120 * 4, Apl + off, p);
        }
        if (!TRANSB) {
            int row = tid >> 4, c4 = (tid & 15) << 2;
            const ll off = (ll)(k0p + row) * ldbp + n0 + c4;
            uint32_t d0 = sBase + (uint32_t)(10240 + stg * 1280 + row * BN_STR + c4) * 4;
            cp_async16(d0, Bph + off, true);
            cp_async16(d0 + 2560 * 4, Bpl + off, true);
        } else {
            int row = tid >> 2, c4 = (tid & 3) << 2;
            bool p = (n0 + row) < N;
            const ll off = (ll)(n0 + row) * ldbp + k0p + c4;
            uint32_t d0 = sBase + (uint32_t)(10240 + stg * 1280 + row * BT_STR + c4) * 4;
            cp_async16(d0, Bph + off, p);
            cp_async16(d0 + 2560 * 4, Bpl + off, p);
        }
    };

    float d[2][4][4];
#pragma unroll
    for (int i = 0; i < 2; i++)
#pragma unroll
        for (int j = 0; j < 4; j++)
#pragma unroll
            for (int c = 0; c < 4; c++) d[i][j][c] = 0.f;

    const int nIter = Kp >> 4;
    stage(0, 0);
    cp_commit();

    for (int it = 0; it < nIter; it++) {
        __syncthreads();
        if (it + 1 < nIter) { stage((it + 1) << 4, (it + 1) & 1); cp_commit(); cp_wait<1>(); }
        else cp_wait<0>();
        __syncthreads();

        const uint32_t aBaseH = sBase +
            (uint32_t)(((it & 1) * 2560 + (wm * 32 + ((grp & 1) << 3) + gi) * A_STR + ((grp >> 1) << 2)) << 2);
        const uint32_t aBaseL = aBaseH + (5120u << 2);
        uint32_t bBaseT = 0;
        if (TRANSB)
            bBaseT = sBase + (uint32_t)((10240 + (grp < 2 ? 0 : 2560) + (it & 1) * 1280 +
                                         (wn * 32 + gi) * BT_STR + ((grp & 1) << 2)) << 2);
        const uint32_t* pBH = BH + (it & 1) * 1280;
        const uint32_t* pBL = BLo + (it & 1) * 1280;

#pragma unroll
        for (int ck = 0; ck < 2; ck++) {
            const int kb = ck * 8;
            uint32_t aH[2][4], aL[2][4];
#pragma unroll
            for (int mt = 0; mt < 2; mt++) {
                uint32_t off = (uint32_t)((mt * 16 * A_STR + kb) << 2);
                ldsm_x4(aH[mt][0], aH[mt][1], aH[mt][2], aH[mt][3], aBaseH + off);
                ldsm_x4(aL[mt][0], aL[mt][1], aL[mt][2], aL[mt][3], aBaseL + off);
            }
#pragma unroll
            for (int nt = 0; nt < 4; nt++) {
                uint32_t b0h, b1h, b0l, b1l;
                if (!TRANSB) {
                    int col = wn * 32 + nt * 8 + g;
                    int i0 = (kb + t) * BN_STR + col, i1 = (kb + t + 4) * BN_STR + col;
                    b0h = pBH[i0]; b1h = pBH[i1];
                    b0l = pBL[i0]; b1l = pBL[i1];
                } else {
                    ldsm_x4(b0h, b1h, b0l, b1l, bBaseT + (uint32_t)((nt * 8 * BT_STR + kb) << 2));
                }
#pragma unroll
                for (int mt = 0; mt < 2; mt++) {
                    mma_bf16(d[mt][nt], aH[mt], b0h, b1h);
                    mma_bf16(d[mt][nt], aL[mt], b0h, b1h);
                    mma_bf16(d[mt][nt], aH[mt], b0l, b1l);
                }
            }
        }
    }

    // ---- epilogue ----
    const bool packK = (EPACK == 1 && h == 1);
    if (EPACK == 2 || packK) {
#pragma unroll
        for (int mt = 0; mt < 2; mt++) {
#pragma unroll
            for (int nt = 0; nt < 4; nt++) {
                int col = n0 + wn * 32 + nt * 8 + 2 * t;
                float b0 = bias ? bias[col] : 0.f;
                float b1 = bias ? bias[col + 1] : 0.f;
#pragma unroll
                for (int rr = 0; rr < 2; rr++) {
                    int row = m0 + wm * 32 + mt * 16 + g + 8 * rr;
                    if (row >= M) continue;
                    float v0 = d[mt][nt][2 * rr + 0] + b0;
                    float v1 = d[mt][nt][2 * rr + 1] + b1;
                    ll idx;
                    if (EPACK == 2) {
                        idx = (ll)row * 256 + (col >> 1);
                    } else {
                        int zk = ((row >> 10) << 3) + (col >> 6);
                        idx = ((ll)zk * 1024 + (row & 1023)) * 32 + ((col & 63) >> 1);
                    }
                    split_pack(v0, v1, Ph[idx], Pl[idx]);
                }
            }
        }
        return;
    }

    if (EPACK == 3) {
        __half* Cz = (__half*)C + (ll)b * sCb + (ll)h * sCh;
#pragma unroll
        for (int mt = 0; mt < 2; mt++) {
#pragma unroll
            for (int nt = 0; nt < 4; nt++) {
                int col = n0 + wn * 32 + nt * 8 + 2 * t;
#pragma unroll
                for (int rr = 0; rr < 2; rr++) {
                    int row = m0 + wm * 32 + mt * 16 + g + 8 * rr;
                    if (row >= M) continue;
                    float v0 = d[mt][nt][2 * rr + 0];
                    float v1 = d[mt][nt][2 * rr + 1];
                    if (col + 1 < N)
                        *(__half2*)(Cz + (ll)row * ldc + col) = __floats2half2_rn(v0, v1);
                    else if (col < N)
                        Cz[(ll)row * ldc + col] = __float2half(v0);
                }
            }
        }
        return;
    }

    float* Cz = C + (ll)b * sCb + (ll)h * sCh;
#pragma unroll
    for (int mt = 0; mt < 2; mt++) {
#pragma unroll
        for (int nt = 0; nt < 4; nt++) {
            int col = n0 + wn * 32 + nt * 8 + 2 * t;
            float b0 = (bias && col < N) ? bias[col] : 0.f;
            float b1 = (bias && col + 1 < N) ? bias[col + 1] : 0.f;
#pragma unroll
            for (int rr = 0; rr < 2; rr++) {
                int row = m0 + wm * 32 + mt * 16 + g + 8 * rr;
                if (row >= M) continue;
                float v0 = d[mt][nt][2 * rr + 0] + b0;
                float v1 = d[mt][nt][2 * rr + 1] + b1;
                if (col < N)     Cz[(ll)row * ldc + col]     = v0;
                if (col + 1 < N) Cz[(ll)row * ldc + col + 1] = v1;
                if (EPACK == 1 && h == 0) {
                    int tloc = row & 1023;
                    if (tloc >= 512) {
                        int zq = ((row >> 10) << 3) + (col >> 6);
                        ll qi = ((ll)zq * 512 + (tloc - 512)) * 32 + ((col & 63) >> 1);
                        split_pack(v0 + pbv[col], v1 + pbv[col + 1], QRh[qi], QRl[qi]);
                    }
                }
            }
        }
    }
}

// ---------------- fused flash attention: bf16x2 QK (3-term), fp16 PV (2-term), fp16 R ----------------
#define PSTR 36
#define FL_SMEM (6 * 2304 * 4)

__global__ void __launch_bounds__(128, 3) flash_attn(
    const float* __restrict__ Q,
    const unsigned int* __restrict__ Kph, const unsigned int* __restrict__ Kpl,
    const unsigned int* __restrict__ VTh,
    const float* __restrict__ pbu, const __half* __restrict__ Rr,
    const unsigned int* __restrict__ mbits,
    unsigned int* __restrict__ Oph, unsigned int* __restrict__ Opl)
{
    extern __shared__ uint32_t smu[];
    uint32_t* VH = smu + 4 * 2304;

    const int z = blockIdx.y, b = z >> 3, h = z & 7;
    const int t0 = blockIdx.x * 64;
    const int tid = threadIdx.x, lane = tid & 31, w = tid >> 5;
    const int g = lane >> 2, t = lane & 3;
    const int grp = lane >> 3, gi = lane & 7;

    const float* Qb = Q + ((ll)(b * TT + t0)) * DM + h * DK;
    const ll rb = (ll)z * 512 * RSTR;

    uint32_t qh[4][4], ql[4][4];
    {
        const int r0 = w * 16 + g, r1 = r0 + 8;
#pragma unroll
        for (int ks = 0; ks < 4; ks++) {
#pragma unroll
            for (int half = 0; half < 2; half++) {
                int c = 16 * ks + 8 * half + 2 * t;
                float u0 = pbu[h * DK + c], u1 = pbu[h * DK + c + 1];
                float x0 = Qb[(ll)r0 * DM + c] + u0;
                float x1 = Qb[(ll)r0 * DM + c + 1] + u1;
                float y0 = Qb[(ll)r1 * DM + c] + u0;
                float y1 = Qb[(ll)r1 * DM + c + 1] + u1;
                split_pack(x0, x1, qh[ks][2 * half + 0], ql[ks][2 * half + 0]);
                split_pack(y0, y1, qh[ks][2 * half + 1], ql[ks][2 * half + 1]);
            }
        }
    }

    float o[8][4];
#pragma unroll
    for (int i = 0; i < 8; i++)
#pragma unroll
        for (int j = 0; j < 4; j++) o[i][j] = 0.f;
    float mx0 = -1e30f, mx1 = -1e30f, l0 = 0.f, l1 = 0.f;

    uint32_t sBase = (uint32_t)__cvta_generic_to_shared(smu);

    auto loadKV = [&](int st, int buf) {
        const unsigned int* kh = Kph + ((ll)z * 1024 + st * 64) * 32;
        const unsigned int* kl = Kpl + ((ll)z * 1024 + st * 64) * 32;
        const unsigned int* vh = VTh + (ll)z * 64 * 512 + st * 32;
        uint32_t o0 = sBase + (uint32_t)(buf * 2304) * 4;
#pragma unroll
        for (int i = 0; i < 4; i++) {
            int idx = tid + 128 * i;
            int row = idx >> 3, c4 = (idx & 7) << 2;
            uint32_t soff = (uint32_t)(row * PSTR + c4) * 4;
            cp_async16(o0 + soff,                kh + (ll)row * 32 + c4, true);
            cp_async16(o0 + 2 * 2304 * 4 + soff, kl + (ll)row * 32 + c4, true);
            cp_async16(o0 + 4 * 2304 * 4 + soff, vh + (ll)row * 512 + c4, true);
        }
    };

    loadKV(0, 0);
    cp_commit();

    const int tg0 = t0 + w * 16 + g, tg1 = tg0 + 8;
    const __half2* R0 = (const __half2*)(Rr + rb + (ll)(tg0 >> 1) * RSTR);
    const __half2* R1 = (const __half2*)(Rr + rb + (ll)(tg1 >> 1) * RSTR);
    const int p0 = (tg0 & 1) << 10, p1 = (tg1 & 1) << 10;
    const uint2* mrow0 = (const uint2*)(mbits + ((ll)b * TT + tg0) * 32);
    const uint2* mrow1 = (const uint2*)(mbits + ((ll)b * TT + tg1) * 32);

    for (int st = 0; st < 16; st++) {
        const int buf = st & 1;
        cp_wait<0>();
        __syncthreads();
        if (st + 1 < 16) { loadKV(st + 1, 1 - buf); cp_commit(); }

        const uint32_t kAddr = sBase +
            (uint32_t)((((grp < 2 ? buf : 2 + buf) * 2304) + gi * PSTR + ((grp & 1) << 2)) << 2);
        const uint32_t* pVH = VH + buf * 2304;

        float sc[8][4];
#pragma unroll
        for (int i = 0; i < 8; i++)
#pragma unroll
            for (int j = 0; j < 4; j++) sc[i][j] = 0.f;
#pragma unroll
        for (int nt = 0; nt < 8; nt++) {
#pragma unroll
            for (int ks = 0; ks < 4; ks++) {
                uint32_t b0h, b1h, b0l, b1l;
                ldsm_x4(b0h, b1h, b0l, b1l, kAddr + (uint32_t)((nt * 8 * PSTR + 8 * ks) << 2));
                mma_bf16(sc[nt], qh[ks], b0h, b1h);
                mma_bf16(sc[nt], ql[ks], b0h, b1h);
                mma_bf16(sc[nt], qh[ks], b0l, b1l);
            }
        }

        const int s0 = st * 64;
#pragma unroll
        for (int nt = 0; nt < 8; nt++) {
            int s_ = s0 + nt * 8 + 2 * t;
            int la = s_ + p0, lb = s_ + p1;
            float2 va = __half22float2(R0[la >> 1]);
            float2 vb = __half22float2(R1[lb >> 1]);
            float pa1 = (la + 1 == LL) ? 0.f : va.y;
            float pb1 = (lb + 1 == LL) ? 0.f : vb.y;
            sc[nt][0] = (sc[nt][0] + va.x) * 0.125f;
            sc[nt][1] = (sc[nt][1] + pa1) * 0.125f;
            sc[nt][2] = (sc[nt][2] + vb.x) * 0.125f;
            sc[nt][3] = (sc[nt][3] + pb1) * 0.125f;
        }
        {
            uint2 w0 = mrow0[st], w1 = mrow1[st];
            u64 m0 = (u64)w0.x | ((u64)w0.y << 32);
            u64 m1 = (u64)w1.x | ((u64)w1.y << 32);
            if (m0 | m1) {
#pragma unroll
                for (int nt = 0; nt < 8; nt++) {
                    int p = nt * 8 + 2 * t;
                    if ((m0 >> p) & 1)       sc[nt][0] = -1e9f;
                    if ((m0 >> (p + 1)) & 1) sc[nt][1] = -1e9f;
                    if ((m1 >> p) & 1)       sc[nt][2] = -1e9f;
                    if ((m1 >> (p + 1)) & 1) sc[nt][3] = -1e9f;
                }
            }
        }

        float rmx0 = -1e30f, rmx1 = -1e30f;
#pragma unroll
        for (int nt = 0; nt < 8; nt++) {
            rmx0 = fmaxf(rmx0, fmaxf(sc[nt][0], sc[nt][1]));
            rmx1 = fmaxf(rmx1, fmaxf(sc[nt][2], sc[nt][3]));
        }
        rmx0 = fmaxf(rmx0, __shfl_xor_sync(0xffffffffu, rmx0, 1));
        rmx0 = fmaxf(rmx0, __shfl_xor_sync(0xffffffffu, rmx0, 2));
        rmx1 = fmaxf(rmx1, __shfl_xor_sync(0xffffffffu, rmx1, 1));
        rmx1 = fmaxf(rmx1, __shfl_xor_sync(0xffffffffu, rmx1, 2));

        float mn0 = fmaxf(mx0, rmx0), mn1 = fmaxf(mx1, rmx1);
        float al0 = __expf(mx0 - mn0), al1 = __expf(mx1 - mn1);
        float rs0 = 0.f, rs1 = 0.f;
#pragma unroll
        for (int nt = 0; nt < 8; nt++) {
            sc[nt][0] = __expf(sc[nt][0] - mn0);
            sc[nt][1] = __expf(sc[nt][1] - mn0);
            sc[nt][2] = __expf(sc[nt][2] - mn1);
            sc[nt][3] = __expf(sc[nt][3] - mn1);
            rs0 += sc[nt][0] + sc[nt][1];
            rs1 += sc[nt][2] + sc[nt][3];
        }
        rs0 += __shfl_xor_sync(0xffffffffu, rs0, 1);
        rs0 += __shfl_xor_sync(0xffffffffu, rs0, 2);
        rs1 += __shfl_xor_sync(0xffffffffu, rs1, 1);
        rs1 += __shfl_xor_sync(0xffffffffu, rs1, 2);
        l0 = l0 * al0 + rs0;
        l1 = l1 * al1 + rs1;
        mx0 = mn0; mx1 = mn1;
#pragma unroll
        for (int dt = 0; dt < 8; dt++) {
            o[dt][0] *= al0; o[dt][1] *= al0;
            o[dt][2] *= al1; o[dt][3] *= al1;
        }

        // ---- O += P @ V : fp16 2-term ----
#pragma unroll
        for (int j = 0; j < 4; j++) {
            uint32_t aPh[4], aPl[4];
            split_pack_f16(sc[2 * j][0],     sc[2 * j][1],     aPh[0], aPl[0]);
            split_pack_f16(sc[2 * j][2],     sc[2 * j][3],     aPh[1], aPl[1]);
            split_pack_f16(sc[2 * j + 1][0], sc[2 * j + 1][1], aPh[2], aPl[2]);
            split_pack_f16(sc[2 * j + 1][2], sc[2 * j + 1][3], aPh[3], aPl[3]);
#pragma unroll
            for (int dt = 0; dt < 8; dt++) {
                const int vrow = (dt * 8 + g) * PSTR;
                uint32_t b0h = pVH[vrow + 8 * j + t];
                uint32_t b1h = pVH[vrow + 8 * j + 4 + t];
                mma_f16(o[dt], aPh, b0h, b1h);
                mma_f16(o[dt], aPl, b0h, b1h);
            }
        }
    }

    float inv0 = 1.f / l0, inv1 = 1.f / l1;
    ll base0 = ((ll)(b * TT + tg0)) * 256 + h * 32;
    ll base1 = ((ll)(b * TT + tg1)) * 256 + h * 32;
#pragma unroll
    for (int dt = 0; dt < 8; dt++) {
        int pj = dt * 4 + t;
        split_pack(o[dt][0] * inv0, o[dt][1] * inv0, Oph[base0 + pj], Opl[base0 + pj]);
        split_pack(o[dt][2] * inv1, o[dt][3] * inv1, Oph[base1 + pj], Opl[base1 + pj]);
    }
}

// ---------------- launch ----------------
extern "C" void kernel_launch(void* const* d_in, const int* in_sizes, int n_in,
                              void* d_out, int out_size)
{
    const float* x   = (const float*)d_in[0];
    const float* pos = (const float*)d_in[1];
    const unsigned char* mask = (const unsigned char*)d_in[2];
    const float* Wq = (const float*)d_in[3];  const float* bq = (const float*)d_in[4];
    const float* Wk = (const float*)d_in[5];  const float* bk = (const float*)d_in[6];
    const float* Wv = (const float*)d_in[7];  const float* bv = (const float*)d_in[8];
    const float* Wp = (const float*)d_in[9];  const float* bp = (const float*)d_in[10];
    const float* Wo = (const float*)d_in[11]; const float* bo = (const float*)d_in[12];
    const float* pbu = (const float*)d_in[13];
    const float* pbv = (const float*)d_in[14];
    float* out = (float*)d_out;

    float *QKV;
    __half* Rh;
    unsigned int *Mb, *Kph, *Kpl, *VTh;
    unsigned int *xph, *xpl, *pph, *ppl, *Pph, *Ppl, *QRh, *QRl, *Oph, *Opl;
    unsigned int *Wqkvh, *Wqkvl, *Wph_, *Wpl_, *Woh, *Wol;
    cudaGetSymbolAddress((void**)&QKV, g_QKV);
    cudaGetSymbolAddress((void**)&Rh, g_Rh);
    cudaGetSymbolAddress((void**)&Mb, g_Mb);
    cudaGetSymbolAddress((void**)&Kph, g_Kph);
    cudaGetSymbolAddress((void**)&Kpl, g_Kpl);
    cudaGetSymbolAddress((void**)&VTh, g_VTh);
    cudaGetSymbolAddress((void**)&xph, g_xph);
    cudaGetSymbolAddress((void**)&xpl, g_xpl);
    cudaGetSymbolAddress((void**)&pph, g_pph);
    cudaGetSymbolAddress((void**)&ppl, g_ppl);
    cudaGetSymbolAddress((void**)&Pph, g_Pph);
    cudaGetSymbolAddress((void**)&Ppl, g_Ppl);
    cudaGetSymbolAddress((void**)&QRh, g_QRh);
    cudaGetSymbolAddress((void**)&QRl, g_QRl);
    cudaGetSymbolAddress((void**)&Oph, g_Oph);
    cudaGetSymbolAddress((void**)&Opl, g_Opl);
    cudaGetSymbolAddress((void**)&Wqkvh, g_Wqkvh);
    cudaGetSymbolAddress((void**)&Wqkvl, g_Wqkvl);
    cudaGetSymbolAddress((void**)&Wph_, g_Wph);
    cudaGetSymbolAddress((void**)&Wpl_, g_Wpl);
    cudaGetSymbolAddress((void**)&Woh, g_Woh);
    cudaGetSymbolAddress((void**)&Wol, g_Wol);

    cudaFuncSetAttribute((const void*)bf16_gemm<0, 0>, cudaFuncAttributeMaxDynamicSharedMemorySize, G2_SMEM);
    cudaFuncSetAttribute((const void*)bf16_gemm<0, 1>, cudaFuncAttributeMaxDynamicSharedMemorySize, G2_SMEM);
    cudaFuncSetAttribute((const void*)bf16_gemm<0, 2>, cudaFuncAttributeMaxDynamicSharedMemorySize, G2_SMEM);
    cudaFuncSetAttribute((const void*)bf16_gemm<1, 3>, cudaFuncAttributeMaxDynamicSharedMemorySize, G2_SMEM);
    cudaFuncSetAttribute((const void*)flash_attn, cudaFuncAttributeMaxDynamicSharedMemorySize, FL_SMEM);

    dim3 blk(256);

    // 1) all independent packs
    megapack1<<<dim3(4096, 1, 8), blk>>>(
        x, pos, mask, Wq, Wk, Wv, Wp, Wo,
        Wqkvh, Wqkvl, Wph_, Wpl_, Woh, Wol, xph, xpl, pph, ppl, Mb);

    // 2) fused Q/K/V projection; K slab -> packed K; Q slab also emits QR (rows>=512)
    bf16_gemm<0, 1><<<dim3(8, 32, 3), blk, G2_SMEM>>>(
        xph, xpl, 256, 0, 0,
        Wqkvh, Wqkvl, 512, 0, 131072,
        QKV, DM, 0, 2097152,
        NB * TT, DM, 256, bq, bk, bv, Kph, Kpl, pbv, QRh, QRl);

    // 3) P projection -> packed Pph/Ppl directly
    bf16_gemm<0, 2><<<dim3(8, 16, 1), blk, G2_SMEM>>>(
        pph, ppl, 256, 0, 0, Wph_, Wpl_, 512, 0, 0,
        nullptr, DM, 0, 0, LL, DM, 256, bp, bp, bp, Pph, Ppl, nullptr, nullptr, nullptr);

    // 4) V transpose-pack (fp16)
    vt_pack<<<512, blk>>>(QKV, VTh);

    // 5) R = (Q[512:]+pbv) @ P^T per (b,h), fp16 output
    bf16_gemm<1, 3><<<dim3(32, 4, 32), blk, G2_SMEM>>>(
        QRh, QRl, 32, 8LL * 512 * 32, 512 * 32,
        Pph, Ppl, 256, 0, 32,
        (float*)Rh, RSTR, 8LL * 512 * RSTR, (ll)512 * RSTR,
        512, LL, 32, nullptr, nullptr, nullptr, nullptr, nullptr, nullptr, nullptr, nullptr);

    // 6) flash attention (fp16 R)
    flash_attn<<<dim3(16, 32), dim3(128), FL_SMEM>>>(
        QKV, Kph, Kpl, VTh, pbu, Rh, Mb, Oph, Opl);

    // 7) out = O @ Wo + bo
    bf16_gemm<0, 0><<<dim3(8, 32, 1), blk, G2_SMEM>>>(
        Oph, Opl, 256, 0, 0, Woh, Wol, 512, 0, 0,
        out, DM, 0, 0, NB * TT, DM, 256, bo, bo, bo, nullptr, nullptr, nullptr, nullptr, nullptr);
}

// round 14
// speedup vs baseline: 2.4458x; 1.0063x over previous
#include <cuda_runtime.h>
#include <cuda_bf16.h>
#include <cuda_fp16.h>
#include <cstdint>

#define TT 1024
#define DM 512
#define NB 4
#define NH 8
#define DK 64
#define LL 2047   // 2*T - 1
#define RSTR 2048
typedef long long ll;
typedef unsigned long long u64;

// ---------------- scratch ----------------
__device__ float g_QKV[3LL * NB * TT * DM];     // Q | (K,V unused)
__device__ __half g_Rh[32LL * 512 * RSTR];      // R in fp16
__device__ unsigned int g_Mb[NB * TT * 32];
__device__ unsigned int g_Kph[32LL * 1024 * 32];
__device__ unsigned int g_Kpl[32LL * 1024 * 32];
__device__ unsigned int g_VTh[32LL * 64 * 512];   // fp16x2 pairs along s
__device__ unsigned int g_xph[NB * TT * 256],  g_xpl[NB * TT * 256];
__device__ unsigned int g_pph[2047 * 256],     g_ppl[2047 * 256];
__device__ unsigned int g_Wqkvh[3 * 256 * 512], g_Wqkvl[3 * 256 * 512];
__device__ unsigned int g_Wph[256 * 512], g_Wpl[256 * 512];
__device__ unsigned int g_Woh[256 * 512], g_Wol[256 * 512];
__device__ unsigned int g_Pph[2047 * 256], g_Ppl[2047 * 256];
__device__ unsigned int g_QRh[32LL * 512 * 32], g_QRl[32LL * 512 * 32];
__device__ unsigned int g_Oph[NB * TT * 256], g_Opl[NB * TT * 256];

// ---------------- helpers ----------------
__device__ __forceinline__ float bf16_hi(float x) {
    return __bfloat162float(__float2bfloat16(x));
}
__device__ __forceinline__ uint32_t pack_bf16(float lo_elem, float hi_elem) {
    uint32_t r;
    asm("cvt.rn.bf16x2.f32 %0, %1, %2;" : "=r"(r) : "f"(hi_elem), "f"(lo_elem));
    return r;
}
__device__ __forceinline__ void split_pack(float a, float b, uint32_t& ph, uint32_t& pl) {
    float ha = bf16_hi(a), hb = bf16_hi(b);
    ph = pack_bf16(a, b);
    pl = pack_bf16(a - ha, b - hb);
}
__device__ __forceinline__ float f16_hi(float x) {
    return __half2float(__float2half_rn(x));
}
__device__ __forceinline__ uint32_t pack_f16(float lo_elem, float hi_elem) {
    uint32_t r;
    asm("cvt.rn.f16x2.f32 %0, %1, %2;" : "=r"(r) : "f"(hi_elem), "f"(lo_elem));
    return r;
}
__device__ __forceinline__ void split_pack_f16(float a, float b, uint32_t& ph, uint32_t& pl) {
    float ha = f16_hi(a), hb = f16_hi(b);
    ph = pack_f16(a, b);
    pl = pack_f16(a - ha, b - hb);
}
__device__ __forceinline__ void mma_bf16(float* d, const uint32_t* a, uint32_t b0, uint32_t b1) {
    asm volatile(
        "mma.sync.aligned.m16n8k16.row.col.f32.bf16.bf16.f32 "
        "{%0,%1,%2,%3}, {%4,%5,%6,%7}, {%8,%9}, {%0,%1,%2,%3};\n"
        : "+f"(d[0]), "+f"(d[1]), "+f"(d[2]), "+f"(d[3])
        : "r"(a[0]), "r"(a[1]), "r"(a[2]), "r"(a[3]), "r"(b0), "r"(b1));
}
__device__ __forceinline__ void mma_f16(float* d, const uint32_t* a, uint32_t b0, uint32_t b1) {
    asm volatile(
        "mma.sync.aligned.m16n8k16.row.col.f32.f16.f16.f32 "
        "{%0,%1,%2,%3}, {%4,%5,%6,%7}, {%8,%9}, {%0,%1,%2,%3};\n"
        : "+f"(d[0]), "+f"(d[1]), "+f"(d[2]), "+f"(d[3])
        : "r"(a[0]), "r"(a[1]), "r"(a[2]), "r"(a[3]), "r"(b0), "r"(b1));
}
__device__ __forceinline__ void ldsm_x4(uint32_t& r0, uint32_t& r1, uint32_t& r2, uint32_t& r3,
                                        uint32_t addr) {
    asm volatile("ldmatrix.sync.aligned.m8n8.x4.shared.b16 {%0,%1,%2,%3}, [%4];\n"
                 : "=r"(r0), "=r"(r1), "=r"(r2), "=r"(r3) : "r"(addr));
}
__device__ __forceinline__ void cp_async16(uint32_t dst, const void* src, bool p) {
    asm volatile("cp.async.cg.shared.global [%0], [%1], 16, %2;\n"
                 :: "r"(dst), "l"(src), "r"(p ? 16 : 0));
}
__device__ __forceinline__ void cp_commit() { asm volatile("cp.async.commit_group;\n"); }
template <int N>
__device__ __forceinline__ void cp_wait() { asm volatile("cp.async.wait_group %0;\n" :: "n"(N)); }

// ---------------- mega-pack 1: all input-only packs, grid (4096,1,8) ----------------
__global__ void __launch_bounds__(256) megapack1(
    const float* __restrict__ x, const float* __restrict__ pos,
    const unsigned char* __restrict__ mask,
    const float* __restrict__ Wq, const float* __restrict__ Wk,
    const float* __restrict__ Wv, const float* __restrict__ Wp,
    const float* __restrict__ Wo,
    unsigned int* __restrict__ Wqkvh, unsigned int* __restrict__ Wqkvl,
    unsigned int* __restrict__ Wph, unsigned int* __restrict__ Wpl,
    unsigned int* __restrict__ Woh, unsigned int* __restrict__ Wol,
    unsigned int* __restrict__ xph, unsigned int* __restrict__ xpl,
    unsigned int* __restrict__ pph, unsigned int* __restrict__ ppl,
    unsigned int* __restrict__ Mb)
{
    const int zz = blockIdx.z, bx = blockIdx.x, tid = threadIdx.x;
    if (zz < 5) {
        if (bx >= 512) return;
        int i = bx * 256 + tid;
        int r = i >> 9, n = i & 511;
        const float* W = zz == 0 ? Wq : zz == 1 ? Wk : zz == 2 ? Wv : zz == 3 ? Wp : Wo;
        unsigned int *ph, *pl;
        if (zz < 3)      { ph = Wqkvh + zz * 131072; pl = Wqkvl + zz * 131072; }
        else if (zz == 3){ ph = Wph; pl = Wpl; }
        else             { ph = Woh; pl = Wol; }
        split_pack(W[(2 * r) * 512 + n], W[(2 * r + 1) * 512 + n], ph[i], pl[i]);
    } else if (zz == 5) {
        ll i = (ll)bx * 256 + tid;
        float2 v = *(const float2*)(x + 2 * i);
        split_pack(v.x, v.y, xph[i], xpl[i]);
    } else if (zz == 6) {
        if (bx >= 2047) return;
        ll i = (ll)bx * 256 + tid;
        float2 v = *(const float2*)(pos + 2 * i);
        split_pack(v.x, v.y, pph[i], ppl[i]);
    } else {
        if (bx >= 512) return;
        int i = bx * 256 + tid;
        const uchar4* p = (const uchar4*)(mask + (ll)i * 32);
        unsigned int bits = 0;
#pragma unroll
        for (int j = 0; j < 8; j++) {
            uchar4 v = p[j];
            unsigned int q = (v.x ? 1u : 0u) | (v.y ? 2u : 0u) | (v.z ? 4u : 0u) | (v.w ? 8u : 0u);
            bits |= q << (4 * j);
        }
        Mb[i] = bits;
    }
}

// ---------------- bf16x2 pipelined GEMM (ldmatrix fragments) ----------------
// EPACK=0: fp32 C.
// EPACK=1: h==1 packed K; h==2 V transpose-pack (fp16, via smem); h==0 fp32 + QR pack.
// EPACK=2: packed P pairs. EPACK=3: fp16 C.
#define A_STR 20
#define BN_STR 72
#define BT_STR 20
#define G2_SMEM ((4 * 2560 + 4 * 1280) * 4)

template <int TRANSB, int EPACK>
__global__ void __launch_bounds__(256) bf16_gemm(
    const unsigned int* __restrict__ Aph, const unsigned int* __restrict__ Apl,
    int ldap, ll sAb, ll sAh,
    const unsigned int* __restrict__ Bph, const unsigned int* __restrict__ Bpl,
    int ldbp, ll sBb, ll sBh,
    float* __restrict__ C, int ldc, ll sCb, ll sCh,
    int M, int N, int Kp,
    const float* __restrict__ bias0, const float* __restrict__ bias1,
    const float* __restrict__ bias2,
    unsigned int* __restrict__ Ph, unsigned int* __restrict__ Pl,
    const float* __restrict__ pbv,
    unsigned int* __restrict__ QRh, unsigned int* __restrict__ QRl,
    unsigned int* __restrict__ VTh)
{
    extern __shared__ uint32_t su[];
    uint32_t* BH = su + 10240;
    uint32_t* BLo = su + 12800;

    const int z = blockIdx.z, b = z >> 3, h = z & 7;
    const float* bias = (h == 0) ? bias0 : (h == 1) ? bias1 : bias2;
    Aph += (ll)b * sAb + (ll)h * sAh;
    Apl += (ll)b * sAb + (ll)h * sAh;
    Bph += (ll)b * sBb + (ll)h * sBh;
    Bpl += (ll)b * sBb + (ll)h * sBh;

    const int tid = threadIdx.x;
    const int lane = tid & 31, wid = tid >> 5;
    const int g = lane >> 2, t = lane & 3;
    const int grp = lane >> 3, gi = lane & 7;
    const int wm = wid & 3, wn = wid >> 2;
    const int m0 = blockIdx.y * 128, n0 = blockIdx.x * 64;

    uint32_t sBase = (uint32_t)__cvta_generic_to_shared(su);

    auto stage = [&](int k0p, int stg) {
#pragma unroll
        for (int i = 0; i < 2; i++) {
            int idx = tid + 256 * i;
            int row = idx >> 2, c4 = (idx & 3) << 2;
            bool p = (m0 + row) < M;
            const ll off = (ll)(m0 + row) * ldap + k0p + c4;
            uint32_t d0 = sBase + (uint32_t)(stg * 2560 + row * A_STR + c4) * 4;
            cp_async16(d0, Aph + off, p);
            cp_async16(d0 + 5120 * 4, Apl + off, p);
        }
        if (!TRANSB) {
            int row = tid >> 4, c4 = (tid & 15) << 2;
            const ll off = (ll)(k0p + row) * ldbp + n0 + c4;
            uint32_t d0 = sBase + (uint32_t)(10240 + stg * 1280 + row * BN_STR + c4) * 4;
            cp_async16(d0, Bph + off, true);
            cp_async16(d0 + 2560 * 4, Bpl + off, true);
        } else {
            int row = tid >> 2, c4 = (tid & 3) << 2;
            bool p = (n0 + row) < N;
            const ll off = (ll)(n0 + row) * ldbp + k0p + c4;
            uint32_t d0 = sBase + (uint32_t)(10240 + stg * 1280 + row * BT_STR + c4) * 4;
            cp_async16(d0, Bph + off, p);
            cp_async16(d0 + 2560 * 4, Bpl + off, p);
        }
    };

    float d[2][4][4];
#pragma unroll
    for (int i = 0; i < 2; i++)
#pragma unroll
        for (int j = 0; j < 4; j++)
#pragma unroll
            for (int c = 0; c < 4; c++) d[i][j][c] = 0.f;

    const int nIter = Kp >> 4;
    stage(0, 0);
    cp_commit();

    for (int it = 0; it < nIter; it++) {
        __syncthreads();
        if (it + 1 < nIter) { stage((it + 1) << 4, (it + 1) & 1); cp_commit(); cp_wait<1>(); }
        else cp_wait<0>();
        __syncthreads();

        const uint32_t aBaseH = sBase +
            (uint32_t)(((it & 1) * 2560 + (wm * 32 + ((grp & 1) << 3) + gi) * A_STR + ((grp >> 1) << 2)) << 2);
        const uint32_t aBaseL = aBaseH + (5120u << 2);
        uint32_t bBaseT = 0;
        if (TRANSB)
            bBaseT = sBase + (uint32_t)((10240 + (grp < 2 ? 0 : 2560) + (it & 1) * 1280 +
                                         (wn * 32 + gi) * BT_STR + ((grp & 1) << 2)) << 2);
        const uint32_t* pBH = BH + (it & 1) * 1280;
        const uint32_t* pBL = BLo + (it & 1) * 1280;

#pragma unroll
        for (int ck = 0; ck < 2; ck++) {
            const int kb = ck * 8;
            uint32_t aH[2][4], aL[2][4];
#pragma unroll
            for (int mt = 0; mt < 2; mt++) {
                uint32_t off = (uint32_t)((mt * 16 * A_STR + kb) << 2);
                ldsm_x4(aH[mt][0], aH[mt][1], aH[mt][2], aH[mt][3], aBaseH + off);
                ldsm_x4(aL[mt][0], aL[mt][1], aL[mt][2], aL[mt][3], aBaseL + off);
            }
#pragma unroll
            for (int nt = 0; nt < 4; nt++) {
                uint32_t b0h, b1h, b0l, b1l;
                if (!TRANSB) {
                    int col = wn * 32 + nt * 8 + g;
                    int i0 = (kb + t) * BN_STR + col, i1 = (kb + t + 4) * BN_STR + col;
                    b0h = pBH[i0]; b1h = pBH[i1];
                    b0l = pBL[i0]; b1l = pBL[i1];
                } else {
                    ldsm_x4(b0h, b1h, b0l, b1l, bBaseT + (uint32_t)((nt * 8 * BT_STR + kb) << 2));
                }
#pragma unroll
                for (int mt = 0; mt < 2; mt++) {
                    mma_bf16(d[mt][nt], aH[mt], b0h, b1h);
                    mma_bf16(d[mt][nt], aL[mt], b0h, b1h);
                    mma_bf16(d[mt][nt], aH[mt], b0l, b1l);
                }
            }
        }
    }

    // ---- epilogue ----
    const bool packK = (EPACK == 1 && h == 1);
    if (EPACK == 2 || packK) {
#pragma unroll
        for (int mt = 0; mt < 2; mt++) {
#pragma unroll
            for (int nt = 0; nt < 4; nt++) {
                int col = n0 + wn * 32 + nt * 8 + 2 * t;
                float b0 = bias ? bias[col] : 0.f;
                float b1 = bias ? bias[col + 1] : 0.f;
#pragma unroll
                for (int rr = 0; rr < 2; rr++) {
                    int row = m0 + wm * 32 + mt * 16 + g + 8 * rr;
                    if (row >= M) continue;
                    float v0 = d[mt][nt][2 * rr + 0] + b0;
                    float v1 = d[mt][nt][2 * rr + 1] + b1;
                    ll idx;
                    if (EPACK == 2) {
                        idx = (ll)row * 256 + (col >> 1);
                    } else {
                        int zk = ((row >> 10) << 3) + (col >> 6);
                        idx = ((ll)zk * 1024 + (row & 1023)) * 32 + ((col & 63) >> 1);
                    }
                    split_pack(v0, v1, Ph[idx], Pl[idx]);
                }
            }
        }
        return;
    }

    if (EPACK == 1 && h == 2) {
        // V slab: transpose-pack to VTh via smem staging (fp16 pairs along s)
        float* sv = (float*)su;   // [128][68] = 34816 B
        __syncthreads();
#pragma unroll
        for (int mt = 0; mt < 2; mt++) {
#pragma unroll
            for (int nt = 0; nt < 4; nt++) {
                int cl = wn * 32 + nt * 8 + 2 * t;
                float b0 = bias[n0 + cl], b1 = bias[n0 + cl + 1];
#pragma unroll
                for (int rr = 0; rr < 2; rr++) {
                    int rl = wm * 32 + mt * 16 + g + 8 * rr;
                    sv[rl * 68 + cl]     = d[mt][nt][2 * rr + 0] + b0;
                    sv[rl * 68 + cl + 1] = d[mt][nt][2 * rr + 1] + b1;
                }
            }
        }
        __syncthreads();
        const int bb = m0 >> 10, s0 = m0 & 1023, head = n0 >> 6;
        const int zv = bb * 8 + head;
        const int dd = tid & 63, sg = tid >> 6;
        ll base = ((ll)zv * 64 + dd) * 512 + ((s0 + sg * 32) >> 1);
#pragma unroll
        for (int j = 0; j < 16; j++)
            VTh[base + j] = pack_f16(sv[(sg * 32 + 2 * j) * 68 + dd],
                                     sv[(sg * 32 + 2 * j + 1) * 68 + dd]);
        return;
    }

    if (EPACK == 3) {
        __half* Cz = (__half*)C + (ll)b * sCb + (ll)h * sCh;
#pragma unroll
        for (int mt = 0; mt < 2; mt++) {
#pragma unroll
            for (int nt = 0; nt < 4; nt++) {
                int col = n0 + wn * 32 + nt * 8 + 2 * t;
#pragma unroll
                for (int rr = 0; rr < 2; rr++) {
                    int row = m0 + wm * 32 + mt * 16 + g + 8 * rr;
                    if (row >= M) continue;
                    float v0 = d[mt][nt][2 * rr + 0];
                    float v1 = d[mt][nt][2 * rr + 1];
                    if (col + 1 < N)
                        *(__half2*)(Cz + (ll)row * ldc + col) = __floats2half2_rn(v0, v1);
                    else if (col < N)
                        Cz[(ll)row * ldc + col] = __float2half(v0);
                }
            }
        }
        return;
    }

    float* Cz = C + (ll)b * sCb + (ll)h * sCh;
#pragma unroll
    for (int mt = 0; mt < 2; mt++) {
#pragma unroll
        for (int nt = 0; nt < 4; nt++) {
            int col = n0 + wn * 32 + nt * 8 + 2 * t;
            float b0 = (bias && col < N) ? bias[col] : 0.f;
            float b1 = (bias && col + 1 < N) ? bias[col + 1] : 0.f;
#pragma unroll
            for (int rr = 0; rr < 2; rr++) {
                int row = m0 + wm * 32 + mt * 16 + g + 8 * rr;
                if (row >= M) continue;
                float v0 = d[mt][nt][2 * rr + 0] + b0;
                float v1 = d[mt][nt][2 * rr + 1] + b1;
                if (col < N)     Cz[(ll)row * ldc + col]     = v0;
                if (col + 1 < N) Cz[(ll)row * ldc + col + 1] = v1;
                if (EPACK == 1 && h == 0) {
                    int tloc = row & 1023;
                    if (tloc >= 512) {
                        int zq = ((row >> 10) << 3) + (col >> 6);
                        ll qi = ((ll)zq * 512 + (tloc - 512)) * 32 + ((col & 63) >> 1);
                        split_pack(v0 + pbv[col], v1 + pbv[col + 1], QRh[qi], QRl[qi]);
                    }
                }
            }
        }
    }
}

// ---------------- fused flash attention: bf16x2 QK (3-term), fp16 PV (2-term), fp16 R ----------------
#define PSTR 36
#define FL_SMEM (6 * 2304 * 4)

__global__ void __launch_bounds__(128, 3) flash_attn(
    const float* __restrict__ Q,
    const unsigned int* __restrict__ Kph, const unsigned int* __restrict__ Kpl,
    const unsigned int* __restrict__ VTh,
    const float* __restrict__ pbu, const __half* __restrict__ Rr,
    const unsigned int* __restrict__ mbits,
    unsigned int* __restrict__ Oph, unsigned int* __restrict__ Opl)
{
    extern __shared__ uint32_t smu[];
    uint32_t* VH = smu + 4 * 2304;

    const int z = blockIdx.y, b = z >> 3, h = z & 7;
    const int t0 = blockIdx.x * 64;
    const int tid = threadIdx.x, lane = tid & 31, w = tid >> 5;
    const int g = lane >> 2, t = lane & 3;
    const int grp = lane >> 3, gi = lane & 7;

    const float* Qb = Q + ((ll)(b * TT + t0)) * DM + h * DK;
    const ll rb = (ll)z * 512 * RSTR;

    uint32_t qh[4][4], ql[4][4];
    {
        const int r0 = w * 16 + g, r1 = r0 + 8;
#pragma unroll
        for (int ks = 0; ks < 4; ks++) {
#pragma unroll
            for (int half = 0; half < 2; half++) {
                int c = 16 * ks + 8 * half + 2 * t;
                float u0 = pbu[h * DK + c], u1 = pbu[h * DK + c + 1];
                float x0 = Qb[(ll)r0 * DM + c] + u0;
                float x1 = Qb[(ll)r0 * DM + c + 1] + u1;
                float y0 = Qb[(ll)r1 * DM + c] + u0;
                float y1 = Qb[(ll)r1 * DM + c + 1] + u1;
                split_pack(x0, x1, qh[ks][2 * half + 0], ql[ks][2 * half + 0]);
                split_pack(y0, y1, qh[ks][2 * half + 1], ql[ks][2 * half + 1]);
            }
        }
    }

    float o[8][4];
#pragma unroll
    for (int i = 0; i < 8; i++)
#pragma unroll
        for (int j = 0; j < 4; j++) o[i][j] = 0.f;
    float mx0 = -1e30f, mx1 = -1e30f, l0 = 0.f, l1 = 0.f;

    uint32_t sBase = (uint32_t)__cvta_generic_to_shared(smu);

    auto loadKV = [&](int st, int buf) {
        const unsigned int* kh = Kph + ((ll)z * 1024 + st * 64) * 32;
        const unsigned int* kl = Kpl + ((ll)z * 1024 + st * 64) * 32;
        const unsigned int* vh = VTh + (ll)z * 64 * 512 + st * 32;
        uint32_t o0 = sBase + (uint32_t)(buf * 2304) * 4;
#pragma unroll
        for (int i = 0; i < 4; i++) {
            int idx = tid + 128 * i;
            int row = idx >> 3, c4 = (idx & 7) << 2;
            uint32_t soff = (uint32_t)(row * PSTR + c4) * 4;
            cp_async16(o0 + soff,                kh + (ll)row * 32 + c4, true);
            cp_async16(o0 + 2 * 2304 * 4 + soff, kl + (ll)row * 32 + c4, true);
            cp_async16(o0 + 4 * 2304 * 4 + soff, vh + (ll)row * 512 + c4, true);
        }
    };

    loadKV(0, 0);
    cp_commit();

    const int tg0 = t0 + w * 16 + g, tg1 = tg0 + 8;
    const __half2* R0 = (const __half2*)(Rr + rb + (ll)(tg0 >> 1) * RSTR);
    const __half2* R1 = (const __half2*)(Rr + rb + (ll)(tg1 >> 1) * RSTR);
    const int p0 = (tg0 & 1) << 10, p1 = (tg1 & 1) << 10;
    const uint2* mrow0 = (const uint2*)(mbits + ((ll)b * TT + tg0) * 32);
    const uint2* mrow1 = (const uint2*)(mbits + ((ll)b * TT + tg1) * 32);

    for (int st = 0; st < 16; st++) {
        const int buf = st & 1;
        cp_wait<0>();
        __syncthreads();
        if (st + 1 < 16) { loadKV(st + 1, 1 - buf); cp_commit(); }

        const uint32_t kAddr = sBase +
            (uint32_t)((((grp < 2 ? buf : 2 + buf) * 2304) + gi * PSTR + ((grp & 1) << 2)) << 2);
        const uint32_t* pVH = VH + buf * 2304;

        float sc[8][4];
#pragma unroll
        for (int i = 0; i < 8; i++)
#pragma unroll
            for (int j = 0; j < 4; j++) sc[i][j] = 0.f;
#pragma unroll
        for (int nt = 0; nt < 8; nt++) {
#pragma unroll
            for (int ks = 0; ks < 4; ks++) {
                uint32_t b0h, b1h, b0l, b1l;
                ldsm_x4(b0h, b1h, b0l, b1l, kAddr + (uint32_t)((nt * 8 * PSTR + 8 * ks) << 2));
                mma_bf16(sc[nt], qh[ks], b0h, b1h);
                mma_bf16(sc[nt], ql[ks], b0h, b1h);
                mma_bf16(sc[nt], qh[ks], b0l, b1l);
            }
        }

        const int s0 = st * 64;
#pragma unroll
        for (int nt = 0; nt < 8; nt++) {
            int s_ = s0 + nt * 8 + 2 * t;
            int la = s_ + p0, lb = s_ + p1;
            float2 va = __half22float2(R0[la >> 1]);
            float2 vb = __half22float2(R1[lb >> 1]);
            float pa1 = (la + 1 == LL) ? 0.f : va.y;
            float pb1 = (lb + 1 == LL) ? 0.f : vb.y;
            sc[nt][0] = (sc[nt][0] + va.x) * 0.125f;
            sc[nt][1] = (sc[nt][1] + pa1) * 0.125f;
            sc[nt][2] = (sc[nt][2] + vb.x) * 0.125f;
            sc[nt][3] = (sc[nt][3] + pb1) * 0.125f;
        }
        {
            uint2 w0 = mrow0[st], w1 = mrow1[st];
            u64 m0 = (u64)w0.x | ((u64)w0.y << 32);
            u64 m1 = (u64)w1.x | ((u64)w1.y << 32);
            if (m0 | m1) {
#pragma unroll
                for (int nt = 0; nt < 8; nt++) {
                    int p = nt * 8 + 2 * t;
                    if ((m0 >> p) & 1)       sc[nt][0] = -1e9f;
                    if ((m0 >> (p + 1)) & 1) sc[nt][1] = -1e9f;
                    if ((m1 >> p) & 1)       sc[nt][2] = -1e9f;
                    if ((m1 >> (p + 1)) & 1) sc[nt][3] = -1e9f;
                }
            }
        }

        float rmx0 = -1e30f, rmx1 = -1e30f;
#pragma unroll
        for (int nt = 0; nt < 8; nt++) {
            rmx0 = fmaxf(rmx0, fmaxf(sc[nt][0], sc[nt][1]));
            rmx1 = fmaxf(rmx1, fmaxf(sc[nt][2], sc[nt][3]));
        }
        rmx0 = fmaxf(rmx0, __shfl_xor_sync(0xffffffffu, rmx0, 1));
        rmx0 = fmaxf(rmx0, __shfl_xor_sync(0xffffffffu, rmx0, 2));
        rmx1 = fmaxf(rmx1, __shfl_xor_sync(0xffffffffu, rmx1, 1));
        rmx1 = fmaxf(rmx1, __shfl_xor_sync(0xffffffffu, rmx1, 2));

        float mn0 = fmaxf(mx0, rmx0), mn1 = fmaxf(mx1, rmx1);
        float al0 = __expf(mx0 - mn0), al1 = __expf(mx1 - mn1);
        float rs0 = 0.f, rs1 = 0.f;
#pragma unroll
        for (int nt = 0; nt < 8; nt++) {
            sc[nt][0] = __expf(sc[nt][0] - mn0);
            sc[nt][1] = __expf(sc[nt][1] - mn0);
            sc[nt][2] = __expf(sc[nt][2] - mn1);
            sc[nt][3] = __expf(sc[nt][3] - mn1);
            rs0 += sc[nt][0] + sc[nt][1];
            rs1 += sc[nt][2] + sc[nt][3];
        }
        rs0 += __shfl_xor_sync(0xffffffffu, rs0, 1);
        rs0 += __shfl_xor_sync(0xffffffffu, rs0, 2);
        rs1 += __shfl_xor_sync(0xffffffffu, rs1, 1);
        rs1 += __shfl_xor_sync(0xffffffffu, rs1, 2);
        l0 = l0 * al0 + rs0;
        l1 = l1 * al1 + rs1;
        mx0 = mn0; mx1 = mn1;
#pragma unroll
        for (int dt = 0; dt < 8; dt++) {
            o[dt][0] *= al0; o[dt][1] *= al0;
            o[dt][2] *= al1; o[dt][3] *= al1;
        }

        // ---- O += P @ V : fp16 2-term ----
#pragma unroll
        for (int j = 0; j < 4; j++) {
            uint32_t aPh[4], aPl[4];
            split_pack_f16(sc[2 * j][0],     sc[2 * j][1],     aPh[0], aPl[0]);
            split_pack_f16(sc[2 * j][2],     sc[2 * j][3],     aPh[1], aPl[1]);
            split_pack_f16(sc[2 * j + 1][0], sc[2 * j + 1][1], aPh[2], aPl[2]);
            split_pack_f16(sc[2 * j + 1][2], sc[2 * j + 1][3], aPh[3], aPl[3]);
#pragma unroll
            for (int dt = 0; dt < 8; dt++) {
                const int vrow = (dt * 8 + g) * PSTR;
                uint32_t b0h = pVH[vrow + 8 * j + t];
                uint32_t b1h = pVH[vrow + 8 * j + 4 + t];
                mma_f16(o[dt], aPh, b0h, b1h);
                mma_f16(o[dt], aPl, b0h, b1h);
            }
        }
    }

    float inv0 = 1.f / l0, inv1 = 1.f / l1;
    ll base0 = ((ll)(b * TT + tg0)) * 256 + h * 32;
    ll base1 = ((ll)(b * TT + tg1)) * 256 + h * 32;
#pragma unroll
    for (int dt = 0; dt < 8; dt++) {
        int pj = dt * 4 + t;
        split_pack(o[dt][0] * inv0, o[dt][1] * inv0, Oph[base0 + pj], Opl[base0 + pj]);
        split_pack(o[dt][2] * inv1, o[dt][3] * inv1, Oph[base1 + pj], Opl[base1 + pj]);
    }
}

// ---------------- launch ----------------
extern "C" void kernel_launch(void* const* d_in, const int* in_sizes, int n_in,
                              void* d_out, int out_size)
{
    const float* x   = (const float*)d_in[0];
    const float* pos = (const float*)d_in[1];
    const unsigned char* mask = (const unsigned char*)d_in[2];
    const float* Wq = (const float*)d_in[3];  const float* bq = (const float*)d_in[4];
    const float* Wk = (const float*)d_in[5];  const float* bk = (const float*)d_in[6];
    const float* Wv = (const float*)d_in[7];  const float* bv = (const float*)d_in[8];
    const float* Wp = (const float*)d_in[9];  const float* bp = (const float*)d_in[10];
    const float* Wo = (const float*)d_in[11]; const float* bo = (const float*)d_in[12];
    const float* pbu = (const float*)d_in[13];
    const float* pbv = (const float*)d_in[14];
    float* out = (float*)d_out;

    float *QKV;
    __half* Rh;
    unsigned int *Mb, *Kph, *Kpl, *VTh;
    unsigned int *xph, *xpl, *pph, *ppl, *Pph, *Ppl, *QRh, *QRl, *Oph, *Opl;
    unsigned int *Wqkvh, *Wqkvl, *Wph_, *Wpl_, *Woh, *Wol;
    cudaGetSymbolAddress((void**)&QKV, g_QKV);
    cudaGetSymbolAddress((void**)&Rh, g_Rh);
    cudaGetSymbolAddress((void**)&Mb, g_Mb);
    cudaGetSymbolAddress((void**)&Kph, g_Kph);
    cudaGetSymbolAddress((void**)&Kpl, g_Kpl);
    cudaGetSymbolAddress((void**)&VTh, g_VTh);
    cudaGetSymbolAddress((void**)&xph, g_xph);
    cudaGetSymbolAddress((void**)&xpl, g_xpl);
    cudaGetSymbolAddress((void**)&pph, g_pph);
    cudaGetSymbolAddress((void**)&ppl, g_ppl);
    cudaGetSymbolAddress((void**)&Pph, g_Pph);
    cudaGetSymbolAddress((void**)&Ppl, g_Ppl);
    cudaGetSymbolAddress((void**)&QRh, g_QRh);
    cudaGetSymbolAddress((void**)&QRl, g_QRl);
    cudaGetSymbolAddress((void**)&Oph, g_Oph);
    cudaGetSymbolAddress((void**)&Opl, g_Opl);
    cudaGetSymbolAddress((void**)&Wqkvh, g_Wqkvh);
    cudaGetSymbolAddress((void**)&Wqkvl, g_Wqkvl);
    cudaGetSymbolAddress((void**)&Wph_, g_Wph);
    cudaGetSymbolAddress((void**)&Wpl_, g_Wpl);
    cudaGetSymbolAddress((void**)&Woh, g_Woh);
    cudaGetSymbolAddress((void**)&Wol, g_Wol);

    cudaFuncSetAttribute((const void*)bf16_gemm<0, 0>, cudaFuncAttributeMaxDynamicSharedMemorySize, G2_SMEM);
    cudaFuncSetAttribute((const void*)bf16_gemm<0, 1>, cudaFuncAttributeMaxDynamicSharedMemorySize, G2_SMEM);
    cudaFuncSetAttribute((const void*)bf16_gemm<0, 2>, cudaFuncAttributeMaxDynamicSharedMemorySize, G2_SMEM);
    cudaFuncSetAttribute((const void*)bf16_gemm<1, 3>, cudaFuncAttributeMaxDynamicSharedMemorySize, G2_SMEM);
    cudaFuncSetAttribute((const void*)flash_attn, cudaFuncAttributeMaxDynamicSharedMemorySize, FL_SMEM);

    dim3 blk(256);

    // 1) all independent packs
    megapack1<<<dim3(4096, 1, 8), blk>>>(
        x, pos, mask, Wq, Wk, Wv, Wp, Wo,
        Wqkvh, Wqkvl, Wph_, Wpl_, Woh, Wol, xph, xpl, pph, ppl, Mb);

    // 2) fused Q/K/V projection:
    //    h==0: fp32 Q + QR pack (rows>=512); h==1: packed K; h==2: transposed fp16 V
    bf16_gemm<0, 1><<<dim3(8, 32, 3), blk, G2_SMEM>>>(
        xph, xpl, 256, 0, 0,
        Wqkvh, Wqkvl, 512, 0, 131072,
        QKV, DM, 0, 2097152,
        NB * TT, DM, 256, bq, bk, bv, Kph, Kpl, pbv, QRh, QRl, VTh);

    // 3) P projection -> packed Pph/Ppl directly
    bf16_gemm<0, 2><<<dim3(8, 16, 1), blk, G2_SMEM>>>(
        pph, ppl, 256, 0, 0, Wph_, Wpl_, 512, 0, 0,
        nullptr, DM, 0, 0, LL, DM, 256, bp, bp, bp, Pph, Ppl, nullptr, nullptr, nullptr, nullptr);

    // 4) R = (Q[512:]+pbv) @ P^T per (b,h), fp16 output
    bf16_gemm<1, 3><<<dim3(32, 4, 32), blk, G2_SMEM>>>(
        QRh, QRl, 32, 8LL * 512 * 32, 512 * 32,
        Pph, Ppl, 256, 0, 32,
        (float*)Rh, RSTR, 8LL * 512 * RSTR, (ll)512 * RSTR,
        512, LL, 32, nullptr, nullptr, nullptr, nullptr, nullptr, nullptr, nullptr, nullptr, nullptr);

    // 5) flash attention (fp16 R)
    flash_attn<<<dim3(16, 32), dim3(128), FL_SMEM>>>(
        QKV, Kph, Kpl, VTh, pbu, Rh, Mb, Oph, Opl);

    // 6) out = O @ Wo + bo
    bf16_gemm<0, 0><<<dim3(8, 32, 1), blk, G2_SMEM>>>(
        Oph, Opl, 256, 0, 0, Woh, Wol, 512, 0, 0,
        out, DM, 0, 0, NB * TT, DM, 256, bo, bo, bo, nullptr, nullptr, nullptr, nullptr, nullptr, nullptr);
}